// round 1
// baseline (speedup 1.0000x reference)
#include <cuda_runtime.h>
#include <math.h>

#define E    64
#define KTOP 6
#define H    1024
#define F    512
#define SF   2048
#define T    2048
#define CAP  384   // 2 * ceil(T*K/E)

// ---------------- scratch (static device globals; allocation-free) ----------------
__device__ int   g_cnt[E];
__device__ int   g_slot_token[E * CAP];
__device__ int   g_pair_slot[T * KTOP];
__device__ float g_pair_w[T * KTOP];
__device__ float g_mid[(size_t)E * CAP * F];     // ~50 MB
__device__ float g_y[(size_t)E * CAP * H];       // ~100 MB
__device__ float g_smid[(size_t)T * SF];         // ~17 MB

// ---------------- helpers ----------------
__device__ __forceinline__ unsigned f2tf(float f) {
    unsigned u;
    asm("cvt.rna.tf32.f32 %0, %1;" : "=r"(u) : "f"(f));
    return u;
}

__device__ __forceinline__ float gelu_tanh(float x) {
    float u = 0.7978845608028654f * (x + 0.044715f * x * x * x);
    return 0.5f * x * (1.0f + tanhf(u));
}

__device__ __forceinline__ void mma_tf32(float c[4], const unsigned a[4], const unsigned b[2]) {
    asm volatile(
        "mma.sync.aligned.m16n8k8.row.col.f32.tf32.tf32.f32 "
        "{%0,%1,%2,%3}, {%4,%5,%6,%7}, {%8,%9}, {%0,%1,%2,%3};\n"
        : "+f"(c[0]), "+f"(c[1]), "+f"(c[2]), "+f"(c[3])
        : "r"(a[0]), "r"(a[1]), "r"(a[2]), "r"(a[3]), "r"(b[0]), "r"(b[1]));
}

// ---------------- kernels ----------------
__global__ void zero_cnt_kernel(int* cnt) {
    if (threadIdx.x < E) cnt[threadIdx.x] = 0;
}

__global__ __launch_bounds__(256) void router_kernel(
    const float* __restrict__ x, const float* __restrict__ rw,
    const float* __restrict__ bias,
    int* __restrict__ cnt, int* __restrict__ slot_token,
    int* __restrict__ pair_slot, float* __restrict__ pair_w)
{
    int t = blockIdx.x;
    __shared__ float xs[H];
    __shared__ float sc[E];
    __shared__ float sb[E];
    for (int i = threadIdx.x; i < H; i += 256) xs[i] = x[(size_t)t * H + i];
    if (threadIdx.x < E) sb[threadIdx.x] = bias[threadIdx.x];
    __syncthreads();

    int warp = threadIdx.x >> 5, lane = threadIdx.x & 31;
    for (int e = warp; e < E; e += 8) {
        const float* w = rw + (size_t)e * H;
        float s = 0.f;
        for (int i = lane; i < H; i += 32) s += xs[i] * w[i];
        #pragma unroll
        for (int o = 16; o; o >>= 1) s += __shfl_xor_sync(0xffffffffu, s, o);
        if (lane == 0) sc[e] = 1.f / (1.f + expf(-s));
    }
    __syncthreads();

    if (threadIdx.x == 0) {
        unsigned long long used = 0ull;
        int idx[KTOP]; float tsc[KTOP]; float sum = 0.f;
        #pragma unroll
        for (int k = 0; k < KTOP; k++) {
            float best = -1e30f; int bi = 0;
            for (int e = 0; e < E; e++) {
                if (used & (1ull << e)) continue;
                float v = sc[e] + sb[e];
                if (v > best) { best = v; bi = e; }   // ties -> lowest index, matches top_k
            }
            used |= 1ull << bi; idx[k] = bi; tsc[k] = sc[bi]; sum += sc[bi];
        }
        float inv = 1.f / (sum + 1e-20f);
        #pragma unroll
        for (int k = 0; k < KTOP; k++) {
            int e = idx[k];
            int pos = atomicAdd(&cnt[e], 1);
            float w = tsc[k] * inv;
            int slot;
            if (pos < CAP) { slot = e * CAP + pos; slot_token[slot] = t; }
            else           { slot = 0; w = 0.f; }
            pair_slot[t * KTOP + k] = slot;
            pair_w[t * KTOP + k]    = w;
        }
    }
}

// Tiled TF32 tensor-core GEMM. Block tile 64x64, BK=16, 4 warps (each 32x32).
// GATHER: A rows gathered via slot_token (rows >= M read as zeros).
// B_NT:   B stored [n][k] (k contiguous);  else [k][n] (n contiguous).
// GELU:   fused tanh-GELU epilogue.
template<bool GATHER, bool B_NT, bool GELU>
__global__ __launch_bounds__(128) void gemm_tf32_kernel(
    const float* __restrict__ Aall, long long sAe, int ldA,
    const float* __restrict__ Ball, long long sBe,
    float* __restrict__ Call, long long sCe, int ldC,
    int Kdim, int Ncols,
    const int* __restrict__ cnts, int Mmax,
    const int* __restrict__ tokall)
{
    const int e  = blockIdx.z;
    const int m0 = blockIdx.y * 64;
    const int n0 = blockIdx.x * 64;
    int M = Mmax;
    if (cnts) { M = cnts[e]; if (M > Mmax) M = Mmax; if (m0 >= M) return; }

    const float* A = Aall + (long long)e * sAe;
    const float* B = Ball + (long long)e * sBe;
    float*       C = Call + (long long)e * sCe;

    __shared__ unsigned As[64][20];  // padded: conflict-free frag loads
    __shared__ unsigned Bs[16][72];

    const int tid  = threadIdx.x;
    const int lane = tid & 31;
    const int warp = tid >> 5;
    const int wm = warp >> 1, wn = warp & 1;
    const int gid = lane >> 2, tig = lane & 3;

    float c[2][4][4];
    #pragma unroll
    for (int i = 0; i < 2; i++)
        #pragma unroll
        for (int j = 0; j < 4; j++)
            #pragma unroll
            for (int q = 0; q < 4; q++) c[i][j][q] = 0.f;

    const int a_row = tid >> 2;        // 0..31
    const int a_col = (tid & 3) * 4;   // 0,4,8,12
    const float* aptr[2];
    #pragma unroll
    for (int j = 0; j < 2; j++) {
        int rg = m0 + a_row + j * 32;
        if (GATHER) {
            int tkn = (rg < M) ? tokall[e * CAP + rg] : -1;
            aptr[j] = (tkn >= 0) ? (Aall + (long long)tkn * ldA) : nullptr;
        } else {
            aptr[j] = A + (long long)rg * ldA;
        }
    }

    for (int k0 = 0; k0 < Kdim; k0 += 16) {
        float4 av[2], bv[2];
        #pragma unroll
        for (int j = 0; j < 2; j++) {
            av[j] = aptr[j] ? *(const float4*)(aptr[j] + k0 + a_col)
                            : make_float4(0.f, 0.f, 0.f, 0.f);
        }
        if (!B_NT) {
            #pragma unroll
            for (int j = 0; j < 2; j++) {
                int kr = (tid >> 4) + j * 8;
                bv[j] = *(const float4*)(B + (long long)(k0 + kr) * Ncols + n0 + (tid & 15) * 4);
            }
        } else {
            #pragma unroll
            for (int j = 0; j < 2; j++) {
                int nr = (tid >> 2) + j * 32;
                bv[j] = *(const float4*)(B + (long long)(n0 + nr) * Kdim + k0 + (tid & 3) * 4);
            }
        }
        __syncthreads();
        #pragma unroll
        for (int j = 0; j < 2; j++) {
            int r = a_row + j * 32;
            As[r][a_col + 0] = f2tf(av[j].x);
            As[r][a_col + 1] = f2tf(av[j].y);
            As[r][a_col + 2] = f2tf(av[j].z);
            As[r][a_col + 3] = f2tf(av[j].w);
        }
        if (!B_NT) {
            #pragma unroll
            for (int j = 0; j < 2; j++) {
                int kr = (tid >> 4) + j * 8; int nc = (tid & 15) * 4;
                Bs[kr][nc + 0] = f2tf(bv[j].x);
                Bs[kr][nc + 1] = f2tf(bv[j].y);
                Bs[kr][nc + 2] = f2tf(bv[j].z);
                Bs[kr][nc + 3] = f2tf(bv[j].w);
            }
        } else {
            #pragma unroll
            for (int j = 0; j < 2; j++) {
                int nr = (tid >> 2) + j * 32; int kc = (tid & 3) * 4;
                Bs[kc + 0][nr] = f2tf(bv[j].x);
                Bs[kc + 1][nr] = f2tf(bv[j].y);
                Bs[kc + 2][nr] = f2tf(bv[j].z);
                Bs[kc + 3][nr] = f2tf(bv[j].w);
            }
        }
        __syncthreads();

        #pragma unroll
        for (int kk = 0; kk < 16; kk += 8) {
            unsigned a[2][4], b[4][2];
            #pragma unroll
            for (int tm = 0; tm < 2; tm++) {
                int r = wm * 32 + tm * 16 + gid;
                a[tm][0] = As[r    ][kk + tig];
                a[tm][1] = As[r + 8][kk + tig];
                a[tm][2] = As[r    ][kk + tig + 4];
                a[tm][3] = As[r + 8][kk + tig + 4];
            }
            #pragma unroll
            for (int tn = 0; tn < 4; tn++) {
                int ncol = wn * 32 + tn * 8 + gid;
                b[tn][0] = Bs[kk + tig    ][ncol];
                b[tn][1] = Bs[kk + tig + 4][ncol];
            }
            #pragma unroll
            for (int tm = 0; tm < 2; tm++)
                #pragma unroll
                for (int tn = 0; tn < 4; tn++)
                    mma_tf32(c[tm][tn], a[tm], b[tn]);
        }
    }

    // epilogue
    #pragma unroll
    for (int tm = 0; tm < 2; tm++) {
        #pragma unroll
        for (int tn = 0; tn < 4; tn++) {
            int row = m0 + wm * 32 + tm * 16 + gid;
            int col = n0 + wn * 32 + tn * 8 + 2 * tig;
            #pragma unroll
            for (int q = 0; q < 4; q++) {
                int r  = row + (q >> 1) * 8;
                int cc = col + (q & 1);
                float v = c[tm][tn][q];
                if (GELU) v = gelu_tanh(v);
                C[(long long)r * ldC + cc] = v;
            }
        }
    }
}

__global__ __launch_bounds__(256) void combine_kernel(
    float* __restrict__ out, const float* __restrict__ y,
    const int* __restrict__ pair_slot, const float* __restrict__ pair_w)
{
    int t = blockIdx.x;
    int slot[KTOP]; float w[KTOP];
    #pragma unroll
    for (int k = 0; k < KTOP; k++) {
        slot[k] = pair_slot[t * KTOP + k];
        w[k]    = pair_w[t * KTOP + k];
    }
    int h4 = threadIdx.x;                      // 256 threads * float4 = 1024
    float4 acc = *(float4*)(out + (size_t)t * H + h4 * 4);
    #pragma unroll
    for (int k = 0; k < KTOP; k++) {
        float4 v = *(const float4*)(y + (size_t)slot[k] * H + h4 * 4);
        acc.x += w[k] * v.x; acc.y += w[k] * v.y;
        acc.z += w[k] * v.z; acc.w += w[k] * v.w;
    }
    *(float4*)(out + (size_t)t * H + h4 * 4) = acc;
}

// ---------------- launch ----------------
extern "C" void kernel_launch(void* const* d_in, const int* in_sizes, int n_in,
                              void* d_out, int out_size)
{
    const float* x   = (const float*)d_in[0];
    const float* rw  = (const float*)d_in[1];
    const float* eb  = (const float*)d_in[2];
    const float* w1  = (const float*)d_in[3];
    const float* w2  = (const float*)d_in[4];
    const float* sw1 = (const float*)d_in[5];
    const float* sw2 = (const float*)d_in[6];
    float* out = (float*)d_out;

    void *pcnt, *ptok, *pps, *ppw, *pmid, *py, *psmid;
    cudaGetSymbolAddress(&pcnt,  g_cnt);
    cudaGetSymbolAddress(&ptok,  g_slot_token);
    cudaGetSymbolAddress(&pps,   g_pair_slot);
    cudaGetSymbolAddress(&ppw,   g_pair_w);
    cudaGetSymbolAddress(&pmid,  g_mid);
    cudaGetSymbolAddress(&py,    g_y);
    cudaGetSymbolAddress(&psmid, g_smid);

    int*   cnt       = (int*)pcnt;
    int*   slot_tok  = (int*)ptok;
    int*   pair_slot = (int*)pps;
    float* pair_w    = (float*)ppw;
    float* mid       = (float*)pmid;
    float* y         = (float*)py;
    float* smid      = (float*)psmid;

    zero_cnt_kernel<<<1, 64>>>(cnt);
    router_kernel<<<T, 256>>>(x, rw, eb, cnt, slot_tok, pair_slot, pair_w);

    // expert GEMM1: mid[e] = gelu(gather(x) @ w1[e])   (M<=cnt[e], N=512, K=1024)
    gemm_tf32_kernel<true, false, true><<<dim3(F / 64, CAP / 64, E), 128>>>(
        x, 0LL, H, w1, (long long)H * F,
        mid, (long long)CAP * F, F,
        H, F, cnt, CAP, slot_tok);

    // expert GEMM2: y[e] = mid[e] @ w2[e]              (N=1024, K=512)
    gemm_tf32_kernel<false, false, false><<<dim3(H / 64, CAP / 64, E), 128>>>(
        mid, (long long)CAP * F, F, w2, (long long)F * H,
        y, (long long)CAP * H, H,
        F, H, cnt, CAP, slot_tok);

    // shared GEMM1: smid = gelu(x @ sw1^T)  (B is [n][k], NT)
    gemm_tf32_kernel<false, true, true><<<dim3(SF / 64, T / 64, 1), 128>>>(
        x, 0LL, H, sw1, 0LL,
        smid, 0LL, SF,
        H, SF, nullptr, T, nullptr);

    // shared GEMM2: out = smid @ sw2^T  (writes full output)
    gemm_tf32_kernel<false, true, false><<<dim3(H / 64, T / 64, 1), 128>>>(
        smid, 0LL, SF, sw2, 0LL,
        out, 0LL, H,
        SF, H, nullptr, T, nullptr);

    // combine: out += sum_k w_k * y[slot_k]  (gather, no atomics)
    combine_kernel<<<T, 256>>>(out, y, pair_slot, pair_w);
}

// round 2
// speedup vs baseline: 1.2278x; 1.2278x over previous
#include <cuda_runtime.h>
#include <math.h>

#define E    64
#define KTOP 6
#define H    1024
#define F    512
#define SF   2048
#define T    2048
#define CAP  384   // 2 * ceil(T*K/E)

// ---------------- scratch (static device globals; allocation-free) ----------------
__device__ int   g_cnt[E];
__device__ int   g_slot_token[E * CAP];
__device__ int   g_pair_slot[T * KTOP];
__device__ float g_pair_w[T * KTOP];
__device__ float g_mid[(size_t)E * CAP * F];     // ~50 MB
__device__ float g_y[(size_t)E * CAP * H];       // ~100 MB
__device__ float g_smid[(size_t)T * SF];         // ~17 MB

// ---------------- helpers ----------------
__device__ __forceinline__ unsigned f2tf(float f) {
    unsigned u;
    asm("cvt.rna.tf32.f32 %0, %1;" : "=r"(u) : "f"(f));
    return u;
}

__device__ __forceinline__ uint4 f2tf4(float4 v) {
    uint4 r;
    r.x = f2tf(v.x); r.y = f2tf(v.y); r.z = f2tf(v.z); r.w = f2tf(v.w);
    return r;
}

__device__ __forceinline__ float gelu_tanh(float x) {
    float u = 0.7978845608028654f * (x + 0.044715f * x * x * x);
    return 0.5f * x * (1.0f + tanhf(u));
}

__device__ __forceinline__ void mma_tf32(float c[4], const unsigned a[4], const unsigned b[2]) {
    asm volatile(
        "mma.sync.aligned.m16n8k8.row.col.f32.tf32.tf32.f32 "
        "{%0,%1,%2,%3}, {%4,%5,%6,%7}, {%8,%9}, {%0,%1,%2,%3};\n"
        : "+f"(c[0]), "+f"(c[1]), "+f"(c[2]), "+f"(c[3])
        : "r"(a[0]), "r"(a[1]), "r"(a[2]), "r"(a[3]), "r"(b[0]), "r"(b[1]));
}

// ---------------- kernels ----------------
__global__ void zero_cnt_kernel(int* cnt) {
    if (threadIdx.x < E) cnt[threadIdx.x] = 0;
}

__global__ __launch_bounds__(256) void router_kernel(
    const float* __restrict__ x, const float* __restrict__ rw,
    const float* __restrict__ bias,
    int* __restrict__ cnt, int* __restrict__ slot_token,
    int* __restrict__ pair_slot, float* __restrict__ pair_w)
{
    int t = blockIdx.x;
    __shared__ float xs[H];
    __shared__ float sc[E];
    __shared__ float sb[E];
    for (int i = threadIdx.x; i < H; i += 256) xs[i] = x[(size_t)t * H + i];
    if (threadIdx.x < E) sb[threadIdx.x] = bias[threadIdx.x];
    __syncthreads();

    int warp = threadIdx.x >> 5, lane = threadIdx.x & 31;
    for (int e = warp; e < E; e += 8) {
        const float* w = rw + (size_t)e * H;
        float s = 0.f;
        for (int i = lane; i < H; i += 32) s += xs[i] * w[i];
        #pragma unroll
        for (int o = 16; o; o >>= 1) s += __shfl_xor_sync(0xffffffffu, s, o);
        if (lane == 0) sc[e] = 1.f / (1.f + expf(-s));
    }
    __syncthreads();

    if (threadIdx.x == 0) {
        unsigned long long used = 0ull;
        int idx[KTOP]; float tsc[KTOP]; float sum = 0.f;
        #pragma unroll
        for (int k = 0; k < KTOP; k++) {
            float best = -1e30f; int bi = 0;
            for (int e = 0; e < E; e++) {
                if (used & (1ull << e)) continue;
                float v = sc[e] + sb[e];
                if (v > best) { best = v; bi = e; }
            }
            used |= 1ull << bi; idx[k] = bi; tsc[k] = sc[bi]; sum += sc[bi];
        }
        float inv = 1.f / (sum + 1e-20f);
        #pragma unroll
        for (int k = 0; k < KTOP; k++) {
            int e = idx[k];
            int pos = atomicAdd(&cnt[e], 1);
            float w = tsc[k] * inv;
            int slot;
            if (pos < CAP) { slot = e * CAP + pos; slot_token[slot] = t; }
            else           { slot = 0; w = 0.f; }
            pair_slot[t * KTOP + k] = slot;
            pair_w[t * KTOP + k]    = w;
        }
    }
}

// TF32 tensor-core GEMM. Block tile 128x128, BK=16, 256 threads (8 warps @ 64x32).
// Double-buffered smem; register-staged global loads; cvt.rna on STS path.
// GATHER: A rows gathered via slot_token (rows >= M read as zeros).
// B_NT:   B stored [n][k] (k contiguous);  else [k][n] (n contiguous).
template<bool GATHER, bool B_NT, bool GELU>
__global__ __launch_bounds__(256, 2) void gemm_tf32_kernel(
    const float* __restrict__ Aall, long long sAe, int ldA,
    const float* __restrict__ Ball, long long sBe,
    float* __restrict__ Call, long long sCe, int ldC,
    int Kdim, int Ncols,
    const int* __restrict__ cnts, int Mmax,
    const int* __restrict__ tokall)
{
    const int e  = blockIdx.z;
    const int m0 = blockIdx.y * 128;
    const int n0 = blockIdx.x * 128;
    int M = Mmax;
    if (cnts) { M = min(cnts[e], Mmax); if (m0 >= M) return; }

    const float* A = Aall + (long long)e * sAe;
    const float* B = Ball + (long long)e * sBe;
    float*       C = Call + (long long)e * sCe;

    // As: [buf][m=128][k=16 pad 20]  (frag loads conflict-free, 16B-aligned STS)
    // Bs: [buf][flat]; NN: [k=16][n=128 pad 136]; NT: [n=128][k=16 pad 20]
    __shared__ __align__(16) unsigned As[2][128][20];
    __shared__ __align__(16) unsigned Bs[2][2560];

    const int tid  = threadIdx.x;
    const int lane = tid & 31;
    const int warp = tid >> 5;
    const int wm = warp >> 2, wn = warp & 3;       // warp grid 2x4
    const int gid = lane >> 2, tig = lane & 3;

    float c[4][4][4];
    #pragma unroll
    for (int i = 0; i < 4; i++)
        #pragma unroll
        for (int j = 0; j < 4; j++)
            #pragma unroll
            for (int q = 0; q < 4; q++) c[i][j][q] = 0.f;

    // ---- global load descriptors (2 float4 per thread per tile, per operand) ----
    // A / B_NT mapping: idx -> row = idx>>2, col4 = (idx&3)*4
    const float* aptr[2];
    int a_sm[2];   // smem word offset
    #pragma unroll
    for (int j = 0; j < 2; j++) {
        int idx = tid + j * 256;
        int mr = idx >> 2, kc = (idx & 3) * 4;
        a_sm[j] = mr * 20 + kc;
        int rg = m0 + mr;
        if (GATHER) {
            int tkn = (rg < M) ? tokall[e * CAP + rg] : -1;
            aptr[j] = (tkn >= 0) ? (Aall + (long long)tkn * ldA + kc) : nullptr;
        } else {
            aptr[j] = A + (long long)rg * ldA + kc;
        }
    }
    const float* bptr[2];
    int b_sm[2];
    #pragma unroll
    for (int j = 0; j < 2; j++) {
        int idx = tid + j * 256;
        if (B_NT) {
            int nr = idx >> 2, kc = (idx & 3) * 4;
            bptr[j] = B + (long long)(n0 + nr) * Kdim + kc;
            b_sm[j] = nr * 20 + kc;
        } else {
            int kr = idx >> 5, nc = (idx & 31) * 4;
            bptr[j] = B + (long long)kr * Ncols + n0 + nc;
            b_sm[j] = kr * 136 + nc;
        }
    }
    const long long bstep = B_NT ? 16LL : 16LL * Ncols;

    const int ntiles = Kdim >> 4;
    float4 av[2], bv[2];

    // prologue: load + store tile 0
    #pragma unroll
    for (int j = 0; j < 2; j++) {
        av[j] = aptr[j] ? *(const float4*)(aptr[j]) : make_float4(0.f,0.f,0.f,0.f);
        bv[j] = *(const float4*)(bptr[j]);
    }
    #pragma unroll
    for (int j = 0; j < 2; j++) {
        *(uint4*)(&As[0][0][0] + a_sm[j]) = f2tf4(av[j]);
        *(uint4*)(&Bs[0][0]    + b_sm[j]) = f2tf4(bv[j]);
    }
    __syncthreads();

    for (int it = 0; it < ntiles; ++it) {
        const int cur = it & 1;
        const bool more = (it + 1 < ntiles);
        if (more) {
            long long ka = (long long)(it + 1) * 16;
            #pragma unroll
            for (int j = 0; j < 2; j++) {
                av[j] = aptr[j] ? *(const float4*)(aptr[j] + ka) : make_float4(0.f,0.f,0.f,0.f);
                bv[j] = *(const float4*)(bptr[j] + (it + 1) * bstep);
            }
        }

        const unsigned (*Asb)[20] = As[cur];
        const unsigned* Bsb = Bs[cur];

        #pragma unroll
        for (int kk = 0; kk < 16; kk += 8) {
            unsigned a[4][4], b[4][2];
            #pragma unroll
            for (int tm = 0; tm < 4; tm++) {
                int r = wm * 64 + tm * 16 + gid;
                a[tm][0] = Asb[r    ][kk + tig];
                a[tm][1] = Asb[r + 8][kk + tig];
                a[tm][2] = Asb[r    ][kk + tig + 4];
                a[tm][3] = Asb[r + 8][kk + tig + 4];
            }
            #pragma unroll
            for (int tn = 0; tn < 4; tn++) {
                int ncol = wn * 32 + tn * 8 + gid;
                if (B_NT) {
                    b[tn][0] = Bsb[ncol * 20 + kk + tig];
                    b[tn][1] = Bsb[ncol * 20 + kk + tig + 4];
                } else {
                    b[tn][0] = Bsb[(kk + tig)     * 136 + ncol];
                    b[tn][1] = Bsb[(kk + tig + 4) * 136 + ncol];
                }
            }
            #pragma unroll
            for (int tm = 0; tm < 4; tm++)
                #pragma unroll
                for (int tn = 0; tn < 4; tn++)
                    mma_tf32(c[tm][tn], a[tm], b[tn]);
        }

        if (more) {
            const int nxt = cur ^ 1;
            #pragma unroll
            for (int j = 0; j < 2; j++) {
                *(uint4*)(&As[nxt][0][0] + a_sm[j]) = f2tf4(av[j]);
                *(uint4*)(&Bs[nxt][0]    + b_sm[j]) = f2tf4(bv[j]);
            }
        }
        __syncthreads();
    }

    // ---- epilogue ----
    #pragma unroll
    for (int tm = 0; tm < 4; tm++) {
        #pragma unroll
        for (int tn = 0; tn < 4; tn++) {
            int row = m0 + wm * 64 + tm * 16 + gid;
            int col = n0 + wn * 32 + tn * 8 + 2 * tig;
            #pragma unroll
            for (int q = 0; q < 4; q++) {
                int r  = row + (q >> 1) * 8;
                int cc = col + (q & 1);
                float v = c[tm][tn][q];
                if (GELU) v = gelu_tanh(v);
                C[(long long)r * ldC + cc] = v;
            }
        }
    }
}

__global__ __launch_bounds__(256) void combine_kernel(
    float* __restrict__ out, const float* __restrict__ y,
    const int* __restrict__ pair_slot, const float* __restrict__ pair_w)
{
    int t = blockIdx.x;
    int slot[KTOP]; float w[KTOP];
    #pragma unroll
    for (int k = 0; k < KTOP; k++) {
        slot[k] = pair_slot[t * KTOP + k];
        w[k]    = pair_w[t * KTOP + k];
    }
    int h4 = threadIdx.x;
    float4 acc = *(float4*)(out + (size_t)t * H + h4 * 4);
    #pragma unroll
    for (int k = 0; k < KTOP; k++) {
        float4 v = *(const float4*)(y + (size_t)slot[k] * H + h4 * 4);
        acc.x += w[k] * v.x; acc.y += w[k] * v.y;
        acc.z += w[k] * v.z; acc.w += w[k] * v.w;
    }
    *(float4*)(out + (size_t)t * H + h4 * 4) = acc;
}

// ---------------- launch ----------------
extern "C" void kernel_launch(void* const* d_in, const int* in_sizes, int n_in,
                              void* d_out, int out_size)
{
    const float* x   = (const float*)d_in[0];
    const float* rw  = (const float*)d_in[1];
    const float* eb  = (const float*)d_in[2];
    const float* w1  = (const float*)d_in[3];
    const float* w2  = (const float*)d_in[4];
    const float* sw1 = (const float*)d_in[5];
    const float* sw2 = (const float*)d_in[6];
    float* out = (float*)d_out;

    void *pcnt, *ptok, *pps, *ppw, *pmid, *py, *psmid;
    cudaGetSymbolAddress(&pcnt,  g_cnt);
    cudaGetSymbolAddress(&ptok,  g_slot_token);
    cudaGetSymbolAddress(&pps,   g_pair_slot);
    cudaGetSymbolAddress(&ppw,   g_pair_w);
    cudaGetSymbolAddress(&pmid,  g_mid);
    cudaGetSymbolAddress(&py,    g_y);
    cudaGetSymbolAddress(&psmid, g_smid);

    int*   cnt       = (int*)pcnt;
    int*   slot_tok  = (int*)ptok;
    int*   pair_slot = (int*)pps;
    float* pair_w    = (float*)ppw;
    float* mid       = (float*)pmid;
    float* y         = (float*)py;
    float* smid      = (float*)psmid;

    zero_cnt_kernel<<<1, 64>>>(cnt);
    router_kernel<<<T, 256>>>(x, rw, eb, cnt, slot_tok, pair_slot, pair_w);

    // expert GEMM1: mid[e] = gelu(gather(x) @ w1[e])   (M<=cnt[e], N=512, K=1024)
    gemm_tf32_kernel<true, false, true><<<dim3(F / 128, CAP / 128, E), 256>>>(
        x, 0LL, H, w1, (long long)H * F,
        mid, (long long)CAP * F, F,
        H, F, cnt, CAP, slot_tok);

    // expert GEMM2: y[e] = mid[e] @ w2[e]              (N=1024, K=512)
    gemm_tf32_kernel<false, false, false><<<dim3(H / 128, CAP / 128, E), 256>>>(
        mid, (long long)CAP * F, F, w2, (long long)F * H,
        y, (long long)CAP * H, H,
        F, H, cnt, CAP, slot_tok);

    // shared GEMM1: smid = gelu(x @ sw1^T)  (B is [n][k], NT)
    gemm_tf32_kernel<false, true, true><<<dim3(SF / 128, T / 128, 1), 256>>>(
        x, 0LL, H, sw1, 0LL,
        smid, 0LL, SF,
        H, SF, nullptr, T, nullptr);

    // shared GEMM2: out = smid @ sw2^T  (writes full output)
    gemm_tf32_kernel<false, true, false><<<dim3(H / 128, T / 128, 1), 256>>>(
        smid, 0LL, SF, sw2, 0LL,
        out, 0LL, H,
        SF, H, nullptr, T, nullptr);

    // combine: out += sum_k w_k * y[slot_k]  (gather, no atomics)
    combine_kernel<<<T, 256>>>(out, y, pair_slot, pair_w);
}

// round 5
// speedup vs baseline: 1.2320x; 1.0034x over previous
#include <cuda_runtime.h>
#include <math.h>
#include <stdint.h>

#define E    64
#define KTOP 6
#define H    1024
#define F    512
#define SF   2048
#define T    2048
#define CAP  384   // 2 * ceil(T*K/E)

// tcgen05 exists only on arch-specific targets (sm_100a/101a/103a).
// The harness also compiles a generic compute_103 PTX pass; give it a fallback.
#if !defined(__CUDA_ARCH__) || defined(__CUDA_ARCH_FEAT_SM103_ALL) || \
    defined(__CUDA_ARCH_FEAT_SM100_ALL) || defined(__CUDA_ARCH_FEAT_SM101_ALL) || \
    defined(__CUDA_ARCH_SPECIFIC__)
#define TC_OK 1
#else
#define TC_OK 0
#endif

// ---------------- scratch (static device globals; allocation-free) ----------------
__device__ int   g_cnt[E];
__device__ int   g_slot_token[E * CAP];
__device__ int   g_pair_slot[T * KTOP];
__device__ float g_pair_w[T * KTOP];
__device__ float g_mid[(size_t)E * CAP * F];
__device__ float g_y[(size_t)E * CAP * H];
__device__ float g_smid[(size_t)T * SF];
__device__ float g_w1t[(size_t)E * F * H];   // w1 transposed: [E][F][H]
__device__ float g_w2t[(size_t)E * H * F];   // w2 transposed: [E][H][F]

// ---------------- generic helpers ----------------
__device__ __forceinline__ float gelu_tanh(float x) {
    float u = 0.7978845608028654f * (x + 0.044715f * x * x * x);
    return 0.5f * x * (1.0f + tanhf(u));
}

#if TC_OK
// ---------------- PTX helpers (tcgen05 path only) ----------------
__device__ __forceinline__ uint32_t smem_u32(const void* p) {
    uint32_t a;
    asm("{ .reg .u64 t; cvta.to.shared.u64 t, %1; cvt.u32.u64 %0, t; }" : "=r"(a) : "l"(p));
    return a;
}

__device__ __forceinline__ uint32_t elect_one() {
    uint32_t pred;
    asm volatile("{\n\t.reg .pred p;\n\telect.sync _|p, 0xFFFFFFFF;\n\tselp.b32 %0, 1, 0, p;\n\t}" : "=r"(pred));
    return pred;
}

__device__ __forceinline__ unsigned f2tf(float f) {
    unsigned u;
    asm("cvt.rna.tf32.f32 %0, %1;" : "=r"(u) : "f"(f));
    return u;
}

__device__ __forceinline__ void sts_tf4(uint32_t addr, float4 v) {
    asm volatile("st.shared.v4.b32 [%0], {%1,%2,%3,%4};"
        :: "r"(addr), "r"(f2tf(v.x)), "r"(f2tf(v.y)), "r"(f2tf(v.z)), "r"(f2tf(v.w)) : "memory");
}

__device__ __forceinline__ void mbar_init(uint32_t mbar, uint32_t cnt) {
    asm volatile("mbarrier.init.shared.b64 [%0], %1;" :: "r"(mbar), "r"(cnt) : "memory");
}

__device__ __forceinline__ void mbar_wait(uint32_t mbar, uint32_t parity) {
    asm volatile(
        "{\n\t.reg .pred P;\n"
        "W_%=:\n\t"
        "mbarrier.try_wait.parity.acquire.cta.shared::cta.b64 P, [%0], %1, 0x989680;\n\t"
        "@P bra.uni D_%=;\n\t"
        "bra.uni W_%=;\n"
        "D_%=:\n\t}"
        :: "r"(mbar), "r"(parity) : "memory");
}

__device__ __forceinline__ void tc_alloc(uint32_t smem_slot, uint32_t ncols) {
    asm volatile("tcgen05.alloc.cta_group::1.sync.aligned.shared::cta.b32 [%0], %1;"
        :: "r"(smem_slot), "r"(ncols) : "memory");
}
__device__ __forceinline__ void tc_relinquish() {
    asm volatile("tcgen05.relinquish_alloc_permit.cta_group::1.sync.aligned;");
}
__device__ __forceinline__ void tc_dealloc(uint32_t tmem, uint32_t ncols) {
    asm volatile("tcgen05.dealloc.cta_group::1.sync.aligned.b32 %0, %1;" :: "r"(tmem), "r"(ncols));
}
__device__ __forceinline__ void tc_commit(uint32_t mbar) {
    asm volatile("tcgen05.commit.cta_group::1.mbarrier::arrive::one.shared::cluster.b64 [%0];"
        :: "r"(mbar) : "memory");
}
__device__ __forceinline__ void fence_async() {
    asm volatile("fence.proxy.async.shared::cta;" ::: "memory");
}
__device__ __forceinline__ void tc_fence_after() {
    asm volatile("tcgen05.fence::after_thread_sync;" ::: "memory");
}
__device__ __forceinline__ void tc_wait_ld() {
    asm volatile("tcgen05.wait::ld.sync.aligned;" ::: "memory");
}

__device__ __forceinline__ void mma_tf32_ss(uint32_t d, uint64_t ad, uint64_t bd,
                                            uint32_t idesc, uint32_t en) {
    asm volatile(
        "{\n\t.reg .pred p;\n\t"
        "setp.ne.u32 p, %5, 0;\n\t"
        "tcgen05.mma.cta_group::1.kind::tf32 [%0], %1, %2, %3, {%4, %4, %4, %4}, p;\n\t}"
        :: "r"(d), "l"(ad), "l"(bd), "r"(idesc), "r"(0u), "r"(en) : "memory");
}

__device__ __forceinline__ void ldtm32(uint32_t* r, uint32_t addr) {
    asm volatile(
        "tcgen05.ld.sync.aligned.32x32b.x32.b32 "
        "{%0, %1, %2, %3, %4, %5, %6, %7, %8, %9, %10, %11, %12, %13, %14, %15, "
        "%16, %17, %18, %19, %20, %21, %22, %23, %24, %25, %26, %27, %28, %29, %30, %31}, [%32];"
        : "=r"(r[0]), "=r"(r[1]), "=r"(r[2]), "=r"(r[3]), "=r"(r[4]), "=r"(r[5]), "=r"(r[6]), "=r"(r[7]),
          "=r"(r[8]), "=r"(r[9]), "=r"(r[10]), "=r"(r[11]), "=r"(r[12]), "=r"(r[13]), "=r"(r[14]), "=r"(r[15]),
          "=r"(r[16]), "=r"(r[17]), "=r"(r[18]), "=r"(r[19]), "=r"(r[20]), "=r"(r[21]), "=r"(r[22]), "=r"(r[23]),
          "=r"(r[24]), "=r"(r[25]), "=r"(r[26]), "=r"(r[27]), "=r"(r[28]), "=r"(r[29]), "=r"(r[30]), "=r"(r[31])
        : "r"(addr));
}

__device__ __forceinline__ uint32_t sw128(uint32_t byte_off) {
    return byte_off ^ ((byte_off >> 3) & 0x70);
}

// K-major SW128 desc base: layout=2, version=1, SBO=64, LBO=1 (validated pattern)
#define DESCK  0x4000404000010000ull
// idesc kind::tf32: dtype=F32(bit4), atype=TF32(2@bits7-9), btype=TF32(2@bits10-12),
// N=256 (32 @bits17-22), M=128 (8 @bits24-28)
#define IDESC_TF32_N256 0x8400910u
#endif  // TC_OK

#define SMEM_BYTES 99392   // 1024 align slack + 2*16KB A + 2*32KB B + ctrl

// ---------------- small kernels ----------------
__global__ void zero_cnt_kernel(int* cnt) {
    if (threadIdx.x < E) cnt[threadIdx.x] = 0;
}

// src: [E][R][Cc] -> dst: [E][Cc][R]; grid (Cc/32, R/32, E), 256 threads (32x8)
__global__ __launch_bounds__(256) void transpose_kernel(
    const float* __restrict__ src, float* __restrict__ dst, int R, int Cc)
{
    __shared__ float tile[32][33];
    int e = blockIdx.z;
    const float* S = src + (size_t)e * R * Cc;
    float*       D = dst + (size_t)e * R * Cc;
    int c0 = blockIdx.x * 32, r0 = blockIdx.y * 32;
    int tx = threadIdx.x & 31, ty = threadIdx.x >> 5;
    #pragma unroll
    for (int i = 0; i < 4; i++)
        tile[ty + i * 8][tx] = S[(size_t)(r0 + ty + i * 8) * Cc + c0 + tx];
    __syncthreads();
    #pragma unroll
    for (int i = 0; i < 4; i++)
        D[(size_t)(c0 + ty + i * 8) * R + r0 + tx] = tile[tx][ty + i * 8];
}

__global__ __launch_bounds__(256) void router_kernel(
    const float* __restrict__ x, const float* __restrict__ rw,
    const float* __restrict__ bias,
    int* __restrict__ cnt, int* __restrict__ slot_token,
    int* __restrict__ pair_slot, float* __restrict__ pair_w)
{
    int t = blockIdx.x;
    __shared__ float xs[H];
    __shared__ float sc[E];
    __shared__ float sb[E];
    for (int i = threadIdx.x; i < H; i += 256) xs[i] = x[(size_t)t * H + i];
    if (threadIdx.x < E) sb[threadIdx.x] = bias[threadIdx.x];
    __syncthreads();

    int warp = threadIdx.x >> 5, lane = threadIdx.x & 31;
    for (int e = warp; e < E; e += 8) {
        const float* w = rw + (size_t)e * H;
        float s = 0.f;
        for (int i = lane; i < H; i += 32) s += xs[i] * w[i];
        #pragma unroll
        for (int o = 16; o; o >>= 1) s += __shfl_xor_sync(0xffffffffu, s, o);
        if (lane == 0) sc[e] = 1.f / (1.f + expf(-s));
    }
    __syncthreads();

    if (threadIdx.x == 0) {
        unsigned long long used = 0ull;
        int idx[KTOP]; float tsc[KTOP]; float sum = 0.f;
        #pragma unroll
        for (int k = 0; k < KTOP; k++) {
            float best = -1e30f; int bi = 0;
            for (int e = 0; e < E; e++) {
                if (used & (1ull << e)) continue;
                float v = sc[e] + sb[e];
                if (v > best) { best = v; bi = e; }
            }
            used |= 1ull << bi; idx[k] = bi; tsc[k] = sc[bi]; sum += sc[bi];
        }
        float inv = 1.f / (sum + 1e-20f);
        #pragma unroll
        for (int k = 0; k < KTOP; k++) {
            int e = idx[k];
            int pos = atomicAdd(&cnt[e], 1);
            float w = tsc[k] * inv;
            int slot;
            if (pos < CAP) { slot = e * CAP + pos; slot_token[slot] = t; }
            else           { slot = 0; w = 0.f; }
            pair_slot[t * KTOP + k] = slot;
            pair_w[t * KTOP + k]    = w;
        }
    }
}

// ---------------- tcgen05 TF32 GEMM (K-major only; generic-target fallback) ----------------
// Block tile: M=128, N=256, K-chunk=32. 256 threads. D in TMEM (256 cols).
// A K-major SW128 (128 rows x 128B); B K-major SW128 (256 rows x 128B), B stored [n][k].
template<bool GATHER, bool GELU>
__global__ __launch_bounds__(256) void gemm_tc(
    const float* __restrict__ Aall, long long sAe, int ldA,
    const float* __restrict__ Ball, long long sBe,
    float* __restrict__ Call, long long sCe, int ldC,
    int Kdim, int Ncols,
    const int* __restrict__ cnts, int Mmax,
    const int* __restrict__ tokall)
{
    const int e  = blockIdx.z;
    const int m0 = blockIdx.y * 128;
    const int n0 = blockIdx.x * 256;
    int M = Mmax;
    if (cnts) { M = min(cnts[e], Mmax); if (m0 >= M) return; }

    const float* B = Ball + (long long)e * sBe;
    float*       C = Call + (long long)e * sCe;

#if TC_OK
    extern __shared__ char smraw_c[];
    const uint32_t sbase = (smem_u32(smraw_c) + 1023u) & ~1023u;
    const uint32_t sA0 = sbase, sA1 = sbase + 16384;
    const uint32_t sB0 = sbase + 32768, sB1 = sbase + 65536;
    const uint32_t ctrl = sbase + 98304;      // [ctrl]=tmem ptr, [ctrl+8],[ctrl+16]=mbars

    const int tid  = threadIdx.x;
    const int warp = tid >> 5;
    const int lane = tid & 31;

    if (warp == 0) { tc_alloc(ctrl, 256); tc_relinquish(); }
    if (tid == 0)  { mbar_init(ctrl + 8, 1); mbar_init(ctrl + 16, 1); }
    __syncthreads();
    uint32_t tmem;
    asm volatile("ld.shared.b32 %0, [%1];" : "=r"(tmem) : "r"(ctrl));

    // ---- load descriptors ----
    const float* aptr[4]; uint32_t a_sts[4];
    #pragma unroll
    for (int j = 0; j < 4; j++) {
        int g = tid + j * 256;
        int m = g >> 3, k4 = (g & 7) * 4;
        a_sts[j] = sw128(m * 128 + k4 * 4);
        if (GATHER) {
            int tok = (m0 + m < M) ? tokall[e * CAP + m0 + m] : -1;
            aptr[j] = (tok >= 0) ? (Aall + (long long)tok * ldA + k4) : nullptr;
        } else {
            aptr[j] = Aall + (long long)e * sAe + (long long)(m0 + m) * ldA + k4;
        }
    }
    const float* bptr[8]; uint32_t b_sts[8];
    #pragma unroll
    for (int j = 0; j < 8; j++) {
        int g = tid + j * 256;
        int n = g >> 3, k4 = (g & 7) * 4;
        b_sts[j] = sw128(n * 128 + k4 * 4);
        bptr[j]  = B + (long long)(n0 + n) * Kdim + k4;
    }

    const int ntiles = Kdim >> 5;

    for (int it = 0; it < ntiles; ++it) {
        const int buf = it & 1;
        const uint32_t sa = buf ? sA1 : sA0;
        const uint32_t sb = buf ? sB1 : sB0;
        if (it >= 2) mbar_wait(ctrl + 8 + 8 * buf, ((it >> 1) + 1) & 1);

        const long long ka = (long long)it * 32;
        float4 va[4], vb[8];
        #pragma unroll
        for (int j = 0; j < 4; j++)
            va[j] = aptr[j] ? *(const float4*)(aptr[j] + ka) : make_float4(0.f, 0.f, 0.f, 0.f);
        #pragma unroll
        for (int j = 0; j < 8; j++)
            vb[j] = *(const float4*)(bptr[j] + ka);
        #pragma unroll
        for (int j = 0; j < 4; j++) sts_tf4(sa + a_sts[j], va[j]);
        #pragma unroll
        for (int j = 0; j < 8; j++) sts_tf4(sb + b_sts[j], vb[j]);
        __syncthreads();

        if (warp == 0 && elect_one()) {
            fence_async();
            uint64_t ad = DESCK | ((sa >> 4) & 0x3FFFu);
            uint64_t bd = DESCK | ((sb >> 4) & 0x3FFFu);
            #pragma unroll
            for (int s = 0; s < 4; s++)
                mma_tf32_ss(tmem, ad + 2 * s, bd + 2 * s, IDESC_TF32_N256, (it | s) != 0);
            tc_commit(ctrl + 8 + 8 * buf);
        }
    }

    // wait for all MMAs (both buffers' last commits)
    {
        int it1 = ntiles - 1, it2 = ntiles - 2;
        mbar_wait(ctrl + 8 + 8 * (it2 & 1), (it2 >> 1) & 1);
        mbar_wait(ctrl + 8 + 8 * (it1 & 1), (it1 >> 1) & 1);
    }
    tc_fence_after();

    // ---- epilogue: TMEM -> (GELU) -> C ----
    {
        const int w4 = warp & 3, half = warp >> 2;
        const int row = m0 + w4 * 32 + lane;
        float* crow = C + (long long)row * ldC + n0;
        #pragma unroll
        for (int i = 0; i < 4; i++) {
            int c0 = half * 128 + i * 32;
            uint32_t r[32];
            ldtm32(r, tmem + c0);
            tc_wait_ld();
            float fv[32];
            #pragma unroll
            for (int q = 0; q < 32; q++) {
                float v = __uint_as_float(r[q]);
                fv[q] = GELU ? gelu_tanh(v) : v;
            }
            #pragma unroll
            for (int q = 0; q < 8; q++) {
                float4 o = make_float4(fv[q*4], fv[q*4+1], fv[q*4+2], fv[q*4+3]);
                *(float4*)(crow + c0 + q * 4) = o;
            }
        }
    }
    __syncthreads();
    if (warp == 0) tc_dealloc(tmem, 256);

#else  // ---------- generic-target SIMT fallback (correct, slow; not expected to run) ----------
    const int tid = threadIdx.x;
    const int r   = tid >> 1;
    const int row = m0 + r;
    const int nh  = (tid & 1) * 128;
    const float* arow;
    if (GATHER) {
        int tok = (row < M) ? tokall[e * CAP + row] : -1;
        arow = (tok >= 0) ? (Aall + (long long)tok * ldA) : nullptr;
    } else {
        arow = Aall + (long long)e * sAe + (long long)row * ldA;
    }
    for (int c = 0; c < 4; c++) {
        float acc[32];
        #pragma unroll
        for (int q = 0; q < 32; q++) acc[q] = 0.f;
        int nb = n0 + nh + c * 32;
        for (int k = 0; k < Kdim; k++) {
            float a = arow ? arow[k] : 0.f;
            #pragma unroll 8
            for (int q = 0; q < 32; q++) acc[q] += a * B[(long long)(nb + q) * Kdim + k];
        }
        float* crow = C + (long long)row * ldC;
        for (int q = 0; q < 32; q++) {
            float v = acc[q];
            if (GELU) v = gelu_tanh(v);
            crow[nb + q] = v;
        }
    }
#endif
}

__global__ __launch_bounds__(256) void combine_kernel(
    float* __restrict__ out, const float* __restrict__ y,
    const int* __restrict__ pair_slot, const float* __restrict__ pair_w)
{
    int t = blockIdx.x;
    int slot[KTOP]; float w[KTOP];
    #pragma unroll
    for (int k = 0; k < KTOP; k++) {
        slot[k] = pair_slot[t * KTOP + k];
        w[k]    = pair_w[t * KTOP + k];
    }
    int h4 = threadIdx.x;
    float4 acc = *(float4*)(out + (size_t)t * H + h4 * 4);
    #pragma unroll
    for (int k = 0; k < KTOP; k++) {
        float4 v = *(const float4*)(y + (size_t)slot[k] * H + h4 * 4);
        acc.x += w[k] * v.x; acc.y += w[k] * v.y;
        acc.z += w[k] * v.z; acc.w += w[k] * v.w;
    }
    *(float4*)(out + (size_t)t * H + h4 * 4) = acc;
}

// ---------------- launch ----------------
extern "C" void kernel_launch(void* const* d_in, const int* in_sizes, int n_in,
                              void* d_out, int out_size)
{
    const float* x   = (const float*)d_in[0];
    const float* rw  = (const float*)d_in[1];
    const float* eb  = (const float*)d_in[2];
    const float* w1  = (const float*)d_in[3];
    const float* w2  = (const float*)d_in[4];
    const float* sw1 = (const float*)d_in[5];
    const float* sw2 = (const float*)d_in[6];
    float* out = (float*)d_out;

    void *pcnt, *ptok, *pps, *ppw, *pmid, *py, *psmid, *pw1t, *pw2t;
    cudaGetSymbolAddress(&pcnt,  g_cnt);
    cudaGetSymbolAddress(&ptok,  g_slot_token);
    cudaGetSymbolAddress(&pps,   g_pair_slot);
    cudaGetSymbolAddress(&ppw,   g_pair_w);
    cudaGetSymbolAddress(&pmid,  g_mid);
    cudaGetSymbolAddress(&py,    g_y);
    cudaGetSymbolAddress(&psmid, g_smid);
    cudaGetSymbolAddress(&pw1t,  g_w1t);
    cudaGetSymbolAddress(&pw2t,  g_w2t);

    int*   cnt       = (int*)pcnt;
    int*   slot_tok  = (int*)ptok;
    int*   pair_slot = (int*)pps;
    float* pair_w    = (float*)ppw;
    float* mid       = (float*)pmid;
    float* y         = (float*)py;
    float* smid      = (float*)psmid;
    float* w1t       = (float*)pw1t;
    float* w2t       = (float*)pw2t;

    cudaFuncSetAttribute(gemm_tc<true,  true>,  cudaFuncAttributeMaxDynamicSharedMemorySize, SMEM_BYTES);
    cudaFuncSetAttribute(gemm_tc<false, true>,  cudaFuncAttributeMaxDynamicSharedMemorySize, SMEM_BYTES);
    cudaFuncSetAttribute(gemm_tc<false, false>, cudaFuncAttributeMaxDynamicSharedMemorySize, SMEM_BYTES);

    zero_cnt_kernel<<<1, 64>>>(cnt);
    router_kernel<<<T, 256>>>(x, rw, eb, cnt, slot_tok, pair_slot, pair_w);

    // transpose expert weights to K-major: w1 [E][H][F] -> w1t [E][F][H]; w2 [E][F][H] likewise
    transpose_kernel<<<dim3(F / 32, H / 32, E), 256>>>(w1, w1t, H, F);
    transpose_kernel<<<dim3(H / 32, F / 32, E), 256>>>(w2, w2t, F, H);

    // expert GEMM1: mid[e] = gelu(gather(x) @ w1[e])   B = w1t[e] [F][H] K-major
    gemm_tc<true, true><<<dim3(F / 256, CAP / 128, E), 256, SMEM_BYTES>>>(
        x, 0LL, H, w1t, (long long)H * F,
        mid, (long long)CAP * F, F,
        H, F, cnt, CAP, slot_tok);

    // expert GEMM2: y[e] = mid[e] @ w2[e]              B = w2t[e] [H][F] K-major
    gemm_tc<false, false><<<dim3(H / 256, CAP / 128, E), 256, SMEM_BYTES>>>(
        mid, (long long)CAP * F, F, w2t, (long long)F * H,
        y, (long long)CAP * H, H,
        F, H, cnt, CAP, slot_tok);

    // shared GEMM1: smid = gelu(x @ sw1^T)   sw1 is [SF][H] (K-contig) -> K-major
    gemm_tc<false, true><<<dim3(SF / 256, T / 128, 1), 256, SMEM_BYTES>>>(
        x, 0LL, H, sw1, 0LL,
        smid, 0LL, SF,
        H, SF, nullptr, T, nullptr);

    // shared GEMM2: out = smid @ sw2^T       sw2 is [H][SF] (K-contig) -> K-major
    gemm_tc<false, false><<<dim3(H / 256, T / 128, 1), 256, SMEM_BYTES>>>(
        smid, 0LL, SF, sw2, 0LL,
        out, 0LL, H,
        SF, H, nullptr, T, nullptr);

    // combine: out += sum_k w_k * y[slot_k]
    combine_kernel<<<T, 256>>>(out, y, pair_slot, pair_w);
}

// round 6
// speedup vs baseline: 1.4773x; 1.1991x over previous
#include <cuda_runtime.h>
#include <math.h>
#include <stdint.h>

#define E    64
#define KTOP 6
#define H    1024
#define F    512
#define SF   2048
#define T    2048
#define CAP  384   // 2 * ceil(T*K/E)

#if !defined(__CUDA_ARCH__) || defined(__CUDA_ARCH_FEAT_SM103_ALL) || \
    defined(__CUDA_ARCH_FEAT_SM100_ALL) || defined(__CUDA_ARCH_FEAT_SM101_ALL) || \
    defined(__CUDA_ARCH_SPECIFIC__)
#define TC_OK 1
#else
#define TC_OK 0
#endif

// ---------------- scratch (static device globals; allocation-free) ----------------
__device__ int   g_cnt[E];
__device__ int   g_slot_token[E * CAP];
__device__ int   g_pair_slot[T * KTOP];
__device__ float g_pair_w[T * KTOP];
__device__ float g_mid[(size_t)E * CAP * F];
__device__ float g_y[(size_t)E * CAP * H];
__device__ float g_smid[(size_t)T * SF];
__device__ float g_w1t[(size_t)E * F * H];   // w1 transposed + tf32-rounded
__device__ float g_w2t[(size_t)E * H * F];   // w2 transposed + tf32-rounded
__device__ float g_xr[(size_t)T * H];        // x  tf32-rounded
__device__ float g_sw1r[(size_t)SF * H];     // sw1 tf32-rounded
__device__ float g_sw2r[(size_t)H * SF];     // sw2 tf32-rounded

// ---------------- generic helpers ----------------
__device__ __forceinline__ float gelu_tanh(float x) {
    float u = 0.7978845608028654f * (x + 0.044715f * x * x * x);
    return 0.5f * x * (1.0f + tanhf(u));
}

__device__ __forceinline__ float f2tf_f(float f) {
    unsigned u;
    asm("cvt.rna.tf32.f32 %0, %1;" : "=r"(u) : "f"(f));
    return __uint_as_float(u);
}

#if TC_OK
// ---------------- PTX helpers (tcgen05 path) ----------------
__device__ __forceinline__ uint32_t smem_u32(const void* p) {
    uint32_t a;
    asm("{ .reg .u64 t; cvta.to.shared.u64 t, %1; cvt.u32.u64 %0, t; }" : "=r"(a) : "l"(p));
    return a;
}
__device__ __forceinline__ uint32_t elect_one() {
    uint32_t pred;
    asm volatile("{\n\t.reg .pred p;\n\telect.sync _|p, 0xFFFFFFFF;\n\tselp.b32 %0, 1, 0, p;\n\t}" : "=r"(pred));
    return pred;
}
__device__ __forceinline__ void cpasync16(uint32_t dst, const void* src, uint32_t sz) {
    asm volatile("cp.async.cg.shared.global [%0], [%1], 16, %2;"
        :: "r"(dst), "l"(src), "r"(sz) : "memory");
}
__device__ __forceinline__ void cp_commit() {
    asm volatile("cp.async.commit_group;" ::: "memory");
}
__device__ __forceinline__ void cp_wait2() {
    asm volatile("cp.async.wait_group 2;" ::: "memory");
}
__device__ __forceinline__ void mbar_init(uint32_t mbar, uint32_t cnt) {
    asm volatile("mbarrier.init.shared.b64 [%0], %1;" :: "r"(mbar), "r"(cnt) : "memory");
}
__device__ __forceinline__ void mbar_wait(uint32_t mbar, uint32_t parity) {
    asm volatile(
        "{\n\t.reg .pred P;\n"
        "W_%=:\n\t"
        "mbarrier.try_wait.parity.acquire.cta.shared::cta.b64 P, [%0], %1, 0x989680;\n\t"
        "@P bra.uni D_%=;\n\t"
        "bra.uni W_%=;\n"
        "D_%=:\n\t}"
        :: "r"(mbar), "r"(parity) : "memory");
}
__device__ __forceinline__ void tc_alloc(uint32_t smem_slot, uint32_t ncols) {
    asm volatile("tcgen05.alloc.cta_group::1.sync.aligned.shared::cta.b32 [%0], %1;"
        :: "r"(smem_slot), "r"(ncols) : "memory");
}
__device__ __forceinline__ void tc_relinquish() {
    asm volatile("tcgen05.relinquish_alloc_permit.cta_group::1.sync.aligned;");
}
__device__ __forceinline__ void tc_dealloc(uint32_t tmem, uint32_t ncols) {
    asm volatile("tcgen05.dealloc.cta_group::1.sync.aligned.b32 %0, %1;" :: "r"(tmem), "r"(ncols));
}
__device__ __forceinline__ void tc_commit(uint32_t mbar) {
    asm volatile("tcgen05.commit.cta_group::1.mbarrier::arrive::one.shared::cluster.b64 [%0];"
        :: "r"(mbar) : "memory");
}
__device__ __forceinline__ void fence_async() {
    asm volatile("fence.proxy.async.shared::cta;" ::: "memory");
}
__device__ __forceinline__ void tc_fence_after() {
    asm volatile("tcgen05.fence::after_thread_sync;" ::: "memory");
}
__device__ __forceinline__ void tc_wait_ld() {
    asm volatile("tcgen05.wait::ld.sync.aligned;" ::: "memory");
}
__device__ __forceinline__ void mma_tf32_ss(uint32_t d, uint64_t ad, uint64_t bd,
                                            uint32_t idesc, uint32_t en) {
    asm volatile(
        "{\n\t.reg .pred p;\n\t"
        "setp.ne.u32 p, %5, 0;\n\t"
        "tcgen05.mma.cta_group::1.kind::tf32 [%0], %1, %2, %3, {%4, %4, %4, %4}, p;\n\t}"
        :: "r"(d), "l"(ad), "l"(bd), "r"(idesc), "r"(0u), "r"(en) : "memory");
}
__device__ __forceinline__ void ldtm32(uint32_t* r, uint32_t addr) {
    asm volatile(
        "tcgen05.ld.sync.aligned.32x32b.x32.b32 "
        "{%0, %1, %2, %3, %4, %5, %6, %7, %8, %9, %10, %11, %12, %13, %14, %15, "
        "%16, %17, %18, %19, %20, %21, %22, %23, %24, %25, %26, %27, %28, %29, %30, %31}, [%32];"
        : "=r"(r[0]), "=r"(r[1]), "=r"(r[2]), "=r"(r[3]), "=r"(r[4]), "=r"(r[5]), "=r"(r[6]), "=r"(r[7]),
          "=r"(r[8]), "=r"(r[9]), "=r"(r[10]), "=r"(r[11]), "=r"(r[12]), "=r"(r[13]), "=r"(r[14]), "=r"(r[15]),
          "=r"(r[16]), "=r"(r[17]), "=r"(r[18]), "=r"(r[19]), "=r"(r[20]), "=r"(r[21]), "=r"(r[22]), "=r"(r[23]),
          "=r"(r[24]), "=r"(r[25]), "=r"(r[26]), "=r"(r[27]), "=r"(r[28]), "=r"(r[29]), "=r"(r[30]), "=r"(r[31])
        : "r"(addr));
}
__device__ __forceinline__ uint32_t sw128(uint32_t byte_off) {
    return byte_off ^ ((byte_off >> 3) & 0x70);
}
// K-major SW128 desc base: layout=2, version=1, SBO=64, LBO=1 (validated)
#define DESCK  0x4000404000010000ull
#endif  // TC_OK

// ---------------- small kernels ----------------
__global__ void zero_cnt_kernel(int* cnt) {
    if (threadIdx.x < E) cnt[threadIdx.x] = 0;
}

// elementwise tf32 round-copy (float4)
__global__ __launch_bounds__(256) void round_copy_kernel(
    const float* __restrict__ src, float* __restrict__ dst, int n4)
{
    int i = blockIdx.x * 256 + threadIdx.x;
    if (i < n4) {
        float4 v = ((const float4*)src)[i];
        v.x = f2tf_f(v.x); v.y = f2tf_f(v.y); v.z = f2tf_f(v.z); v.w = f2tf_f(v.w);
        ((float4*)dst)[i] = v;
    }
}

// src: [E][R][Cc] -> dst: [E][Cc][R], tf32-rounded on store
__global__ __launch_bounds__(256) void transpose_kernel(
    const float* __restrict__ src, float* __restrict__ dst, int R, int Cc)
{
    __shared__ float tile[32][33];
    int e = blockIdx.z;
    const float* S = src + (size_t)e * R * Cc;
    float*       D = dst + (size_t)e * R * Cc;
    int c0 = blockIdx.x * 32, r0 = blockIdx.y * 32;
    int tx = threadIdx.x & 31, ty = threadIdx.x >> 5;
    #pragma unroll
    for (int i = 0; i < 4; i++)
        tile[ty + i * 8][tx] = S[(size_t)(r0 + ty + i * 8) * Cc + c0 + tx];
    __syncthreads();
    #pragma unroll
    for (int i = 0; i < 4; i++)
        D[(size_t)(c0 + ty + i * 8) * R + r0 + tx] = f2tf_f(tile[tx][ty + i * 8]);
}

__global__ __launch_bounds__(256) void router_kernel(
    const float* __restrict__ x, const float* __restrict__ rw,
    const float* __restrict__ bias,
    int* __restrict__ cnt, int* __restrict__ slot_token,
    int* __restrict__ pair_slot, float* __restrict__ pair_w)
{
    int t = blockIdx.x;
    __shared__ float xs[H];
    __shared__ float sc[E];
    __shared__ float sb[E];
    for (int i = threadIdx.x; i < H; i += 256) xs[i] = x[(size_t)t * H + i];
    if (threadIdx.x < E) sb[threadIdx.x] = bias[threadIdx.x];
    __syncthreads();

    int warp = threadIdx.x >> 5, lane = threadIdx.x & 31;
    for (int e = warp; e < E; e += 8) {
        const float* w = rw + (size_t)e * H;
        float s = 0.f;
        for (int i = lane; i < H; i += 32) s += xs[i] * w[i];
        #pragma unroll
        for (int o = 16; o; o >>= 1) s += __shfl_xor_sync(0xffffffffu, s, o);
        if (lane == 0) sc[e] = 1.f / (1.f + expf(-s));
    }
    __syncthreads();

    if (threadIdx.x == 0) {
        unsigned long long used = 0ull;
        int idx[KTOP]; float tsc[KTOP]; float sum = 0.f;
        #pragma unroll
        for (int k = 0; k < KTOP; k++) {
            float best = -1e30f; int bi = 0;
            for (int e = 0; e < E; e++) {
                if (used & (1ull << e)) continue;
                float v = sc[e] + sb[e];
                if (v > best) { best = v; bi = e; }
            }
            used |= 1ull << bi; idx[k] = bi; tsc[k] = sc[bi]; sum += sc[bi];
        }
        float inv = 1.f / (sum + 1e-20f);
        #pragma unroll
        for (int k = 0; k < KTOP; k++) {
            int e = idx[k];
            int pos = atomicAdd(&cnt[e], 1);
            float w = tsc[k] * inv;
            int slot;
            if (pos < CAP) { slot = e * CAP + pos; slot_token[slot] = t; }
            else           { slot = 0; w = 0.f; }
            pair_slot[t * KTOP + k] = slot;
            pair_w[t * KTOP + k]    = w;
        }
    }
}

// ---------------- tcgen05 TF32 GEMM: cp.async 4-buffer pipeline ----------------
// Block tile M=128 x NTILE, K-chunk 32, 256 threads, D in TMEM.
// Operands pre-rounded to tf32 bit patterns; no in-loop conversion.
template<bool GATHER, bool GELU, bool ROUND, int NTILE>
__global__ __launch_bounds__(256) void gemm_tc(
    const float* __restrict__ Aall, long long sAe, int ldA,
    const float* __restrict__ Ball, long long sBe,
    float* __restrict__ Call, long long sCe, int ldC,
    int Kdim, int Ncols,
    const int* __restrict__ cnts, int Mmax,
    const int* __restrict__ tokall)
{
    const int e  = blockIdx.z;
    const int m0 = blockIdx.y * 128;
    const int n0 = blockIdx.x * NTILE;
    int M = Mmax;
    if (cnts) { M = min(cnts[e], Mmax); if (m0 >= M) return; }

    const float* B = Ball + (long long)e * sBe;
    float*       C = Call + (long long)e * sCe;

#if TC_OK
    constexpr int ABYTES = 16384;               // 128 rows x 128B
    constexpr int BBYTES = NTILE * 128;         // NTILE rows x 128B
    constexpr int STAGE  = ABYTES + BBYTES;
    constexpr int NB     = NTILE / 32;          // B cp.asyncs per thread
    constexpr uint32_t IDESC = (NTILE == 256) ? 0x8400910u : 0x8200910u;

    extern __shared__ char smraw_c[];
    const uint32_t sbase = (smem_u32(smraw_c) + 1023u) & ~1023u;
    const uint32_t ctrl  = sbase + 4 * STAGE;   // [0]=tmem ptr; mbars at +8,+16,+24,+32

    const int tid  = threadIdx.x;
    const int warp = tid >> 5;
    const int lane = tid & 31;

    if (warp == 0) { tc_alloc(ctrl, 256); tc_relinquish(); }
    if (tid == 0) {
        #pragma unroll
        for (int j = 0; j < 4; j++) mbar_init(ctrl + 8 + 8 * j, 1);
    }
    __syncthreads();
    uint32_t tmem;
    asm volatile("ld.shared.b32 %0, [%1];" : "=r"(tmem) : "r"(ctrl));

    // ---- per-thread load descriptors ----
    const float* aptr[4]; uint32_t a_sts[4], a_ok[4];
    #pragma unroll
    for (int j = 0; j < 4; j++) {
        int g = tid + j * 256;
        int m = g >> 3, k4 = (g & 7) * 4;
        a_sts[j] = sw128(m * 128 + k4 * 4);
        if (GATHER) {
            int tok = (m0 + m < M) ? tokall[e * CAP + m0 + m] : -1;
            a_ok[j] = (tok >= 0) ? 16u : 0u;
            aptr[j] = (tok >= 0) ? (Aall + (long long)tok * ldA + k4) : Aall;
        } else {
            a_ok[j] = 16u;
            aptr[j] = Aall + (long long)e * sAe + (long long)(m0 + m) * ldA + k4;
        }
    }
    const float* bptr[NB]; uint32_t b_sts[NB];
    #pragma unroll
    for (int j = 0; j < NB; j++) {
        int g = tid + j * 256;
        int n = g >> 3, k4 = (g & 7) * 4;
        b_sts[j] = sw128(n * 128 + k4 * 4);
        bptr[j]  = B + (long long)(n0 + n) * Kdim + k4;
    }

    const int ntiles = Kdim >> 5;

    auto issue = [&](int it) {
        uint32_t base = sbase + (it & 3) * STAGE;
        long long ka = (long long)it * 32;
        #pragma unroll
        for (int j = 0; j < 4; j++)
            cpasync16(base + a_sts[j], aptr[j] + ka, a_ok[j]);
        #pragma unroll
        for (int j = 0; j < NB; j++)
            cpasync16(base + ABYTES + b_sts[j], bptr[j] + ka, 16u);
    };

    // prologue: 3 stages in flight
    issue(0); cp_commit();
    issue(1); cp_commit();
    issue(2); cp_commit();

    for (int it = 0; it < ntiles; ++it) {
        cp_wait2();          // stage it's group retired (this thread)
        __syncthreads();     // all threads' data visible

        if (warp == 0 && elect_one()) {
            fence_async();
            uint32_t sa = sbase + (it & 3) * STAGE;
            uint64_t ad = DESCK | ((sa >> 4) & 0x3FFFu);
            uint64_t bd = DESCK | (((sa + ABYTES) >> 4) & 0x3FFFu);
            #pragma unroll
            for (int s = 0; s < 4; s++)
                mma_tf32_ss(tmem, ad + 2 * s, bd + 2 * s, IDESC, (it | s) != 0);
            tc_commit(ctrl + 8 + 8 * (it & 3));
        }

        if (it + 3 < ntiles) {
            if (it >= 1) {
                int p = it - 1;                     // MMA(it-1) freed buffer (it+3)&3
                mbar_wait(ctrl + 8 + 8 * (p & 3), (p >> 2) & 1);
            }
            issue(it + 3);
        }
        cp_commit();         // always commit (possibly empty) to keep accounting
    }

    {   // wait last MMA (in-order completion)
        int p = ntiles - 1;
        mbar_wait(ctrl + 8 + 8 * (p & 3), (p >> 2) & 1);
    }
    tc_fence_after();

    // ---- epilogue: TMEM -> (GELU/ROUND) -> C ----
    {
        const int w4 = warp & 3, half = warp >> 2;
        const int row = m0 + w4 * 32 + lane;
        float* crow = C + (long long)row * ldC + n0;
        #pragma unroll
        for (int i = 0; i < NTILE / 64; i++) {
            int c0 = half * (NTILE / 2) + i * 32;
            uint32_t r[32];
            ldtm32(r, tmem + c0);
            tc_wait_ld();
            float fv[32];
            #pragma unroll
            for (int q = 0; q < 32; q++) {
                float v = __uint_as_float(r[q]);
                if (GELU)  v = gelu_tanh(v);
                if (ROUND) v = f2tf_f(v);
                fv[q] = v;
            }
            #pragma unroll
            for (int q = 0; q < 8; q++) {
                float4 o = make_float4(fv[q*4], fv[q*4+1], fv[q*4+2], fv[q*4+3]);
                *(float4*)(crow + c0 + q * 4) = o;
            }
        }
    }
    __syncthreads();
    if (warp == 0) tc_dealloc(tmem, 256);

#else  // ---------- generic-target SIMT fallback (correct, slow; never runs on device) ----------
    const int tid = threadIdx.x;
    const int nper = NTILE / 128;   // 1 or 2 col-halves of 128
    const int r   = tid >> 1;
    const int row = m0 + r;
    const int nh  = (tid & 1) * (NTILE / 2);
    const float* arow;
    if (GATHER) {
        int tok = (row < M) ? tokall[e * CAP + row] : -1;
        arow = (tok >= 0) ? (Aall + (long long)tok * ldA) : nullptr;
    } else {
        arow = Aall + (long long)e * sAe + (long long)row * ldA;
    }
    for (int c = 0; c < 2 * nper; c++) {
        float acc[32];
        #pragma unroll
        for (int q = 0; q < 32; q++) acc[q] = 0.f;
        int nb = n0 + nh + c * 32;
        for (int k = 0; k < Kdim; k++) {
            float a = arow ? arow[k] : 0.f;
            #pragma unroll 8
            for (int q = 0; q < 32; q++) acc[q] += a * B[(long long)(nb + q) * Kdim + k];
        }
        float* crow = C + (long long)row * ldC;
        for (int q = 0; q < 32; q++) {
            float v = acc[q];
            if (GELU) v = gelu_tanh(v);
            crow[nb + q] = v;
        }
    }
#endif
}

__global__ __launch_bounds__(256) void combine_kernel(
    float* __restrict__ out, const float* __restrict__ y,
    const int* __restrict__ pair_slot, const float* __restrict__ pair_w)
{
    int t = blockIdx.x;
    int slot[KTOP]; float w[KTOP];
    #pragma unroll
    for (int k = 0; k < KTOP; k++) {
        slot[k] = pair_slot[t * KTOP + k];
        w[k]    = pair_w[t * KTOP + k];
    }
    int h4 = threadIdx.x;
    float4 acc = *(float4*)(out + (size_t)t * H + h4 * 4);
    #pragma unroll
    for (int k = 0; k < KTOP; k++) {
        float4 v = *(const float4*)(y + (size_t)slot[k] * H + h4 * 4);
        acc.x += w[k] * v.x; acc.y += w[k] * v.y;
        acc.z += w[k] * v.z; acc.w += w[k] * v.w;
    }
    *(float4*)(out + (size_t)t * H + h4 * 4) = acc;
}

// ---------------- launch ----------------
extern "C" void kernel_launch(void* const* d_in, const int* in_sizes, int n_in,
                              void* d_out, int out_size)
{
    const float* x   = (const float*)d_in[0];
    const float* rw  = (const float*)d_in[1];
    const float* eb  = (const float*)d_in[2];
    const float* w1  = (const float*)d_in[3];
    const float* w2  = (const float*)d_in[4];
    const float* sw1 = (const float*)d_in[5];
    const float* sw2 = (const float*)d_in[6];
    float* out = (float*)d_out;

    void *pcnt, *ptok, *pps, *ppw, *pmid, *py, *psmid, *pw1t, *pw2t, *pxr, *psw1r, *psw2r;
    cudaGetSymbolAddress(&pcnt,  g_cnt);
    cudaGetSymbolAddress(&ptok,  g_slot_token);
    cudaGetSymbolAddress(&pps,   g_pair_slot);
    cudaGetSymbolAddress(&ppw,   g_pair_w);
    cudaGetSymbolAddress(&pmid,  g_mid);
    cudaGetSymbolAddress(&py,    g_y);
    cudaGetSymbolAddress(&psmid, g_smid);
    cudaGetSymbolAddress(&pw1t,  g_w1t);
    cudaGetSymbolAddress(&pw2t,  g_w2t);
    cudaGetSymbolAddress(&pxr,   g_xr);
    cudaGetSymbolAddress(&psw1r, g_sw1r);
    cudaGetSymbolAddress(&psw2r, g_sw2r);

    int*   cnt       = (int*)pcnt;
    int*   slot_tok  = (int*)ptok;
    int*   pair_slot = (int*)pps;
    float* pair_w    = (float*)ppw;
    float* mid       = (float*)pmid;
    float* y         = (float*)py;
    float* smid      = (float*)psmid;
    float* w1t       = (float*)pw1t;
    float* w2t       = (float*)pw2t;
    float* xr        = (float*)pxr;
    float* sw1r      = (float*)psw1r;
    float* sw2r      = (float*)psw2r;

    const int SM256 = 4 * (16384 + 256 * 128) + 1024 + 64;   // 197696
    const int SM128 = 4 * (16384 + 128 * 128) + 1024 + 64;   // 132160
    cudaFuncSetAttribute(gemm_tc<true,  true,  true,  256>, cudaFuncAttributeMaxDynamicSharedMemorySize, SM256);
    cudaFuncSetAttribute(gemm_tc<false, false, false, 256>, cudaFuncAttributeMaxDynamicSharedMemorySize, SM256);
    cudaFuncSetAttribute(gemm_tc<false, true,  true,  256>, cudaFuncAttributeMaxDynamicSharedMemorySize, SM256);
    cudaFuncSetAttribute(gemm_tc<false, false, false, 128>, cudaFuncAttributeMaxDynamicSharedMemorySize, SM128);

    zero_cnt_kernel<<<1, 64>>>(cnt);
    router_kernel<<<T, 256>>>(x, rw, eb, cnt, slot_tok, pair_slot, pair_w);

    // pre-round operands to tf32 bit patterns
    round_copy_kernel<<<(T * H / 4 + 255) / 256, 256>>>(x,   xr,   T * H / 4);
    round_copy_kernel<<<(SF * H / 4 + 255) / 256, 256>>>(sw1, sw1r, SF * H / 4);
    round_copy_kernel<<<(H * SF / 4 + 255) / 256, 256>>>(sw2, sw2r, H * SF / 4);

    // transpose + round expert weights to K-major
    transpose_kernel<<<dim3(F / 32, H / 32, E), 256>>>(w1, w1t, H, F);
    transpose_kernel<<<dim3(H / 32, F / 32, E), 256>>>(w2, w2t, F, H);

    // expert GEMM1: mid[e] = round(gelu(gather(xr) @ w1t[e]))
    gemm_tc<true, true, true, 256><<<dim3(F / 256, CAP / 128, E), 256, SM256>>>(
        xr, 0LL, H, w1t, (long long)H * F,
        mid, (long long)CAP * F, F,
        H, F, cnt, CAP, slot_tok);

    // expert GEMM2: y[e] = mid[e] @ w2t[e]
    gemm_tc<false, false, false, 256><<<dim3(H / 256, CAP / 128, E), 256, SM256>>>(
        mid, (long long)CAP * F, F, w2t, (long long)F * H,
        y, (long long)CAP * H, H,
        F, H, cnt, CAP, slot_tok);

    // shared GEMM1: smid = round(gelu(xr @ sw1r^T))
    gemm_tc<false, true, true, 256><<<dim3(SF / 256, T / 128, 1), 256, SM256>>>(
        xr, 0LL, H, sw1r, 0LL,
        smid, 0LL, SF,
        H, SF, nullptr, T, nullptr);

    // shared GEMM2: out = smid @ sw2r^T  (N=128 tiles -> 128 CTAs)
    gemm_tc<false, false, false, 128><<<dim3(H / 128, T / 128, 1), 256, SM128>>>(
        smid, 0LL, SF, sw2r, 0LL,
        out, 0LL, H,
        SF, H, nullptr, T, nullptr);

    // combine: out += sum_k w_k * y[slot_k]
    combine_kernel<<<T, 256>>>(out, y, pair_slot, pair_w);
}

// round 7
// speedup vs baseline: 2.0328x; 1.3761x over previous
#include <cuda_runtime.h>
#include <math.h>
#include <stdint.h>

#define E    64
#define KTOP 6
#define H    1024
#define F    512
#define SF   2048
#define T    2048
#define CAP  384   // 2 * ceil(T*K/E)

#if !defined(__CUDA_ARCH__) || defined(__CUDA_ARCH_FEAT_SM103_ALL) || \
    defined(__CUDA_ARCH_FEAT_SM100_ALL) || defined(__CUDA_ARCH_FEAT_SM101_ALL) || \
    defined(__CUDA_ARCH_SPECIFIC__)
#define TC_OK 1
#else
#define TC_OK 0
#endif

// ---------------- scratch (static device globals; allocation-free) ----------------
__device__ int   g_cnt[E];
__device__ int   g_slot_token[E * CAP];
__device__ int   g_pair_slot[T * KTOP];
__device__ float g_pair_w[T * KTOP];
__device__ float g_mid[(size_t)E * CAP * F];
__device__ float g_y[(size_t)E * CAP * H];
__device__ float g_smid[(size_t)T * SF];
__device__ float g_w1t[(size_t)E * F * H];   // w1 transposed + tf32-rounded
__device__ float g_w2t[(size_t)E * H * F];   // w2 transposed + tf32-rounded
__device__ float g_xr[(size_t)T * H];        // x  tf32-rounded
__device__ float g_sw1r[(size_t)SF * H];     // sw1 tf32-rounded
__device__ float g_sw2r[(size_t)H * SF];     // sw2 tf32-rounded

// ---------------- generic helpers ----------------
__device__ __forceinline__ float gelu_tanh(float x) {
    float u = 0.7978845608028654f * (x + 0.044715f * x * x * x);
    return 0.5f * x * (1.0f + tanhf(u));
}

__device__ __forceinline__ float f2tf_f(float f) {
    unsigned u;
    asm("cvt.rna.tf32.f32 %0, %1;" : "=r"(u) : "f"(f));
    return __uint_as_float(u);
}

#if TC_OK
// ---------------- PTX helpers (tcgen05 path) ----------------
__device__ __forceinline__ uint32_t smem_u32(const void* p) {
    uint32_t a;
    asm("{ .reg .u64 t; cvta.to.shared.u64 t, %1; cvt.u32.u64 %0, t; }" : "=r"(a) : "l"(p));
    return a;
}
__device__ __forceinline__ uint32_t elect_one() {
    uint32_t pred;
    asm volatile("{\n\t.reg .pred p;\n\telect.sync _|p, 0xFFFFFFFF;\n\tselp.b32 %0, 1, 0, p;\n\t}" : "=r"(pred));
    return pred;
}
__device__ __forceinline__ void cpasync16(uint32_t dst, const void* src, uint32_t sz) {
    asm volatile("cp.async.cg.shared.global [%0], [%1], 16, %2;"
        :: "r"(dst), "l"(src), "r"(sz) : "memory");
}
__device__ __forceinline__ void cp_commit() {
    asm volatile("cp.async.commit_group;" ::: "memory");
}
__device__ __forceinline__ void cp_wait2() {
    asm volatile("cp.async.wait_group 2;" ::: "memory");
}
__device__ __forceinline__ void mbar_init(uint32_t mbar, uint32_t cnt) {
    asm volatile("mbarrier.init.shared.b64 [%0], %1;" :: "r"(mbar), "r"(cnt) : "memory");
}
__device__ __forceinline__ void mbar_wait(uint32_t mbar, uint32_t parity) {
    asm volatile(
        "{\n\t.reg .pred P;\n"
        "W_%=:\n\t"
        "mbarrier.try_wait.parity.acquire.cta.shared::cta.b64 P, [%0], %1, 0x989680;\n\t"
        "@P bra.uni D_%=;\n\t"
        "bra.uni W_%=;\n"
        "D_%=:\n\t}"
        :: "r"(mbar), "r"(parity) : "memory");
}
__device__ __forceinline__ void tc_alloc(uint32_t smem_slot, uint32_t ncols) {
    asm volatile("tcgen05.alloc.cta_group::1.sync.aligned.shared::cta.b32 [%0], %1;"
        :: "r"(smem_slot), "r"(ncols) : "memory");
}
__device__ __forceinline__ void tc_relinquish() {
    asm volatile("tcgen05.relinquish_alloc_permit.cta_group::1.sync.aligned;");
}
__device__ __forceinline__ void tc_dealloc(uint32_t tmem, uint32_t ncols) {
    asm volatile("tcgen05.dealloc.cta_group::1.sync.aligned.b32 %0, %1;" :: "r"(tmem), "r"(ncols));
}
__device__ __forceinline__ void tc_commit(uint32_t mbar) {
    asm volatile("tcgen05.commit.cta_group::1.mbarrier::arrive::one.shared::cluster.b64 [%0];"
        :: "r"(mbar) : "memory");
}
__device__ __forceinline__ void fence_async() {
    asm volatile("fence.proxy.async.shared::cta;" ::: "memory");
}
__device__ __forceinline__ void tc_fence_after() {
    asm volatile("tcgen05.fence::after_thread_sync;" ::: "memory");
}
__device__ __forceinline__ void tc_wait_ld() {
    asm volatile("tcgen05.wait::ld.sync.aligned;" ::: "memory");
}
__device__ __forceinline__ void mma_tf32_ss(uint32_t d, uint64_t ad, uint64_t bd,
                                            uint32_t idesc, uint32_t en) {
    asm volatile(
        "{\n\t.reg .pred p;\n\t"
        "setp.ne.u32 p, %5, 0;\n\t"
        "tcgen05.mma.cta_group::1.kind::tf32 [%0], %1, %2, %3, {%4, %4, %4, %4}, p;\n\t}"
        :: "r"(d), "l"(ad), "l"(bd), "r"(idesc), "r"(0u), "r"(en) : "memory");
}
__device__ __forceinline__ void ldtm32(uint32_t* r, uint32_t addr) {
    asm volatile(
        "tcgen05.ld.sync.aligned.32x32b.x32.b32 "
        "{%0, %1, %2, %3, %4, %5, %6, %7, %8, %9, %10, %11, %12, %13, %14, %15, "
        "%16, %17, %18, %19, %20, %21, %22, %23, %24, %25, %26, %27, %28, %29, %30, %31}, [%32];"
        : "=r"(r[0]), "=r"(r[1]), "=r"(r[2]), "=r"(r[3]), "=r"(r[4]), "=r"(r[5]), "=r"(r[6]), "=r"(r[7]),
          "=r"(r[8]), "=r"(r[9]), "=r"(r[10]), "=r"(r[11]), "=r"(r[12]), "=r"(r[13]), "=r"(r[14]), "=r"(r[15]),
          "=r"(r[16]), "=r"(r[17]), "=r"(r[18]), "=r"(r[19]), "=r"(r[20]), "=r"(r[21]), "=r"(r[22]), "=r"(r[23]),
          "=r"(r[24]), "=r"(r[25]), "=r"(r[26]), "=r"(r[27]), "=r"(r[28]), "=r"(r[29]), "=r"(r[30]), "=r"(r[31])
        : "r"(addr));
}
__device__ __forceinline__ uint32_t sw128(uint32_t byte_off) {
    return byte_off ^ ((byte_off >> 3) & 0x70);
}
// K-major SW128 desc base: layout=2, version=1, SBO=64, LBO=1 (validated)
#define DESCK  0x4000404000010000ull
#endif  // TC_OK

// ---------------- fused prep kernel: zero cnt + round sw1/sw2 ----------------
__global__ __launch_bounds__(256) void prep_kernel(
    const float* __restrict__ sw1, float* __restrict__ sw1r,
    const float* __restrict__ sw2, float* __restrict__ sw2r,
    int* __restrict__ cnt)
{
    if (blockIdx.x == 0 && threadIdx.x < E) cnt[threadIdx.x] = 0;
    int i = blockIdx.x * 256 + threadIdx.x;                 // n4 = SF*H/4 per array
    float4 a = ((const float4*)sw1)[i];
    a.x = f2tf_f(a.x); a.y = f2tf_f(a.y); a.z = f2tf_f(a.z); a.w = f2tf_f(a.w);
    ((float4*)sw1r)[i] = a;
    float4 b = ((const float4*)sw2)[i];
    b.x = f2tf_f(b.x); b.y = f2tf_f(b.y); b.z = f2tf_f(b.z); b.w = f2tf_f(b.w);
    ((float4*)sw2r)[i] = b;
}

// ---------------- router (fused: also writes tf32-rounded x) ----------------
__global__ __launch_bounds__(256) void router_kernel(
    const float* __restrict__ x, const float* __restrict__ rw,
    const float* __restrict__ bias,
    int* __restrict__ cnt, int* __restrict__ slot_token,
    int* __restrict__ pair_slot, float* __restrict__ pair_w,
    float* __restrict__ xr)
{
    int t = blockIdx.x;
    __shared__ float xs[H];
    __shared__ float sc[E];
    __shared__ float sb[E];
    for (int i = threadIdx.x; i < H; i += 256) xs[i] = x[(size_t)t * H + i];
    if (threadIdx.x < E) sb[threadIdx.x] = bias[threadIdx.x];
    __syncthreads();

    // rounded copy of this token's row
    {
        float4 v = ((const float4*)(xs))[threadIdx.x];
        v.x = f2tf_f(v.x); v.y = f2tf_f(v.y); v.z = f2tf_f(v.z); v.w = f2tf_f(v.w);
        ((float4*)(xr + (size_t)t * H))[threadIdx.x] = v;
    }

    int warp = threadIdx.x >> 5, lane = threadIdx.x & 31;
    for (int e = warp; e < E; e += 8) {
        const float* w = rw + (size_t)e * H;
        float s = 0.f;
        for (int i = lane; i < H; i += 32) s += xs[i] * w[i];
        #pragma unroll
        for (int o = 16; o; o >>= 1) s += __shfl_xor_sync(0xffffffffu, s, o);
        if (lane == 0) sc[e] = 1.f / (1.f + expf(-s));
    }
    __syncthreads();

    if (threadIdx.x == 0) {
        unsigned long long used = 0ull;
        int idx[KTOP]; float tsc[KTOP]; float sum = 0.f;
        #pragma unroll
        for (int k = 0; k < KTOP; k++) {
            float best = -1e30f; int bi = 0;
            for (int e = 0; e < E; e++) {
                if (used & (1ull << e)) continue;
                float v = sc[e] + sb[e];
                if (v > best) { best = v; bi = e; }
            }
            used |= 1ull << bi; idx[k] = bi; tsc[k] = sc[bi]; sum += sc[bi];
        }
        float inv = 1.f / (sum + 1e-20f);
        #pragma unroll
        for (int k = 0; k < KTOP; k++) {
            int e = idx[k];
            int pos = atomicAdd(&cnt[e], 1);
            float w = tsc[k] * inv;
            int slot;
            if (pos < CAP) { slot = e * CAP + pos; slot_token[slot] = t; }
            else           { slot = 0; w = 0.f; }
            pair_slot[t * KTOP + k] = slot;
            pair_w[t * KTOP + k]    = w;
        }
    }
}

// ---------------- float4 transpose + tf32 round ----------------
// src [E][R][C] -> dst [E][C][R]; tile 32 rows x 128 cols; grid (C/128, R/32, E)
__global__ __launch_bounds__(256) void transpose4_kernel(
    const float* __restrict__ src, float* __restrict__ dst, int R, int Cc)
{
    __shared__ float tile[32][132];
    int e = blockIdx.z;
    const float* S = src + (size_t)e * R * Cc;
    float*       D = dst + (size_t)e * R * Cc;
    int r0 = blockIdx.y * 32, c0 = blockIdx.x * 128;
    int tx = threadIdx.x & 31, ty = threadIdx.x >> 5;   // tx 0..31, ty 0..7
    #pragma unroll
    for (int i = 0; i < 4; i++) {
        int r = ty + 8 * i;
        float4 v = *(const float4*)(S + (size_t)(r0 + r) * Cc + c0 + tx * 4);
        tile[r][tx * 4 + 0] = f2tf_f(v.x);
        tile[r][tx * 4 + 1] = f2tf_f(v.y);
        tile[r][tx * 4 + 2] = f2tf_f(v.z);
        tile[r][tx * 4 + 3] = f2tf_f(v.w);
    }
    __syncthreads();
    int rx = threadIdx.x & 7, cy = threadIdx.x >> 3;    // rx 0..7, cy 0..31
    #pragma unroll
    for (int i = 0; i < 4; i++) {
        int c = cy + 32 * i;
        float4 o = make_float4(tile[rx * 4 + 0][c], tile[rx * 4 + 1][c],
                               tile[rx * 4 + 2][c], tile[rx * 4 + 3][c]);
        *(float4*)(D + (size_t)(c0 + c) * R + r0 + rx * 4) = o;
    }
}

// ---------------- tcgen05 TF32 GEMM: cp.async 4-buffer pipeline ----------------
template<bool GATHER, bool GELU, bool ROUND, int NTILE>
__global__ __launch_bounds__(256) void gemm_tc(
    const float* __restrict__ Aall, long long sAe, int ldA,
    const float* __restrict__ Ball, long long sBe,
    float* __restrict__ Call, long long sCe, int ldC,
    int Kdim, int Ncols,
    const int* __restrict__ cnts, int Mmax,
    const int* __restrict__ tokall)
{
    const int e  = blockIdx.z;
    const int m0 = blockIdx.y * 128;
    const int n0 = blockIdx.x * NTILE;
    int M = Mmax;
    if (cnts) { M = min(cnts[e], Mmax); if (m0 >= M) return; }

    const float* B = Ball + (long long)e * sBe;
    float*       C = Call + (long long)e * sCe;

#if TC_OK
    constexpr int ABYTES = 16384;
    constexpr int BBYTES = NTILE * 128;
    constexpr int STAGE  = ABYTES + BBYTES;
    constexpr int NB     = NTILE / 32;
    constexpr uint32_t IDESC = (NTILE == 256) ? 0x8400910u : 0x8200910u;

    extern __shared__ char smraw_c[];
    const uint32_t sbase = (smem_u32(smraw_c) + 1023u) & ~1023u;
    const uint32_t ctrl  = sbase + 4 * STAGE;

    const int tid  = threadIdx.x;
    const int warp = tid >> 5;
    const int lane = tid & 31;

    if (warp == 0) { tc_alloc(ctrl, 256); tc_relinquish(); }
    if (tid == 0) {
        #pragma unroll
        for (int j = 0; j < 4; j++) mbar_init(ctrl + 8 + 8 * j, 1);
    }
    __syncthreads();
    uint32_t tmem;
    asm volatile("ld.shared.b32 %0, [%1];" : "=r"(tmem) : "r"(ctrl));

    const float* aptr[4]; uint32_t a_sts[4], a_ok[4];
    #pragma unroll
    for (int j = 0; j < 4; j++) {
        int g = tid + j * 256;
        int m = g >> 3, k4 = (g & 7) * 4;
        a_sts[j] = sw128(m * 128 + k4 * 4);
        if (GATHER) {
            int tok = (m0 + m < M) ? tokall[e * CAP + m0 + m] : -1;
            a_ok[j] = (tok >= 0) ? 16u : 0u;
            aptr[j] = (tok >= 0) ? (Aall + (long long)tok * ldA + k4) : Aall;
        } else {
            a_ok[j] = 16u;
            aptr[j] = Aall + (long long)e * sAe + (long long)(m0 + m) * ldA + k4;
        }
    }
    const float* bptr[NB]; uint32_t b_sts[NB];
    #pragma unroll
    for (int j = 0; j < NB; j++) {
        int g = tid + j * 256;
        int n = g >> 3, k4 = (g & 7) * 4;
        b_sts[j] = sw128(n * 128 + k4 * 4);
        bptr[j]  = B + (long long)(n0 + n) * Kdim + k4;
    }

    const int ntiles = Kdim >> 5;

    auto issue = [&](int it) {
        uint32_t base = sbase + (it & 3) * STAGE;
        long long ka = (long long)it * 32;
        #pragma unroll
        for (int j = 0; j < 4; j++)
            cpasync16(base + a_sts[j], aptr[j] + ka, a_ok[j]);
        #pragma unroll
        for (int j = 0; j < NB; j++)
            cpasync16(base + ABYTES + b_sts[j], bptr[j] + ka, 16u);
    };

    issue(0); cp_commit();
    issue(1); cp_commit();
    issue(2); cp_commit();

    for (int it = 0; it < ntiles; ++it) {
        cp_wait2();
        __syncthreads();

        if (warp == 0 && elect_one()) {
            fence_async();
            uint32_t sa = sbase + (it & 3) * STAGE;
            uint64_t ad = DESCK | ((sa >> 4) & 0x3FFFu);
            uint64_t bd = DESCK | (((sa + ABYTES) >> 4) & 0x3FFFu);
            #pragma unroll
            for (int s = 0; s < 4; s++)
                mma_tf32_ss(tmem, ad + 2 * s, bd + 2 * s, IDESC, (it | s) != 0);
            tc_commit(ctrl + 8 + 8 * (it & 3));
        }

        if (it + 3 < ntiles) {
            if (it >= 1) {
                int p = it - 1;
                mbar_wait(ctrl + 8 + 8 * (p & 3), (p >> 2) & 1);
            }
            issue(it + 3);
        }
        cp_commit();
    }

    {
        int p = ntiles - 1;
        mbar_wait(ctrl + 8 + 8 * (p & 3), (p >> 2) & 1);
    }
    tc_fence_after();

    {
        const int w4 = warp & 3, half = warp >> 2;
        const int row = m0 + w4 * 32 + lane;
        float* crow = C + (long long)row * ldC + n0;
        #pragma unroll
        for (int i = 0; i < NTILE / 64; i++) {
            int c0 = half * (NTILE / 2) + i * 32;
            uint32_t r[32];
            ldtm32(r, tmem + c0);
            tc_wait_ld();
            float fv[32];
            #pragma unroll
            for (int q = 0; q < 32; q++) {
                float v = __uint_as_float(r[q]);
                if (GELU)  v = gelu_tanh(v);
                if (ROUND) v = f2tf_f(v);
                fv[q] = v;
            }
            #pragma unroll
            for (int q = 0; q < 8; q++) {
                float4 o = make_float4(fv[q*4], fv[q*4+1], fv[q*4+2], fv[q*4+3]);
                *(float4*)(crow + c0 + q * 4) = o;
            }
        }
    }
    __syncthreads();
    if (warp == 0) tc_dealloc(tmem, 256);

#else  // generic-target SIMT fallback (correct; never runs on device)
    const int tid = threadIdx.x;
    const int nper = NTILE / 128;
    const int r   = tid >> 1;
    const int row = m0 + r;
    const int nh  = (tid & 1) * (NTILE / 2);
    const float* arow;
    if (GATHER) {
        int tok = (row < M) ? tokall[e * CAP + row] : -1;
        arow = (tok >= 0) ? (Aall + (long long)tok * ldA) : nullptr;
    } else {
        arow = Aall + (long long)e * sAe + (long long)row * ldA;
    }
    for (int c = 0; c < 2 * nper; c++) {
        float acc[32];
        #pragma unroll
        for (int q = 0; q < 32; q++) acc[q] = 0.f;
        int nb = n0 + nh + c * 32;
        for (int k = 0; k < Kdim; k++) {
            float a = arow ? arow[k] : 0.f;
            #pragma unroll 8
            for (int q = 0; q < 32; q++) acc[q] += a * B[(long long)(nb + q) * Kdim + k];
        }
        float* crow = C + (long long)row * ldC;
        for (int q = 0; q < 32; q++) {
            float v = acc[q];
            if (GELU) v = gelu_tanh(v);
            crow[nb + q] = v;
        }
    }
#endif
}

__global__ __launch_bounds__(256) void combine_kernel(
    float* __restrict__ out, const float* __restrict__ y,
    const int* __restrict__ pair_slot, const float* __restrict__ pair_w)
{
    int t = blockIdx.x;
    int slot[KTOP]; float w[KTOP];
    #pragma unroll
    for (int k = 0; k < KTOP; k++) {
        slot[k] = pair_slot[t * KTOP + k];
        w[k]    = pair_w[t * KTOP + k];
    }
    int h4 = threadIdx.x;
    float4 acc = *(float4*)(out + (size_t)t * H + h4 * 4);
    #pragma unroll
    for (int k = 0; k < KTOP; k++) {
        float4 v = *(const float4*)(y + (size_t)slot[k] * H + h4 * 4);
        acc.x += w[k] * v.x; acc.y += w[k] * v.y;
        acc.z += w[k] * v.z; acc.w += w[k] * v.w;
    }
    *(float4*)(out + (size_t)t * H + h4 * 4) = acc;
}

// ---------------- launch ----------------
extern "C" void kernel_launch(void* const* d_in, const int* in_sizes, int n_in,
                              void* d_out, int out_size)
{
    const float* x   = (const float*)d_in[0];
    const float* rw  = (const float*)d_in[1];
    const float* eb  = (const float*)d_in[2];
    const float* w1  = (const float*)d_in[3];
    const float* w2  = (const float*)d_in[4];
    const float* sw1 = (const float*)d_in[5];
    const float* sw2 = (const float*)d_in[6];
    float* out = (float*)d_out;

    void *pcnt, *ptok, *pps, *ppw, *pmid, *py, *psmid, *pw1t, *pw2t, *pxr, *psw1r, *psw2r;
    cudaGetSymbolAddress(&pcnt,  g_cnt);
    cudaGetSymbolAddress(&ptok,  g_slot_token);
    cudaGetSymbolAddress(&pps,   g_pair_slot);
    cudaGetSymbolAddress(&ppw,   g_pair_w);
    cudaGetSymbolAddress(&pmid,  g_mid);
    cudaGetSymbolAddress(&py,    g_y);
    cudaGetSymbolAddress(&psmid, g_smid);
    cudaGetSymbolAddress(&pw1t,  g_w1t);
    cudaGetSymbolAddress(&pw2t,  g_w2t);
    cudaGetSymbolAddress(&pxr,   g_xr);
    cudaGetSymbolAddress(&psw1r, g_sw1r);
    cudaGetSymbolAddress(&psw2r, g_sw2r);

    int*   cnt       = (int*)pcnt;
    int*   slot_tok  = (int*)ptok;
    int*   pair_slot = (int*)pps;
    float* pair_w    = (float*)ppw;
    float* mid       = (float*)pmid;
    float* y         = (float*)py;
    float* smid      = (float*)psmid;
    float* w1t       = (float*)pw1t;
    float* w2t       = (float*)pw2t;
    float* xr        = (float*)pxr;
    float* sw1r      = (float*)psw1r;
    float* sw2r      = (float*)psw2r;

    const int SM256 = 4 * (16384 + 256 * 128) + 1024 + 64;
    const int SM128 = 4 * (16384 + 128 * 128) + 1024 + 64;
    cudaFuncSetAttribute(gemm_tc<true,  true,  true,  256>, cudaFuncAttributeMaxDynamicSharedMemorySize, SM256);
    cudaFuncSetAttribute(gemm_tc<false, false, false, 256>, cudaFuncAttributeMaxDynamicSharedMemorySize, SM256);
    cudaFuncSetAttribute(gemm_tc<false, true,  true,  256>, cudaFuncAttributeMaxDynamicSharedMemorySize, SM256);
    cudaFuncSetAttribute(gemm_tc<false, false, false, 128>, cudaFuncAttributeMaxDynamicSharedMemorySize, SM128);

    // (0) prep: zero cnt + round sw1/sw2
    prep_kernel<<<SF * H / 4 / 256, 256>>>(sw1, sw1r, sw2, sw2r, cnt);
    // (1) router (+ rounded x)
    router_kernel<<<T, 256>>>(x, rw, eb, cnt, slot_tok, pair_slot, pair_w, xr);
    // (2) transpose w1 -> w1t  [E][F][H]
    transpose4_kernel<<<dim3(F / 128, H / 32, E), 256>>>(w1, w1t, H, F);
    // (3) expert GEMM1  <-- ncu captures this launch
    gemm_tc<true, true, true, 256><<<dim3(F / 256, CAP / 128, E), 256, SM256>>>(
        xr, 0LL, H, w1t, (long long)H * F,
        mid, (long long)CAP * F, F,
        H, F, cnt, CAP, slot_tok);
    // (4) transpose w2 -> w2t  [E][H][F]
    transpose4_kernel<<<dim3(H / 128, F / 32, E), 256>>>(w2, w2t, F, H);
    // (5) expert GEMM2
    gemm_tc<false, false, false, 256><<<dim3(H / 256, CAP / 128, E), 256, SM256>>>(
        mid, (long long)CAP * F, F, w2t, (long long)F * H,
        y, (long long)CAP * H, H,
        F, H, cnt, CAP, slot_tok);
    // (6) shared GEMM1
    gemm_tc<false, true, true, 256><<<dim3(SF / 256, T / 128, 1), 256, SM256>>>(
        xr, 0LL, H, sw1r, 0LL,
        smid, 0LL, SF,
        H, SF, nullptr, T, nullptr);
    // (7) shared GEMM2
    gemm_tc<false, false, false, 128><<<dim3(H / 128, T / 128, 1), 256, SM128>>>(
        smid, 0LL, SF, sw2r, 0LL,
        out, 0LL, H,
        SF, H, nullptr, T, nullptr);
    // (8) combine
    combine_kernel<<<T, 256>>>(out, y, pair_slot, pair_w);
}

// round 8
// speedup vs baseline: 2.0443x; 1.0056x over previous
#include <cuda_runtime.h>
#include <math.h>
#include <stdint.h>

#define E    64
#define KTOP 6
#define H    1024
#define F    512
#define SF   2048
#define T    2048
#define CAP  384   // 2 * ceil(T*K/E)

#if !defined(__CUDA_ARCH__) || defined(__CUDA_ARCH_FEAT_SM103_ALL) || \
    defined(__CUDA_ARCH_FEAT_SM100_ALL) || defined(__CUDA_ARCH_FEAT_SM101_ALL) || \
    defined(__CUDA_ARCH_SPECIFIC__)
#define TC_OK 1
#else
#define TC_OK 0
#endif

// ---------------- scratch (static device globals; allocation-free) ----------------
__device__ int   g_cnt[E];
__device__ int   g_slot_token[E * CAP];
__device__ int   g_pair_slot[T * KTOP];
__device__ float g_pair_w[T * KTOP];
__device__ float g_mid[(size_t)E * CAP * F];
__device__ float g_y[(size_t)E * CAP * H];
__device__ float g_smid[(size_t)T * SF];
__device__ float g_w1t[(size_t)E * F * H];   // w1 transposed + tf32-rounded
__device__ float g_w2t[(size_t)E * H * F];   // w2 transposed + tf32-rounded
__device__ float g_xr[(size_t)T * H];        // x  tf32-rounded
__device__ float g_sw1r[(size_t)SF * H];     // sw1 tf32-rounded
__device__ float g_sw2r[(size_t)H * SF];     // sw2 tf32-rounded

// ---------------- generic helpers ----------------
__device__ __forceinline__ float gelu_tanh(float x) {
    float u = 0.7978845608028654f * (x + 0.044715f * x * x * x);
    return 0.5f * x * (1.0f + tanhf(u));
}

__device__ __forceinline__ float f2tf_f(float f) {
    unsigned u;
    asm("cvt.rna.tf32.f32 %0, %1;" : "=r"(u) : "f"(f));
    return __uint_as_float(u);
}

#if TC_OK
// ---------------- PTX helpers (tcgen05 path) ----------------
__device__ __forceinline__ uint32_t smem_u32(const void* p) {
    uint32_t a;
    asm("{ .reg .u64 t; cvta.to.shared.u64 t, %1; cvt.u32.u64 %0, t; }" : "=r"(a) : "l"(p));
    return a;
}
__device__ __forceinline__ uint32_t elect_one() {
    uint32_t pred;
    asm volatile("{\n\t.reg .pred p;\n\telect.sync _|p, 0xFFFFFFFF;\n\tselp.b32 %0, 1, 0, p;\n\t}" : "=r"(pred));
    return pred;
}
__device__ __forceinline__ void cpasync16(uint32_t dst, const void* src, uint32_t sz) {
    asm volatile("cp.async.cg.shared.global [%0], [%1], 16, %2;"
        :: "r"(dst), "l"(src), "r"(sz) : "memory");
}
__device__ __forceinline__ void cp_commit() {
    asm volatile("cp.async.commit_group;" ::: "memory");
}
__device__ __forceinline__ void cp_wait2() {
    asm volatile("cp.async.wait_group 2;" ::: "memory");
}
__device__ __forceinline__ void mbar_init(uint32_t mbar, uint32_t cnt) {
    asm volatile("mbarrier.init.shared.b64 [%0], %1;" :: "r"(mbar), "r"(cnt) : "memory");
}
__device__ __forceinline__ void mbar_wait(uint32_t mbar, uint32_t parity) {
    asm volatile(
        "{\n\t.reg .pred P;\n"
        "W_%=:\n\t"
        "mbarrier.try_wait.parity.acquire.cta.shared::cta.b64 P, [%0], %1, 0x989680;\n\t"
        "@P bra.uni D_%=;\n\t"
        "bra.uni W_%=;\n"
        "D_%=:\n\t}"
        :: "r"(mbar), "r"(parity) : "memory");
}
__device__ __forceinline__ void tc_alloc(uint32_t smem_slot, uint32_t ncols) {
    asm volatile("tcgen05.alloc.cta_group::1.sync.aligned.shared::cta.b32 [%0], %1;"
        :: "r"(smem_slot), "r"(ncols) : "memory");
}
__device__ __forceinline__ void tc_relinquish() {
    asm volatile("tcgen05.relinquish_alloc_permit.cta_group::1.sync.aligned;");
}
__device__ __forceinline__ void tc_dealloc(uint32_t tmem, uint32_t ncols) {
    asm volatile("tcgen05.dealloc.cta_group::1.sync.aligned.b32 %0, %1;" :: "r"(tmem), "r"(ncols));
}
__device__ __forceinline__ void tc_commit(uint32_t mbar) {
    asm volatile("tcgen05.commit.cta_group::1.mbarrier::arrive::one.shared::cluster.b64 [%0];"
        :: "r"(mbar) : "memory");
}
__device__ __forceinline__ void fence_async() {
    asm volatile("fence.proxy.async.shared::cta;" ::: "memory");
}
__device__ __forceinline__ void tc_fence_after() {
    asm volatile("tcgen05.fence::after_thread_sync;" ::: "memory");
}
__device__ __forceinline__ void tc_wait_ld() {
    asm volatile("tcgen05.wait::ld.sync.aligned;" ::: "memory");
}
__device__ __forceinline__ void mma_tf32_ss(uint32_t d, uint64_t ad, uint64_t bd,
                                            uint32_t idesc, uint32_t en) {
    asm volatile(
        "{\n\t.reg .pred p;\n\t"
        "setp.ne.u32 p, %5, 0;\n\t"
        "tcgen05.mma.cta_group::1.kind::tf32 [%0], %1, %2, %3, {%4, %4, %4, %4}, p;\n\t}"
        :: "r"(d), "l"(ad), "l"(bd), "r"(idesc), "r"(0u), "r"(en) : "memory");
}
__device__ __forceinline__ void ldtm32(uint32_t* r, uint32_t addr) {
    asm volatile(
        "tcgen05.ld.sync.aligned.32x32b.x32.b32 "
        "{%0, %1, %2, %3, %4, %5, %6, %7, %8, %9, %10, %11, %12, %13, %14, %15, "
        "%16, %17, %18, %19, %20, %21, %22, %23, %24, %25, %26, %27, %28, %29, %30, %31}, [%32];"
        : "=r"(r[0]), "=r"(r[1]), "=r"(r[2]), "=r"(r[3]), "=r"(r[4]), "=r"(r[5]), "=r"(r[6]), "=r"(r[7]),
          "=r"(r[8]), "=r"(r[9]), "=r"(r[10]), "=r"(r[11]), "=r"(r[12]), "=r"(r[13]), "=r"(r[14]), "=r"(r[15]),
          "=r"(r[16]), "=r"(r[17]), "=r"(r[18]), "=r"(r[19]), "=r"(r[20]), "=r"(r[21]), "=r"(r[22]), "=r"(r[23]),
          "=r"(r[24]), "=r"(r[25]), "=r"(r[26]), "=r"(r[27]), "=r"(r[28]), "=r"(r[29]), "=r"(r[30]), "=r"(r[31])
        : "r"(addr));
}
__device__ __forceinline__ uint32_t sw128(uint32_t byte_off) {
    return byte_off ^ ((byte_off >> 3) & 0x70);
}
// K-major SW128 desc base: layout=2, version=1, SBO=64, LBO=1 (validated)
#define DESCK  0x4000404000010000ull
#endif  // TC_OK

// ---------------- fused prep kernel: zero cnt + round sw1/sw2 ----------------
__global__ __launch_bounds__(256) void prep_kernel(
    const float* __restrict__ sw1, float* __restrict__ sw1r,
    const float* __restrict__ sw2, float* __restrict__ sw2r,
    int* __restrict__ cnt)
{
    if (blockIdx.x == 0 && threadIdx.x < E) cnt[threadIdx.x] = 0;
    int i = blockIdx.x * 256 + threadIdx.x;                 // n4 = SF*H/4 per array
    float4 a = ((const float4*)sw1)[i];
    a.x = f2tf_f(a.x); a.y = f2tf_f(a.y); a.z = f2tf_f(a.z); a.w = f2tf_f(a.w);
    ((float4*)sw1r)[i] = a;
    float4 b = ((const float4*)sw2)[i];
    b.x = f2tf_f(b.x); b.y = f2tf_f(b.y); b.z = f2tf_f(b.z); b.w = f2tf_f(b.w);
    ((float4*)sw2r)[i] = b;
}

// ---------------- router (fused: also writes tf32-rounded x) ----------------
__global__ __launch_bounds__(256) void router_kernel(
    const float* __restrict__ x, const float* __restrict__ rw,
    const float* __restrict__ bias,
    int* __restrict__ cnt, int* __restrict__ slot_token,
    int* __restrict__ pair_slot, float* __restrict__ pair_w,
    float* __restrict__ xr)
{
    int t = blockIdx.x;
    __shared__ float xs[H];
    __shared__ float sc[E];
    __shared__ float sb[E];
    for (int i = threadIdx.x; i < H; i += 256) xs[i] = x[(size_t)t * H + i];
    if (threadIdx.x < E) sb[threadIdx.x] = bias[threadIdx.x];
    __syncthreads();

    // rounded copy of this token's row
    {
        float4 v = ((const float4*)(xs))[threadIdx.x];
        v.x = f2tf_f(v.x); v.y = f2tf_f(v.y); v.z = f2tf_f(v.z); v.w = f2tf_f(v.w);
        ((float4*)(xr + (size_t)t * H))[threadIdx.x] = v;
    }

    int warp = threadIdx.x >> 5, lane = threadIdx.x & 31;
    for (int e = warp; e < E; e += 8) {
        const float* w = rw + (size_t)e * H;
        float s = 0.f;
        for (int i = lane; i < H; i += 32) s += xs[i] * w[i];
        #pragma unroll
        for (int o = 16; o; o >>= 1) s += __shfl_xor_sync(0xffffffffu, s, o);
        if (lane == 0) sc[e] = 1.f / (1.f + expf(-s));
    }
    __syncthreads();

    if (threadIdx.x == 0) {
        unsigned long long used = 0ull;
        int idx[KTOP]; float tsc[KTOP]; float sum = 0.f;
        #pragma unroll
        for (int k = 0; k < KTOP; k++) {
            float best = -1e30f; int bi = 0;
            for (int e = 0; e < E; e++) {
                if (used & (1ull << e)) continue;
                float v = sc[e] + sb[e];
                if (v > best) { best = v; bi = e; }
            }
            used |= 1ull << bi; idx[k] = bi; tsc[k] = sc[bi]; sum += sc[bi];
        }
        float inv = 1.f / (sum + 1e-20f);
        #pragma unroll
        for (int k = 0; k < KTOP; k++) {
            int e = idx[k];
            int pos = atomicAdd(&cnt[e], 1);
            float w = tsc[k] * inv;
            int slot;
            if (pos < CAP) { slot = e * CAP + pos; slot_token[slot] = t; }
            else           { slot = 0; w = 0.f; }
            pair_slot[t * KTOP + k] = slot;
            pair_w[t * KTOP + k]    = w;
        }
    }
}

// ---------------- float4 transpose + tf32 round ----------------
// src [E][R][C] -> dst [E][C][R]; tile 32 rows x 128 cols; grid (C/128, R/32, E)
__global__ __launch_bounds__(256) void transpose4_kernel(
    const float* __restrict__ src, float* __restrict__ dst, int R, int Cc)
{
    __shared__ float tile[32][132];
    int e = blockIdx.z;
    const float* S = src + (size_t)e * R * Cc;
    float*       D = dst + (size_t)e * R * Cc;
    int r0 = blockIdx.y * 32, c0 = blockIdx.x * 128;
    int tx = threadIdx.x & 31, ty = threadIdx.x >> 5;   // tx 0..31, ty 0..7
    #pragma unroll
    for (int i = 0; i < 4; i++) {
        int r = ty + 8 * i;
        float4 v = *(const float4*)(S + (size_t)(r0 + r) * Cc + c0 + tx * 4);
        tile[r][tx * 4 + 0] = f2tf_f(v.x);
        tile[r][tx * 4 + 1] = f2tf_f(v.y);
        tile[r][tx * 4 + 2] = f2tf_f(v.z);
        tile[r][tx * 4 + 3] = f2tf_f(v.w);
    }
    __syncthreads();
    int rx = threadIdx.x & 7, cy = threadIdx.x >> 3;    // rx 0..7, cy 0..31
    #pragma unroll
    for (int i = 0; i < 4; i++) {
        int c = cy + 32 * i;
        float4 o = make_float4(tile[rx * 4 + 0][c], tile[rx * 4 + 1][c],
                               tile[rx * 4 + 2][c], tile[rx * 4 + 3][c]);
        *(float4*)(D + (size_t)(c0 + c) * R + r0 + rx * 4) = o;
    }
}

// ---------------- tcgen05 TF32 GEMM: cp.async 4-buffer pipeline ----------------
template<bool GATHER, bool GELU, bool ROUND, int NTILE>
__global__ __launch_bounds__(256) void gemm_tc(
    const float* __restrict__ Aall, long long sAe, int ldA,
    const float* __restrict__ Ball, long long sBe,
    float* __restrict__ Call, long long sCe, int ldC,
    int Kdim, int Ncols,
    const int* __restrict__ cnts, int Mmax,
    const int* __restrict__ tokall)
{
    const int e  = blockIdx.z;
    const int m0 = blockIdx.y * 128;
    const int n0 = blockIdx.x * NTILE;
    int M = Mmax;
    if (cnts) { M = min(cnts[e], Mmax); if (m0 >= M) return; }

    const float* B = Ball + (long long)e * sBe;
    float*       C = Call + (long long)e * sCe;

#if TC_OK
    constexpr int ABYTES = 16384;
    constexpr int BBYTES = NTILE * 128;
    constexpr int STAGE  = ABYTES + BBYTES;
    constexpr int NB     = NTILE / 32;
    constexpr uint32_t IDESC = (NTILE == 256) ? 0x8400910u : 0x8200910u;

    extern __shared__ char smraw_c[];
    const uint32_t sbase = (smem_u32(smraw_c) + 1023u) & ~1023u;
    const uint32_t ctrl  = sbase + 4 * STAGE;

    const int tid  = threadIdx.x;
    const int warp = tid >> 5;
    const int lane = tid & 31;

    if (warp == 0) { tc_alloc(ctrl, 256); tc_relinquish(); }
    if (tid == 0) {
        #pragma unroll
        for (int j = 0; j < 4; j++) mbar_init(ctrl + 8 + 8 * j, 1);
    }
    __syncthreads();
    uint32_t tmem;
    asm volatile("ld.shared.b32 %0, [%1];" : "=r"(tmem) : "r"(ctrl));

    const float* aptr[4]; uint32_t a_sts[4], a_ok[4];
    #pragma unroll
    for (int j = 0; j < 4; j++) {
        int g = tid + j * 256;
        int m = g >> 3, k4 = (g & 7) * 4;
        a_sts[j] = sw128(m * 128 + k4 * 4);
        if (GATHER) {
            int tok = (m0 + m < M) ? tokall[e * CAP + m0 + m] : -1;
            a_ok[j] = (tok >= 0) ? 16u : 0u;
            aptr[j] = (tok >= 0) ? (Aall + (long long)tok * ldA + k4) : Aall;
        } else {
            a_ok[j] = 16u;
            aptr[j] = Aall + (long long)e * sAe + (long long)(m0 + m) * ldA + k4;
        }
    }
    const float* bptr[NB]; uint32_t b_sts[NB];
    #pragma unroll
    for (int j = 0; j < NB; j++) {
        int g = tid + j * 256;
        int n = g >> 3, k4 = (g & 7) * 4;
        b_sts[j] = sw128(n * 128 + k4 * 4);
        bptr[j]  = B + (long long)(n0 + n) * Kdim + k4;
    }

    const int ntiles = Kdim >> 5;

    auto issue = [&](int it) {
        uint32_t base = sbase + (it & 3) * STAGE;
        long long ka = (long long)it * 32;
        #pragma unroll
        for (int j = 0; j < 4; j++)
            cpasync16(base + a_sts[j], aptr[j] + ka, a_ok[j]);
        #pragma unroll
        for (int j = 0; j < NB; j++)
            cpasync16(base + ABYTES + b_sts[j], bptr[j] + ka, 16u);
    };

    issue(0); cp_commit();
    issue(1); cp_commit();
    issue(2); cp_commit();

    for (int it = 0; it < ntiles; ++it) {
        cp_wait2();
        __syncthreads();

        if (warp == 0 && elect_one()) {
            fence_async();
            uint32_t sa = sbase + (it & 3) * STAGE;
            uint64_t ad = DESCK | ((sa >> 4) & 0x3FFFu);
            uint64_t bd = DESCK | (((sa + ABYTES) >> 4) & 0x3FFFu);
            #pragma unroll
            for (int s = 0; s < 4; s++)
                mma_tf32_ss(tmem, ad + 2 * s, bd + 2 * s, IDESC, (it | s) != 0);
            tc_commit(ctrl + 8 + 8 * (it & 3));
        }

        if (it + 3 < ntiles) {
            if (it >= 1) {
                int p = it - 1;
                mbar_wait(ctrl + 8 + 8 * (p & 3), (p >> 2) & 1);
            }
            issue(it + 3);
        }
        cp_commit();
    }

    {
        int p = ntiles - 1;
        mbar_wait(ctrl + 8 + 8 * (p & 3), (p >> 2) & 1);
    }
    tc_fence_after();

    {
        const int w4 = warp & 3, half = warp >> 2;
        const int row = m0 + w4 * 32 + lane;
        float* crow = C + (long long)row * ldC + n0;
        #pragma unroll
        for (int i = 0; i < NTILE / 64; i++) {
            int c0 = half * (NTILE / 2) + i * 32;
            uint32_t r[32];
            ldtm32(r, tmem + c0);
            tc_wait_ld();
            float fv[32];
            #pragma unroll
            for (int q = 0; q < 32; q++) {
                float v = __uint_as_float(r[q]);
                if (GELU)  v = gelu_tanh(v);
                if (ROUND) v = f2tf_f(v);
                fv[q] = v;
            }
            #pragma unroll
            for (int q = 0; q < 8; q++) {
                float4 o = make_float4(fv[q*4], fv[q*4+1], fv[q*4+2], fv[q*4+3]);
                *(float4*)(crow + c0 + q * 4) = o;
            }
        }
    }
    __syncthreads();
    if (warp == 0) tc_dealloc(tmem, 256);

#else  // generic-target SIMT fallback (correct; never runs on device)
    const int tid = threadIdx.x;
    const int nper = NTILE / 128;
    const int r   = tid >> 1;
    const int row = m0 + r;
    const int nh  = (tid & 1) * (NTILE / 2);
    const float* arow;
    if (GATHER) {
        int tok = (row < M) ? tokall[e * CAP + row] : -1;
        arow = (tok >= 0) ? (Aall + (long long)tok * ldA) : nullptr;
    } else {
        arow = Aall + (long long)e * sAe + (long long)row * ldA;
    }
    for (int c = 0; c < 2 * nper; c++) {
        float acc[32];
        #pragma unroll
        for (int q = 0; q < 32; q++) acc[q] = 0.f;
        int nb = n0 + nh + c * 32;
        for (int k = 0; k < Kdim; k++) {
            float a = arow ? arow[k] : 0.f;
            #pragma unroll 8
            for (int q = 0; q < 32; q++) acc[q] += a * B[(long long)(nb + q) * Kdim + k];
        }
        float* crow = C + (long long)row * ldC;
        for (int q = 0; q < 32; q++) {
            float v = acc[q];
            if (GELU) v = gelu_tanh(v);
            crow[nb + q] = v;
        }
    }
#endif
}

__global__ __launch_bounds__(256) void combine_kernel(
    float* __restrict__ out, const float* __restrict__ y,
    const int* __restrict__ pair_slot, const float* __restrict__ pair_w)
{
    int t = blockIdx.x;
    int slot[KTOP]; float w[KTOP];
    #pragma unroll
    for (int k = 0; k < KTOP; k++) {
        slot[k] = pair_slot[t * KTOP + k];
        w[k]    = pair_w[t * KTOP + k];
    }
    int h4 = threadIdx.x;
    float4 acc = *(float4*)(out + (size_t)t * H + h4 * 4);
    #pragma unroll
    for (int k = 0; k < KTOP; k++) {
        float4 v = *(const float4*)(y + (size_t)slot[k] * H + h4 * 4);
        acc.x += w[k] * v.x; acc.y += w[k] * v.y;
        acc.z += w[k] * v.z; acc.w += w[k] * v.w;
    }
    *(float4*)(out + (size_t)t * H + h4 * 4) = acc;
}

// ---------------- launch ----------------
extern "C" void kernel_launch(void* const* d_in, const int* in_sizes, int n_in,
                              void* d_out, int out_size)
{
    const float* x   = (const float*)d_in[0];
    const float* rw  = (const float*)d_in[1];
    const float* eb  = (const float*)d_in[2];
    const float* w1  = (const float*)d_in[3];
    const float* w2  = (const float*)d_in[4];
    const float* sw1 = (const float*)d_in[5];
    const float* sw2 = (const float*)d_in[6];
    float* out = (float*)d_out;

    void *pcnt, *ptok, *pps, *ppw, *pmid, *py, *psmid, *pw1t, *pw2t, *pxr, *psw1r, *psw2r;
    cudaGetSymbolAddress(&pcnt,  g_cnt);
    cudaGetSymbolAddress(&ptok,  g_slot_token);
    cudaGetSymbolAddress(&pps,   g_pair_slot);
    cudaGetSymbolAddress(&ppw,   g_pair_w);
    cudaGetSymbolAddress(&pmid,  g_mid);
    cudaGetSymbolAddress(&py,    g_y);
    cudaGetSymbolAddress(&psmid, g_smid);
    cudaGetSymbolAddress(&pw1t,  g_w1t);
    cudaGetSymbolAddress(&pw2t,  g_w2t);
    cudaGetSymbolAddress(&pxr,   g_xr);
    cudaGetSymbolAddress(&psw1r, g_sw1r);
    cudaGetSymbolAddress(&psw2r, g_sw2r);

    int*   cnt       = (int*)pcnt;
    int*   slot_tok  = (int*)ptok;
    int*   pair_slot = (int*)pps;
    float* pair_w    = (float*)ppw;
    float* mid       = (float*)pmid;
    float* y         = (float*)py;
    float* smid      = (float*)psmid;
    float* w1t       = (float*)pw1t;
    float* w2t       = (float*)pw2t;
    float* xr        = (float*)pxr;
    float* sw1r      = (float*)psw1r;
    float* sw2r      = (float*)psw2r;

    const int SM256 = 4 * (16384 + 256 * 128) + 1024 + 64;
    const int SM128 = 4 * (16384 + 128 * 128) + 1024 + 64;
    cudaFuncSetAttribute(gemm_tc<true,  true,  true,  256>, cudaFuncAttributeMaxDynamicSharedMemorySize, SM256);
    cudaFuncSetAttribute(gemm_tc<false, false, false, 256>, cudaFuncAttributeMaxDynamicSharedMemorySize, SM256);
    cudaFuncSetAttribute(gemm_tc<false, true,  true,  256>, cudaFuncAttributeMaxDynamicSharedMemorySize, SM256);
    cudaFuncSetAttribute(gemm_tc<false, false, false, 128>, cudaFuncAttributeMaxDynamicSharedMemorySize, SM128);

    // (0) prep: zero cnt + round sw1/sw2
    prep_kernel<<<SF * H / 4 / 256, 256>>>(sw1, sw1r, sw2, sw2r, cnt);
    // (1) router (+ rounded x)
    router_kernel<<<T, 256>>>(x, rw, eb, cnt, slot_tok, pair_slot, pair_w, xr);
    // (2) transpose w1 -> w1t  [E][F][H]
    transpose4_kernel<<<dim3(F / 128, H / 32, E), 256>>>(w1, w1t, H, F);
    // (3) expert GEMM1  <-- ncu captures this launch
    gemm_tc<true, true, true, 256><<<dim3(F / 256, CAP / 128, E), 256, SM256>>>(
        xr, 0LL, H, w1t, (long long)H * F,
        mid, (long long)CAP * F, F,
        H, F, cnt, CAP, slot_tok);
    // (4) transpose w2 -> w2t  [E][H][F]
    transpose4_kernel<<<dim3(H / 128, F / 32, E), 256>>>(w2, w2t, F, H);
    // (5) expert GEMM2
    gemm_tc<false, false, false, 256><<<dim3(H / 256, CAP / 128, E), 256, SM256>>>(
        mid, (long long)CAP * F, F, w2t, (long long)F * H,
        y, (long long)CAP * H, H,
        F, H, cnt, CAP, slot_tok);
    // (6) shared GEMM1
    gemm_tc<false, true, true, 256><<<dim3(SF / 256, T / 128, 1), 256, SM256>>>(
        xr, 0LL, H, sw1r, 0LL,
        smid, 0LL, SF,
        H, SF, nullptr, T, nullptr);
    // (7) shared GEMM2
    gemm_tc<false, false, false, 128><<<dim3(H / 128, T / 128, 1), 256, SM128>>>(
        smid, 0LL, SF, sw2r, 0LL,
        out, 0LL, H,
        SF, H, nullptr, T, nullptr);
    // (8) combine
    combine_kernel<<<T, 256>>>(out, y, pair_slot, pair_w);
}

// round 9
// speedup vs baseline: 2.4782x; 1.2123x over previous
#include <cuda_runtime.h>
#include <math.h>
#include <stdint.h>

#define E    64
#define KTOP 6
#define H    1024
#define F    512
#define SF   2048
#define T    2048
#define CAP  384

#if !defined(__CUDA_ARCH__) || defined(__CUDA_ARCH_FEAT_SM103_ALL) || \
    defined(__CUDA_ARCH_FEAT_SM100_ALL) || defined(__CUDA_ARCH_FEAT_SM101_ALL) || \
    defined(__CUDA_ARCH_SPECIFIC__)
#define TC_OK 1
#else
#define TC_OK 0
#endif

__device__ int   g_cnt[E];
__device__ int   g_slot_token[E * CAP];
__device__ int   g_pair_slot[T * KTOP];
__device__ float g_pair_w[T * KTOP];
__device__ float g_mid[(size_t)E * CAP * F];
__device__ float g_y[(size_t)E * CAP * H];
__device__ float g_smid[(size_t)T * SF];
__device__ float g_w1t[(size_t)E * F * H];
__device__ float g_w2t[(size_t)E * H * F];
__device__ float g_xr[(size_t)T * H];
__device__ float g_sw1r[(size_t)SF * H];
__device__ float g_sw2r[(size_t)H * SF];

__device__ __forceinline__ float gelu_tanh(float x) {
    float u = 0.7978845608028654f * (x + 0.044715f * x * x * x);
    return 0.5f * x * (1.0f + tanhf(u));
}
__device__ __forceinline__ float f2tf_f(float f) {
    unsigned u;
    asm("cvt.rna.tf32.f32 %0, %1;" : "=r"(u) : "f"(f));
    return __uint_as_float(u);
}

#if TC_OK
__device__ __forceinline__ uint32_t smem_u32(const void* p) {
    uint32_t a;
    asm("{ .reg .u64 t; cvta.to.shared.u64 t, %1; cvt.u32.u64 %0, t; }" : "=r"(a) : "l"(p));
    return a;
}
__device__ __forceinline__ uint32_t elect_one() {
    uint32_t pred;
    asm volatile("{\n\t.reg .pred p;\n\telect.sync _|p, 0xFFFFFFFF;\n\tselp.b32 %0, 1, 0, p;\n\t}" : "=r"(pred));
    return pred;
}
__device__ __forceinline__ void cpasync16(uint32_t dst, const void* src, uint32_t sz) {
    asm volatile("cp.async.cg.shared.global [%0], [%1], 16, %2;" :: "r"(dst), "l"(src), "r"(sz) : "memory");
}
__device__ __forceinline__ void cp_commit() { asm volatile("cp.async.commit_group;" ::: "memory"); }
__device__ __forceinline__ void cp_wait2()  { asm volatile("cp.async.wait_group 2;" ::: "memory"); }
__device__ __forceinline__ void mbar_init(uint32_t mbar, uint32_t cnt) {
    asm volatile("mbarrier.init.shared.b64 [%0], %1;" :: "r"(mbar), "r"(cnt) : "memory");
}
__device__ __forceinline__ void mbar_wait(uint32_t mbar, uint32_t parity) {
    asm volatile(
        "{\n\t.reg .pred P;\nW_%=:\n\t"
        "mbarrier.try_wait.parity.acquire.cta.shared::cta.b64 P, [%0], %1, 0x989680;\n\t"
        "@P bra.uni D_%=;\n\tbra.uni W_%=;\nD_%=:\n\t}"
        :: "r"(mbar), "r"(parity) : "memory");
}
__device__ __forceinline__ void tc_alloc(uint32_t s, uint32_t n) {
    asm volatile("tcgen05.alloc.cta_group::1.sync.aligned.shared::cta.b32 [%0], %1;" :: "r"(s), "r"(n) : "memory");
}
__device__ __forceinline__ void tc_relinquish() {
    asm volatile("tcgen05.relinquish_alloc_permit.cta_group::1.sync.aligned;");
}
__device__ __forceinline__ void tc_dealloc(uint32_t t, uint32_t n) {
    asm volatile("tcgen05.dealloc.cta_group::1.sync.aligned.b32 %0, %1;" :: "r"(t), "r"(n));
}
__device__ __forceinline__ void tc_commit(uint32_t mbar) {
    asm volatile("tcgen05.commit.cta_group::1.mbarrier::arrive::one.shared::cluster.b64 [%0];" :: "r"(mbar) : "memory");
}
__device__ __forceinline__ void fence_async()   { asm volatile("fence.proxy.async.shared::cta;" ::: "memory"); }
__device__ __forceinline__ void tc_fence_after(){ asm volatile("tcgen05.fence::after_thread_sync;" ::: "memory"); }
__device__ __forceinline__ void tc_wait_ld()    { asm volatile("tcgen05.wait::ld.sync.aligned;" ::: "memory"); }
__device__ __forceinline__ void mma_tf32_ss(uint32_t d, uint64_t ad, uint64_t bd, uint32_t idesc, uint32_t en) {
    asm volatile(
        "{\n\t.reg .pred p;\n\tsetp.ne.u32 p, %5, 0;\n\t"
        "tcgen05.mma.cta_group::1.kind::tf32 [%0], %1, %2, %3, {%4, %4, %4, %4}, p;\n\t}"
        :: "r"(d), "l"(ad), "l"(bd), "r"(idesc), "r"(0u), "r"(en) : "memory");
}
__device__ __forceinline__ void ldtm32(uint32_t* r, uint32_t addr) {
    asm volatile(
        "tcgen05.ld.sync.aligned.32x32b.x32.b32 "
        "{%0, %1, %2, %3, %4, %5, %6, %7, %8, %9, %10, %11, %12, %13, %14, %15, "
        "%16, %17, %18, %19, %20, %21, %22, %23, %24, %25, %26, %27, %28, %29, %30, %31}, [%32];"
        : "=r"(r[0]), "=r"(r[1]), "=r"(r[2]), "=r"(r[3]), "=r"(r[4]), "=r"(r[5]), "=r"(r[6]), "=r"(r[7]),
          "=r"(r[8]), "=r"(r[9]), "=r"(r[10]), "=r"(r[11]), "=r"(r[12]), "=r"(r[13]), "=r"(r[14]), "=r"(r[15]),
          "=r"(r[16]), "=r"(r[17]), "=r"(r[18]), "=r"(r[19]), "=r"(r[20]), "=r"(r[21]), "=r"(r[22]), "=r"(r[23]),
          "=r"(r[24]), "=r"(r[25]), "=r"(r[26]), "=r"(r[27]), "=r"(r[28]), "=r"(r[29]), "=r"(r[30]), "=r"(r[31])
        : "r"(addr));
}
__device__ __forceinline__ uint32_t sw128(uint32_t b) { return b ^ ((b >> 3) & 0x70); }
#define DESCK  0x4000404000010000ull
#endif

__global__ void zero_cnt_kernel(int* cnt) {
    if (threadIdx.x < E) cnt[threadIdx.x] = 0;
}

__global__ __launch_bounds__(256) void prep_kernel(
    const float* __restrict__ sw1, float* __restrict__ sw1r,
    const float* __restrict__ sw2, float* __restrict__ sw2r)
{
    int i = blockIdx.x * 256 + threadIdx.x;
    float4 a = ((const float4*)sw1)[i];
    a.x = f2tf_f(a.x); a.y = f2tf_f(a.y); a.z = f2tf_f(a.z); a.w = f2tf_f(a.w);
    ((float4*)sw1r)[i] = a;
    float4 b = ((const float4*)sw2)[i];
    b.x = f2tf_f(b.x); b.y = f2tf_f(b.y); b.z = f2tf_f(b.z); b.w = f2tf_f(b.w);
    ((float4*)sw2r)[i] = b;
}

// router v2: 8 tokens per block (rw traffic /8); also writes tf32-rounded x
__global__ __launch_bounds__(256) void router2_kernel(
    const float* __restrict__ x, const float* __restrict__ rw,
    const float* __restrict__ bias,
    int* __restrict__ cnt, int* __restrict__ slot_token,
    int* __restrict__ pair_slot, float* __restrict__ pair_w,
    float* __restrict__ xr)
{
    const int tb = blockIdx.x * 8;
    __shared__ float xs[8][H];
    __shared__ float sc[8][E];
    __shared__ float sb[E];
    const int tid = threadIdx.x;
    const int warp = tid >> 5, lane = tid & 31;

    for (int i = tid; i < 8 * H / 4; i += 256) {
        int row = i >> 8, c4 = i & 255;
        float4 v = ((const float4*)(x + (size_t)(tb + row) * H))[c4];
        ((float4*)xs[row])[c4] = v;
        float4 r = make_float4(f2tf_f(v.x), f2tf_f(v.y), f2tf_f(v.z), f2tf_f(v.w));
        ((float4*)(xr + (size_t)(tb + row) * H))[c4] = r;
    }
    if (tid < E) sb[tid] = bias[tid];
    __syncthreads();

    for (int q = 0; q < 8; q++) {
        int e = warp * 8 + q;
        const float* wrow = rw + (size_t)e * H;
        float s[8];
        #pragma unroll
        for (int tt = 0; tt < 8; tt++) s[tt] = 0.f;
        for (int i = lane; i < H; i += 32) {
            float wv = wrow[i];
            #pragma unroll
            for (int tt = 0; tt < 8; tt++) s[tt] += xs[tt][i] * wv;
        }
        #pragma unroll
        for (int o = 16; o; o >>= 1)
            #pragma unroll
            for (int tt = 0; tt < 8; tt++) s[tt] += __shfl_xor_sync(0xffffffffu, s[tt], o);
        if (lane == 0) {
            #pragma unroll
            for (int tt = 0; tt < 8; tt++) sc[tt][e] = 1.f / (1.f + expf(-s[tt]));
        }
    }
    __syncthreads();

    if (tid < 8) {
        int t = tb + tid;
        unsigned long long used = 0ull;
        int idx[KTOP]; float tsc[KTOP]; float sum = 0.f;
        #pragma unroll
        for (int k = 0; k < KTOP; k++) {
            float best = -1e30f; int bi = 0;
            for (int e = 0; e < E; e++) {
                if (used & (1ull << e)) continue;
                float v = sc[tid][e] + sb[e];
                if (v > best) { best = v; bi = e; }
            }
            used |= 1ull << bi; idx[k] = bi; tsc[k] = sc[tid][bi]; sum += sc[tid][bi];
        }
        float inv = 1.f / (sum + 1e-20f);
        #pragma unroll
        for (int k = 0; k < KTOP; k++) {
            int e = idx[k];
            int pos = atomicAdd(&cnt[e], 1);
            float w = tsc[k] * inv;
            int slot;
            if (pos < CAP) { slot = e * CAP + pos; slot_token[slot] = t; }
            else           { slot = 0; w = 0.f; }
            pair_slot[t * KTOP + k] = slot;
            pair_w[t * KTOP + k]    = w;
        }
    }
}

// float4 transpose + tf32 round: src [E][R][C] -> dst [E][C][R]
__global__ __launch_bounds__(256) void transpose4_kernel(
    const float* __restrict__ src, float* __restrict__ dst, int R, int Cc)
{
    __shared__ float tile[32][132];
    int e = blockIdx.z;
    const float* S = src + (size_t)e * R * Cc;
    float*       D = dst + (size_t)e * R * Cc;
    int r0 = blockIdx.y * 32, c0 = blockIdx.x * 128;
    int tx = threadIdx.x & 31, ty = threadIdx.x >> 5;
    #pragma unroll
    for (int i = 0; i < 4; i++) {
        int r = ty + 8 * i;
        float4 v = *(const float4*)(S + (size_t)(r0 + r) * Cc + c0 + tx * 4);
        tile[r][tx * 4 + 0] = f2tf_f(v.x);
        tile[r][tx * 4 + 1] = f2tf_f(v.y);
        tile[r][tx * 4 + 2] = f2tf_f(v.z);
        tile[r][tx * 4 + 3] = f2tf_f(v.w);
    }
    __syncthreads();
    int rx = threadIdx.x & 7, cy = threadIdx.x >> 3;
    #pragma unroll
    for (int i = 0; i < 4; i++) {
        int c = cy + 32 * i;
        float4 o = make_float4(tile[rx * 4 + 0][c], tile[rx * 4 + 1][c],
                               tile[rx * 4 + 2][c], tile[rx * 4 + 3][c]);
        *(float4*)(D + (size_t)(c0 + c) * R + r0 + rx * 4) = o;
    }
}

// tcgen05 TF32 GEMM, cp.async 4-stage (unchanged from R7 — validated)
template<bool GATHER, bool GELU, bool ROUND, int NTILE>
__global__ __launch_bounds__(256) void gemm_tc(
    const float* __restrict__ Aall, long long sAe, int ldA,
    const float* __restrict__ Ball, long long sBe,
    float* __restrict__ Call, long long sCe, int ldC,
    int Kdim, int Ncols,
    const int* __restrict__ cnts, int Mmax,
    const int* __restrict__ tokall)
{
    const int e  = blockIdx.z;
    const int m0 = blockIdx.y * 128;
    const int n0 = blockIdx.x * NTILE;
    int M = Mmax;
    if (cnts) { M = min(cnts[e], Mmax); if (m0 >= M) return; }

    const float* B = Ball + (long long)e * sBe;
    float*       C = Call + (long long)e * sCe;

#if TC_OK
    constexpr int ABYTES = 16384;
    constexpr int BBYTES = NTILE * 128;
    constexpr int STAGE  = ABYTES + BBYTES;
    constexpr int NB     = NTILE / 32;
    constexpr uint32_t IDESC = (NTILE == 256) ? 0x8400910u : 0x8200910u;

    extern __shared__ char smraw_c[];
    const uint32_t sbase = (smem_u32(smraw_c) + 1023u) & ~1023u;
    const uint32_t ctrl  = sbase + 4 * STAGE;

    const int tid  = threadIdx.x;
    const int warp = tid >> 5;
    const int lane = tid & 31;

    if (warp == 0) { tc_alloc(ctrl, 256); tc_relinquish(); }
    if (tid == 0) {
        #pragma unroll
        for (int j = 0; j < 4; j++) mbar_init(ctrl + 8 + 8 * j, 1);
    }
    __syncthreads();
    uint32_t tmem;
    asm volatile("ld.shared.b32 %0, [%1];" : "=r"(tmem) : "r"(ctrl));

    const float* aptr[4]; uint32_t a_sts[4], a_ok[4];
    #pragma unroll
    for (int j = 0; j < 4; j++) {
        int g = tid + j * 256;
        int m = g >> 3, k4 = (g & 7) * 4;
        a_sts[j] = sw128(m * 128 + k4 * 4);
        if (GATHER) {
            int tok = (m0 + m < M) ? tokall[e * CAP + m0 + m] : -1;
            a_ok[j] = (tok >= 0) ? 16u : 0u;
            aptr[j] = (tok >= 0) ? (Aall + (long long)tok * ldA + k4) : Aall;
        } else {
            a_ok[j] = 16u;
            aptr[j] = Aall + (long long)e * sAe + (long long)(m0 + m) * ldA + k4;
        }
    }
    const float* bptr[NB]; uint32_t b_sts[NB];
    #pragma unroll
    for (int j = 0; j < NB; j++) {
        int g = tid + j * 256;
        int n = g >> 3, k4 = (g & 7) * 4;
        b_sts[j] = sw128(n * 128 + k4 * 4);
        bptr[j]  = B + (long long)(n0 + n) * Kdim + k4;
    }

    const int ntiles = Kdim >> 5;

    auto issue = [&](int it) {
        uint32_t base = sbase + (it & 3) * STAGE;
        long long ka = (long long)it * 32;
        #pragma unroll
        for (int j = 0; j < 4; j++) cpasync16(base + a_sts[j], aptr[j] + ka, a_ok[j]);
        #pragma unroll
        for (int j = 0; j < NB; j++) cpasync16(base + ABYTES + b_sts[j], bptr[j] + ka, 16u);
    };

    issue(0); cp_commit();
    issue(1); cp_commit();
    issue(2); cp_commit();

    for (int it = 0; it < ntiles; ++it) {
        cp_wait2();
        __syncthreads();

        if (warp == 0 && elect_one()) {
            fence_async();
            uint32_t sa = sbase + (it & 3) * STAGE;
            uint64_t ad = DESCK | ((sa >> 4) & 0x3FFFu);
            uint64_t bd = DESCK | (((sa + ABYTES) >> 4) & 0x3FFFu);
            #pragma unroll
            for (int s = 0; s < 4; s++)
                mma_tf32_ss(tmem, ad + 2 * s, bd + 2 * s, IDESC, (it | s) != 0);
            tc_commit(ctrl + 8 + 8 * (it & 3));
        }

        if (it + 3 < ntiles) {
            if (it >= 1) {
                int p = it - 1;
                mbar_wait(ctrl + 8 + 8 * (p & 3), (p >> 2) & 1);
            }
            issue(it + 3);
        }
        cp_commit();
    }

    {
        int p = ntiles - 1;
        mbar_wait(ctrl + 8 + 8 * (p & 3), (p >> 2) & 1);
    }
    tc_fence_after();

    {
        const int w4 = warp & 3, half = warp >> 2;
        const int row = m0 + w4 * 32 + lane;
        float* crow = C + (long long)row * ldC + n0;
        #pragma unroll
        for (int i = 0; i < NTILE / 64; i++) {
            int c0 = half * (NTILE / 2) + i * 32;
            uint32_t r[32];
            ldtm32(r, tmem + c0);
            tc_wait_ld();
            float fv[32];
            #pragma unroll
            for (int q = 0; q < 32; q++) {
                float v = __uint_as_float(r[q]);
                if (GELU)  v = gelu_tanh(v);
                if (ROUND) v = f2tf_f(v);
                fv[q] = v;
            }
            #pragma unroll
            for (int q = 0; q < 8; q++) {
                float4 o = make_float4(fv[q*4], fv[q*4+1], fv[q*4+2], fv[q*4+3]);
                *(float4*)(crow + c0 + q * 4) = o;
            }
        }
    }
    __syncthreads();
    if (warp == 0) tc_dealloc(tmem, 256);

#else  // generic-target fallback (compile-only)
    const int tid = threadIdx.x;
    const int nper = NTILE / 128;
    const int row = m0 + (tid >> 1);
    const int nh  = (tid & 1) * (NTILE / 2);
    const float* arow;
    if (GATHER) {
        int tok = (row < M) ? tokall[e * CAP + row] : -1;
        arow = (tok >= 0) ? (Aall + (long long)tok * ldA) : nullptr;
    } else {
        arow = Aall + (long long)e * sAe + (long long)row * ldA;
    }
    for (int c = 0; c < 2 * nper; c++) {
        float acc[32];
        #pragma unroll
        for (int q = 0; q < 32; q++) acc[q] = 0.f;
        int nb = n0 + nh + c * 32;
        for (int k = 0; k < Kdim; k++) {
            float a = arow ? arow[k] : 0.f;
            #pragma unroll 8
            for (int q = 0; q < 32; q++) acc[q] += a * B[(long long)(nb + q) * Kdim + k];
        }
        float* crow = C + (long long)row * ldC;
        for (int q = 0; q < 32; q++) {
            float v = acc[q];
            if (GELU) v = gelu_tanh(v);
            crow[nb + q] = v;
        }
    }
#endif
}

__global__ __launch_bounds__(256) void combine_kernel(
    float* __restrict__ out, const float* __restrict__ y,
    const int* __restrict__ pair_slot, const float* __restrict__ pair_w)
{
    int t = blockIdx.x;
    int slot[KTOP]; float w[KTOP];
    #pragma unroll
    for (int k = 0; k < KTOP; k++) {
        slot[k] = pair_slot[t * KTOP + k];
        w[k]    = pair_w[t * KTOP + k];
    }
    int h4 = threadIdx.x;
    float4 acc = *(float4*)(out + (size_t)t * H + h4 * 4);
    #pragma unroll
    for (int k = 0; k < KTOP; k++) {
        float4 v = *(const float4*)(y + (size_t)slot[k] * H + h4 * 4);
        acc.x += w[k] * v.x; acc.y += w[k] * v.y;
        acc.z += w[k] * v.z; acc.w += w[k] * v.w;
    }
    *(float4*)(out + (size_t)t * H + h4 * 4) = acc;
}

// ---------------- launch (forked-stream graph) ----------------
extern "C" void kernel_launch(void* const* d_in, const int* in_sizes, int n_in,
                              void* d_out, int out_size)
{
    const float* x   = (const float*)d_in[0];
    const float* rw  = (const float*)d_in[1];
    const float* eb  = (const float*)d_in[2];
    const float* w1  = (const float*)d_in[3];
    const float* w2  = (const float*)d_in[4];
    const float* sw1 = (const float*)d_in[5];
    const float* sw2 = (const float*)d_in[6];
    float* out = (float*)d_out;

    void *pcnt, *ptok, *pps, *ppw, *pmid, *py, *psmid, *pw1t, *pw2t, *pxr, *psw1r, *psw2r;
    cudaGetSymbolAddress(&pcnt,  g_cnt);
    cudaGetSymbolAddress(&ptok,  g_slot_token);
    cudaGetSymbolAddress(&pps,   g_pair_slot);
    cudaGetSymbolAddress(&ppw,   g_pair_w);
    cudaGetSymbolAddress(&pmid,  g_mid);
    cudaGetSymbolAddress(&py,    g_y);
    cudaGetSymbolAddress(&psmid, g_smid);
    cudaGetSymbolAddress(&pw1t,  g_w1t);
    cudaGetSymbolAddress(&pw2t,  g_w2t);
    cudaGetSymbolAddress(&pxr,   g_xr);
    cudaGetSymbolAddress(&psw1r, g_sw1r);
    cudaGetSymbolAddress(&psw2r, g_sw2r);

    int*   cnt       = (int*)pcnt;
    int*   slot_tok  = (int*)ptok;
    int*   pair_slot = (int*)pps;
    float* pair_w    = (float*)ppw;
    float* mid       = (float*)pmid;
    float* y         = (float*)py;
    float* smid      = (float*)psmid;
    float* w1t       = (float*)pw1t;
    float* w2t       = (float*)pw2t;
    float* xr        = (float*)pxr;
    float* sw1r      = (float*)psw1r;
    float* sw2r      = (float*)psw2r;

    static cudaStream_t s1 = nullptr, s2 = nullptr;
    static cudaEvent_t evFork, evT1, evT2, evR, evS;
    if (!s1) {
        cudaStreamCreateWithFlags(&s1, cudaStreamNonBlocking);
        cudaStreamCreateWithFlags(&s2, cudaStreamNonBlocking);
        cudaEventCreateWithFlags(&evFork, cudaEventDisableTiming);
        cudaEventCreateWithFlags(&evT1,   cudaEventDisableTiming);
        cudaEventCreateWithFlags(&evT2,   cudaEventDisableTiming);
        cudaEventCreateWithFlags(&evR,    cudaEventDisableTiming);
        cudaEventCreateWithFlags(&evS,    cudaEventDisableTiming);
        const int SM256 = 4 * (16384 + 256 * 128) + 1024 + 64;
        const int SM128 = 4 * (16384 + 128 * 128) + 1024 + 64;
        cudaFuncSetAttribute(gemm_tc<true,  true,  true,  256>, cudaFuncAttributeMaxDynamicSharedMemorySize, SM256);
        cudaFuncSetAttribute(gemm_tc<false, false, false, 256>, cudaFuncAttributeMaxDynamicSharedMemorySize, SM256);
        cudaFuncSetAttribute(gemm_tc<false, true,  true,  256>, cudaFuncAttributeMaxDynamicSharedMemorySize, SM256);
        cudaFuncSetAttribute(gemm_tc<false, false, false, 128>, cudaFuncAttributeMaxDynamicSharedMemorySize, SM128);
    }
    const int SM256 = 4 * (16384 + 256 * 128) + 1024 + 64;
    const int SM128 = 4 * (16384 + 128 * 128) + 1024 + 64;

    // main chain (stream 0): zero -> router -> G1 -> G2 -> combine
    zero_cnt_kernel<<<1, 64>>>(cnt);
    cudaEventRecord(evFork, 0);
    cudaStreamWaitEvent(s1, evFork, 0);
    cudaStreamWaitEvent(s2, evFork, 0);

    // s1: transposes (feed G1/G2)
    transpose4_kernel<<<dim3(F / 128, H / 32, E), 256, 0, s1>>>(w1, w1t, H, F);
    cudaEventRecord(evT1, s1);
    transpose4_kernel<<<dim3(H / 128, F / 32, E), 256, 0, s1>>>(w2, w2t, F, H);
    cudaEventRecord(evT2, s1);

    // s2: shared-expert chain (prep; SG1 waits router for xr)
    prep_kernel<<<SF * H / 4 / 256, 256, 0, s2>>>(sw1, sw1r, sw2, sw2r);

    router2_kernel<<<T / 8, 256>>>(x, rw, eb, cnt, slot_tok, pair_slot, pair_w, xr);
    cudaEventRecord(evR, 0);
    cudaStreamWaitEvent(s2, evR, 0);

    gemm_tc<false, true, true, 256><<<dim3(SF / 256, T / 128, 1), 256, SM256, s2>>>(
        xr, 0LL, H, sw1r, 0LL, smid, 0LL, SF, H, SF, nullptr, T, nullptr);
    gemm_tc<false, false, false, 128><<<dim3(H / 128, T / 128, 1), 256, SM128, s2>>>(
        smid, 0LL, SF, sw2r, 0LL, out, 0LL, H, SF, H, nullptr, T, nullptr);
    cudaEventRecord(evS, s2);

    cudaStreamWaitEvent(0, evT1, 0);
    gemm_tc<true, true, true, 256><<<dim3(F / 256, CAP / 128, E), 256, SM256>>>(
        xr, 0LL, H, w1t, (long long)H * F, mid, (long long)CAP * F, F,
        H, F, cnt, CAP, slot_tok);
    cudaStreamWaitEvent(0, evT2, 0);
    gemm_tc<false, false, false, 256><<<dim3(H / 256, CAP / 128, E), 256, SM256>>>(
        mid, (long long)CAP * F, F, w2t, (long long)F * H, y, (long long)CAP * H, H,
        F, H, cnt, CAP, slot_tok);

    cudaStreamWaitEvent(0, evS, 0);
    combine_kernel<<<T, 256>>>(out, y, pair_slot, pair_w);
}

// round 10
// speedup vs baseline: 2.7325x; 1.1026x over previous
#include <cuda_runtime.h>
#include <math.h>
#include <stdint.h>

#define E    64
#define KTOP 6
#define H    1024
#define F    512
#define SF   2048
#define T    2048
#define CAP  384

#if !defined(__CUDA_ARCH__) || defined(__CUDA_ARCH_FEAT_SM103_ALL) || \
    defined(__CUDA_ARCH_FEAT_SM100_ALL) || defined(__CUDA_ARCH_FEAT_SM101_ALL) || \
    defined(__CUDA_ARCH_SPECIFIC__)
#define TC_OK 1
#else
#define TC_OK 0
#endif

__device__ int   g_cnt[E];
__device__ int   g_slot_token[E * CAP];
__device__ int   g_pair_slot[T * KTOP];
__device__ float g_pair_w[T * KTOP];
__device__ float g_mid[(size_t)E * CAP * F];
__device__ float g_y[(size_t)E * CAP * H];
__device__ float g_smid[(size_t)T * SF];
__device__ float g_xr[(size_t)T * H];
__device__ float g_sw1r[(size_t)SF * H];
__device__ float g_sw2r[(size_t)H * SF];

__device__ __forceinline__ float gelu_tanh(float x) {
    float u = 0.7978845608028654f * (x + 0.044715f * x * x * x);
    return 0.5f * x * (1.0f + tanhf(u));
}
__device__ __forceinline__ float f2tf_f(float f) {
    unsigned u;
    asm("cvt.rna.tf32.f32 %0, %1;" : "=r"(u) : "f"(f));
    return __uint_as_float(u);
}

#if TC_OK
__device__ __forceinline__ uint32_t smem_u32(const void* p) {
    uint32_t a;
    asm("{ .reg .u64 t; cvta.to.shared.u64 t, %1; cvt.u32.u64 %0, t; }" : "=r"(a) : "l"(p));
    return a;
}
__device__ __forceinline__ uint32_t elect_one() {
    uint32_t pred;
    asm volatile("{\n\t.reg .pred p;\n\telect.sync _|p, 0xFFFFFFFF;\n\tselp.b32 %0, 1, 0, p;\n\t}" : "=r"(pred));
    return pred;
}
__device__ __forceinline__ void cpasync16(uint32_t dst, const void* src, uint32_t sz) {
    asm volatile("cp.async.cg.shared.global [%0], [%1], 16, %2;" :: "r"(dst), "l"(src), "r"(sz) : "memory");
}
__device__ __forceinline__ void cp_commit() { asm volatile("cp.async.commit_group;" ::: "memory"); }
__device__ __forceinline__ void cp_wait1()  { asm volatile("cp.async.wait_group 1;" ::: "memory"); }
__device__ __forceinline__ void cp_wait2()  { asm volatile("cp.async.wait_group 2;" ::: "memory"); }
__device__ __forceinline__ void mbar_init(uint32_t mbar, uint32_t cnt) {
    asm volatile("mbarrier.init.shared.b64 [%0], %1;" :: "r"(mbar), "r"(cnt) : "memory");
}
__device__ __forceinline__ void mbar_wait(uint32_t mbar, uint32_t parity) {
    asm volatile(
        "{\n\t.reg .pred P;\nW_%=:\n\t"
        "mbarrier.try_wait.parity.acquire.cta.shared::cta.b64 P, [%0], %1, 0x989680;\n\t"
        "@P bra.uni D_%=;\n\tbra.uni W_%=;\nD_%=:\n\t}"
        :: "r"(mbar), "r"(parity) : "memory");
}
__device__ __forceinline__ void tc_alloc(uint32_t s, uint32_t n) {
    asm volatile("tcgen05.alloc.cta_group::1.sync.aligned.shared::cta.b32 [%0], %1;" :: "r"(s), "r"(n) : "memory");
}
__device__ __forceinline__ void tc_relinquish() {
    asm volatile("tcgen05.relinquish_alloc_permit.cta_group::1.sync.aligned;");
}
__device__ __forceinline__ void tc_dealloc(uint32_t t, uint32_t n) {
    asm volatile("tcgen05.dealloc.cta_group::1.sync.aligned.b32 %0, %1;" :: "r"(t), "r"(n));
}
__device__ __forceinline__ void tc_commit(uint32_t mbar) {
    asm volatile("tcgen05.commit.cta_group::1.mbarrier::arrive::one.shared::cluster.b64 [%0];" :: "r"(mbar) : "memory");
}
__device__ __forceinline__ void fence_async()   { asm volatile("fence.proxy.async.shared::cta;" ::: "memory"); }
__device__ __forceinline__ void tc_fence_after(){ asm volatile("tcgen05.fence::after_thread_sync;" ::: "memory"); }
__device__ __forceinline__ void tc_wait_ld()    { asm volatile("tcgen05.wait::ld.sync.aligned;" ::: "memory"); }
__device__ __forceinline__ void mma_tf32_ss(uint32_t d, uint64_t ad, uint64_t bd, uint32_t idesc, uint32_t en) {
    asm volatile(
        "{\n\t.reg .pred p;\n\tsetp.ne.u32 p, %5, 0;\n\t"
        "tcgen05.mma.cta_group::1.kind::tf32 [%0], %1, %2, %3, {%4, %4, %4, %4}, p;\n\t}"
        :: "r"(d), "l"(ad), "l"(bd), "r"(idesc), "r"(0u), "r"(en) : "memory");
}
__device__ __forceinline__ void ldtm32(uint32_t* r, uint32_t addr) {
    asm volatile(
        "tcgen05.ld.sync.aligned.32x32b.x32.b32 "
        "{%0, %1, %2, %3, %4, %5, %6, %7, %8, %9, %10, %11, %12, %13, %14, %15, "
        "%16, %17, %18, %19, %20, %21, %22, %23, %24, %25, %26, %27, %28, %29, %30, %31}, [%32];"
        : "=r"(r[0]), "=r"(r[1]), "=r"(r[2]), "=r"(r[3]), "=r"(r[4]), "=r"(r[5]), "=r"(r[6]), "=r"(r[7]),
          "=r"(r[8]), "=r"(r[9]), "=r"(r[10]), "=r"(r[11]), "=r"(r[12]), "=r"(r[13]), "=r"(r[14]), "=r"(r[15]),
          "=r"(r[16]), "=r"(r[17]), "=r"(r[18]), "=r"(r[19]), "=r"(r[20]), "=r"(r[21]), "=r"(r[22]), "=r"(r[23]),
          "=r"(r[24]), "=r"(r[25]), "=r"(r[26]), "=r"(r[27]), "=r"(r[28]), "=r"(r[29]), "=r"(r[30]), "=r"(r[31])
        : "r"(addr));
}
__device__ __forceinline__ float lds_f32(uint32_t a) {
    float v; asm volatile("ld.shared.f32 %0, [%1];" : "=f"(v) : "r"(a)); return v;
}
__device__ __forceinline__ void sts128(uint32_t a, float4 v) {
    asm volatile("st.shared.v4.f32 [%0], {%1,%2,%3,%4};" :: "r"(a), "f"(v.x), "f"(v.y), "f"(v.z), "f"(v.w) : "memory");
}
__device__ __forceinline__ uint32_t sw128(uint32_t b) { return b ^ ((b >> 3) & 0x70); }
#define DESCK  0x4000404000010000ull
#define IDESC_N256 0x8400910u
#define IDESC_N128 0x8200910u
#endif

__global__ void zero_cnt_kernel(int* cnt) {
    if (threadIdx.x < E) cnt[threadIdx.x] = 0;
}

__global__ __launch_bounds__(256) void prep_kernel(
    const float* __restrict__ sw1, float* __restrict__ sw1r,
    const float* __restrict__ sw2, float* __restrict__ sw2r)
{
    int i = blockIdx.x * 256 + threadIdx.x;
    float4 a = ((const float4*)sw1)[i];
    a.x = f2tf_f(a.x); a.y = f2tf_f(a.y); a.z = f2tf_f(a.z); a.w = f2tf_f(a.w);
    ((float4*)sw1r)[i] = a;
    float4 b = ((const float4*)sw2)[i];
    b.x = f2tf_f(b.x); b.y = f2tf_f(b.y); b.z = f2tf_f(b.z); b.w = f2tf_f(b.w);
    ((float4*)sw2r)[i] = b;
}

__global__ __launch_bounds__(256) void router2_kernel(
    const float* __restrict__ x, const float* __restrict__ rw,
    const float* __restrict__ bias,
    int* __restrict__ cnt, int* __restrict__ slot_token,
    int* __restrict__ pair_slot, float* __restrict__ pair_w,
    float* __restrict__ xr)
{
    const int tb = blockIdx.x * 8;
    __shared__ float xs[8][H];
    __shared__ float sc[8][E];
    __shared__ float sb[E];
    const int tid = threadIdx.x;
    const int warp = tid >> 5, lane = tid & 31;

    for (int i = tid; i < 8 * H / 4; i += 256) {
        int row = i >> 8, c4 = i & 255;
        float4 v = ((const float4*)(x + (size_t)(tb + row) * H))[c4];
        ((float4*)xs[row])[c4] = v;
        float4 r = make_float4(f2tf_f(v.x), f2tf_f(v.y), f2tf_f(v.z), f2tf_f(v.w));
        ((float4*)(xr + (size_t)(tb + row) * H))[c4] = r;
    }
    if (tid < E) sb[tid] = bias[tid];
    __syncthreads();

    for (int q = 0; q < 8; q++) {
        int e = warp * 8 + q;
        const float* wrow = rw + (size_t)e * H;
        float s[8];
        #pragma unroll
        for (int tt = 0; tt < 8; tt++) s[tt] = 0.f;
        for (int i = lane; i < H; i += 32) {
            float wv = wrow[i];
            #pragma unroll
            for (int tt = 0; tt < 8; tt++) s[tt] += xs[tt][i] * wv;
        }
        #pragma unroll
        for (int o = 16; o; o >>= 1)
            #pragma unroll
            for (int tt = 0; tt < 8; tt++) s[tt] += __shfl_xor_sync(0xffffffffu, s[tt], o);
        if (lane == 0) {
            #pragma unroll
            for (int tt = 0; tt < 8; tt++) sc[tt][e] = 1.f / (1.f + expf(-s[tt]));
        }
    }
    __syncthreads();

    if (tid < 8) {
        int t = tb + tid;
        unsigned long long used = 0ull;
        int idx[KTOP]; float tsc[KTOP]; float sum = 0.f;
        #pragma unroll
        for (int k = 0; k < KTOP; k++) {
            float best = -1e30f; int bi = 0;
            for (int e = 0; e < E; e++) {
                if (used & (1ull << e)) continue;
                float v = sc[tid][e] + sb[e];
                if (v > best) { best = v; bi = e; }
            }
            used |= 1ull << bi; idx[k] = bi; tsc[k] = sc[tid][bi]; sum += sc[tid][bi];
        }
        float inv = 1.f / (sum + 1e-20f);
        #pragma unroll
        for (int k = 0; k < KTOP; k++) {
            int e = idx[k];
            int pos = atomicAdd(&cnt[e], 1);
            float w = tsc[k] * inv;
            int slot;
            if (pos < CAP) { slot = e * CAP + pos; slot_token[slot] = t; }
            else           { slot = 0; w = 0.f; }
            pair_slot[t * KTOP + k] = slot;
            pair_w[t * KTOP + k]    = w;
        }
    }
}

// ===== gemm_tc: validated K-major-B tcgen05 GEMM (shared expert) =====
template<bool GATHER, bool GELU, bool ROUND, int NTILE>
__global__ __launch_bounds__(256) void gemm_tc(
    const float* __restrict__ Aall, long long sAe, int ldA,
    const float* __restrict__ Ball, long long sBe,
    float* __restrict__ Call, long long sCe, int ldC,
    int Kdim, int Ncols,
    const int* __restrict__ cnts, int Mmax,
    const int* __restrict__ tokall)
{
    const int e  = blockIdx.z;
    const int m0 = blockIdx.y * 128;
    const int n0 = blockIdx.x * NTILE;
    int M = Mmax;
    if (cnts) { M = min(cnts[e], Mmax); if (m0 >= M) return; }
    const float* B = Ball + (long long)e * sBe;
    float*       C = Call + (long long)e * sCe;

#if TC_OK
    constexpr int ABYTES = 16384;
    constexpr int BBYTES = NTILE * 128;
    constexpr int STAGE  = ABYTES + BBYTES;
    constexpr int NB     = NTILE / 32;
    constexpr uint32_t IDESC = (NTILE == 256) ? IDESC_N256 : IDESC_N128;

    extern __shared__ char smraw_c[];
    const uint32_t sbase = (smem_u32(smraw_c) + 1023u) & ~1023u;
    const uint32_t ctrl  = sbase + 4 * STAGE;
    const int tid = threadIdx.x, warp = tid >> 5, lane = tid & 31;

    if (warp == 0) { tc_alloc(ctrl, 256); tc_relinquish(); }
    if (tid == 0) {
        #pragma unroll
        for (int j = 0; j < 4; j++) mbar_init(ctrl + 8 + 8 * j, 1);
    }
    __syncthreads();
    uint32_t tmem;
    asm volatile("ld.shared.b32 %0, [%1];" : "=r"(tmem) : "r"(ctrl));

    const float* aptr[4]; uint32_t a_sts[4], a_ok[4];
    #pragma unroll
    for (int j = 0; j < 4; j++) {
        int g = tid + j * 256;
        int m = g >> 3, k4 = (g & 7) * 4;
        a_sts[j] = sw128(m * 128 + k4 * 4);
        if (GATHER) {
            int tok = (m0 + m < M) ? tokall[e * CAP + m0 + m] : -1;
            a_ok[j] = (tok >= 0) ? 16u : 0u;
            aptr[j] = (tok >= 0) ? (Aall + (long long)tok * ldA + k4) : Aall;
        } else {
            a_ok[j] = 16u;
            aptr[j] = Aall + (long long)e * sAe + (long long)(m0 + m) * ldA + k4;
        }
    }
    const float* bptr[NB]; uint32_t b_sts[NB];
    #pragma unroll
    for (int j = 0; j < NB; j++) {
        int g = tid + j * 256;
        int n = g >> 3, k4 = (g & 7) * 4;
        b_sts[j] = sw128(n * 128 + k4 * 4);
        bptr[j]  = B + (long long)(n0 + n) * Kdim + k4;
    }
    const int ntiles = Kdim >> 5;

    auto issue = [&](int it) {
        uint32_t base = sbase + (it & 3) * STAGE;
        long long ka = (long long)it * 32;
        #pragma unroll
        for (int j = 0; j < 4; j++) cpasync16(base + a_sts[j], aptr[j] + ka, a_ok[j]);
        #pragma unroll
        for (int j = 0; j < NB; j++) cpasync16(base + ABYTES + b_sts[j], bptr[j] + ka, 16u);
    };

    issue(0); cp_commit();
    issue(1); cp_commit();
    issue(2); cp_commit();

    for (int it = 0; it < ntiles; ++it) {
        cp_wait2();
        __syncthreads();
        if (warp == 0 && elect_one()) {
            fence_async();
            uint32_t sa = sbase + (it & 3) * STAGE;
            uint64_t ad = DESCK | ((sa >> 4) & 0x3FFFu);
            uint64_t bd = DESCK | (((sa + ABYTES) >> 4) & 0x3FFFu);
            #pragma unroll
            for (int s = 0; s < 4; s++)
                mma_tf32_ss(tmem, ad + 2 * s, bd + 2 * s, IDESC, (it | s) != 0);
            tc_commit(ctrl + 8 + 8 * (it & 3));
        }
        if (it + 3 < ntiles) {
            if (it >= 1) mbar_wait(ctrl + 8 + 8 * ((it - 1) & 3), ((it - 1) >> 2) & 1);
            issue(it + 3);
        }
        cp_commit();
    }
    { int p = ntiles - 1; mbar_wait(ctrl + 8 + 8 * (p & 3), (p >> 2) & 1); }
    tc_fence_after();

    {
        const int w4 = warp & 3, half = warp >> 2;
        const int row = m0 + w4 * 32 + lane;
        float* crow = C + (long long)row * ldC + n0;
        #pragma unroll
        for (int i = 0; i < NTILE / 64; i++) {
            int c0 = half * (NTILE / 2) + i * 32;
            uint32_t r[32];
            ldtm32(r, tmem + c0);
            tc_wait_ld();
            #pragma unroll
            for (int q = 0; q < 8; q++) {
                float4 o;
                float* ov = (float*)&o;
                #pragma unroll
                for (int z = 0; z < 4; z++) {
                    float v = __uint_as_float(r[q * 4 + z]);
                    if (GELU)  v = gelu_tanh(v);
                    if (ROUND) v = f2tf_f(v);
                    ov[z] = v;
                }
                *(float4*)(crow + c0 + q * 4) = o;
            }
        }
    }
    __syncthreads();
    if (warp == 0) tc_dealloc(tmem, 256);
#else
    const int tid = threadIdx.x;
    const int row = m0 + (tid >> 1);
    const int nh  = (tid & 1) * (NTILE / 2);
    const float* arow;
    if (GATHER) {
        int tok = (row < M) ? tokall[e * CAP + row] : -1;
        arow = (tok >= 0) ? (Aall + (long long)tok * ldA) : nullptr;
    } else arow = Aall + (long long)e * sAe + (long long)row * ldA;
    for (int c = 0; c < NTILE / 64; c++) {
        float acc[32];
        #pragma unroll
        for (int q = 0; q < 32; q++) acc[q] = 0.f;
        int nb = n0 + nh + c * 32;
        for (int k = 0; k < Kdim; k++) {
            float a = arow ? arow[k] : 0.f;
            #pragma unroll 8
            for (int q = 0; q < 32; q++) acc[q] += a * B[(long long)(nb + q) * Kdim + k];
        }
        float* crow = C + (long long)row * ldC;
        for (int q = 0; q < 32; q++) {
            float v = acc[q];
            if (GELU) v = gelu_tanh(v);
            crow[nb + q] = v;
        }
    }
#endif
}

// ===== gemm_bt: expert GEMM, B stored [K][N]; in-kernel SMEM transpose+round =====
template<bool GATHER, bool GELU, bool ROUND>
__global__ __launch_bounds__(256) void gemm_bt(
    const float* __restrict__ Aall, long long sAe, int ldA,
    const float* __restrict__ Ball, long long sBe, int ldB,
    float* __restrict__ Call, long long sCe, int ldC,
    int Kdim,
    const int* __restrict__ cnts, int Mmax,
    const int* __restrict__ tokall)
{
    const int e  = blockIdx.z;
    const int m0 = blockIdx.y * 128;
    const int n0 = blockIdx.x * 256;
    int M = Mmax;
    if (cnts) { M = min(cnts[e], Mmax); if (m0 >= M) return; }
    const float* B = Ball + (long long)e * sBe;
    float*       C = Call + (long long)e * sCe;

#if TC_OK
    extern __shared__ char smraw_b[];
    const uint32_t sbase = (smem_u32(smraw_b) + 1023u) & ~1023u;
    // A: 4x16KB @0 ; BK: 2x32KB @65536 ; BR: 2x33280 @131072 ; ctrl @197632
    const uint32_t ctrl = sbase + 197632u;
    const int tid = threadIdx.x, warp = tid >> 5, lane = tid & 31;

    if (warp == 0) { tc_alloc(ctrl, 256); tc_relinquish(); }
    if (tid == 0) {
        #pragma unroll
        for (int j = 0; j < 4; j++) mbar_init(ctrl + 8 + 8 * j, 1);
    }
    __syncthreads();
    uint32_t tmem;
    asm volatile("ld.shared.b32 %0, [%1];" : "=r"(tmem) : "r"(ctrl));

    const float* aptr[4]; uint32_t a_sts[4], a_ok[4];
    #pragma unroll
    for (int j = 0; j < 4; j++) {
        int g = tid + j * 256;
        int m = g >> 3, k4 = (g & 7) * 4;
        a_sts[j] = sw128(m * 128 + k4 * 4);
        if (GATHER) {
            int tok = (m0 + m < M) ? tokall[e * CAP + m0 + m] : -1;
            a_ok[j] = (tok >= 0) ? 16u : 0u;
            aptr[j] = (tok >= 0) ? (Aall + (long long)tok * ldA + k4) : Aall;
        } else {
            a_ok[j] = 16u;
            aptr[j] = Aall + (long long)e * sAe + (long long)(m0 + m) * ldA + k4;
        }
    }
    const float* brsrc = B + (long long)(tid >> 3) * ldB + n0 + (tid & 7) * 4;
    const uint32_t brdst = (uint32_t)(tid >> 3) * 1040u + (uint32_t)(tid & 7) * 16u;

    const int ntiles = Kdim >> 5;
    auto issueA = [&](int it) {
        uint32_t base = sbase + (it & 3) * 16384u;
        long long ka = (long long)it * 32;
        #pragma unroll
        for (int j = 0; j < 4; j++) cpasync16(base + a_sts[j], aptr[j] + ka, a_ok[j]);
    };
    auto issueB = [&](int it) {
        uint32_t base = sbase + 131072u + (it & 1) * 33280u + brdst;
        const float* src = brsrc + (long long)it * 32 * ldB;
        #pragma unroll
        for (int j = 0; j < 8; j++) cpasync16(base + j * 128u, src + j * 32, 16u);
    };

    // groups: #0={A0,B0} #1={A1,B1} #2={A2}; loop it commits #(it+3)={A(it+3),B(it+2)}
    issueA(0); issueB(0); cp_commit();
    issueA(1); issueB(1); cp_commit();
    issueA(2);            cp_commit();

    for (int it = 0; it < ntiles; ++it) {
        cp_wait1();                 // A(it), BR(it) retired
        __syncthreads();
        if (it >= 2) mbar_wait(ctrl + 8 + 8 * ((it - 2) & 3), ((it - 2) >> 2) & 1);  // BK[it&1] free

        {   // transpose+round BR[it&1] -> BK[it&1]
            uint32_t brb = sbase + 131072u + (it & 1) * 33280u + (uint32_t)tid * 4u;
            uint32_t bkb = sbase + 65536u + (it & 1) * 32768u + (uint32_t)tid * 128u;
            uint32_t swx = (uint32_t)(tid & 7) << 4;
            float fv[32];
            #pragma unroll
            for (int k = 0; k < 32; k++) fv[k] = f2tf_f(lds_f32(brb + (uint32_t)k * 1040u));
            #pragma unroll
            for (int j = 0; j < 8; j++) {
                float4 q = make_float4(fv[4*j], fv[4*j+1], fv[4*j+2], fv[4*j+3]);
                sts128(bkb + (((uint32_t)(j * 16)) ^ swx), q);
            }
        }
        __syncthreads();

        if (warp == 0 && elect_one()) {
            fence_async();
            uint32_t sa = sbase + (it & 3) * 16384u;
            uint32_t sb = sbase + 65536u + (it & 1) * 32768u;
            uint64_t ad = DESCK | ((sa >> 4) & 0x3FFFu);
            uint64_t bd = DESCK | ((sb >> 4) & 0x3FFFu);
            #pragma unroll
            for (int s = 0; s < 4; s++)
                mma_tf32_ss(tmem, ad + 2 * s, bd + 2 * s, IDESC_N256, (it | s) != 0);
            tc_commit(ctrl + 8 + 8 * (it & 3));
        }

        if (it + 3 < ntiles || it + 2 < ntiles) {
            if (it >= 1) mbar_wait(ctrl + 8 + 8 * ((it - 1) & 3), ((it - 1) >> 2) & 1);  // A[(it+3)&3] free
            if (it + 3 < ntiles) issueA(it + 3);
            if (it + 2 < ntiles) issueB(it + 2);
        }
        cp_commit();
    }
    { int p = ntiles - 1; mbar_wait(ctrl + 8 + 8 * (p & 3), (p >> 2) & 1); }
    tc_fence_after();

    {
        const int w4 = warp & 3, half = warp >> 2;
        const int row = m0 + w4 * 32 + lane;
        float* crow = C + (long long)row * ldC + n0;
        #pragma unroll
        for (int i = 0; i < 4; i++) {
            int c0 = half * 128 + i * 32;
            uint32_t r[32];
            ldtm32(r, tmem + c0);
            tc_wait_ld();
            #pragma unroll
            for (int q = 0; q < 8; q++) {
                float4 o;
                float* ov = (float*)&o;
                #pragma unroll
                for (int z = 0; z < 4; z++) {
                    float v = __uint_as_float(r[q * 4 + z]);
                    if (GELU)  v = gelu_tanh(v);
                    if (ROUND) v = f2tf_f(v);
                    ov[z] = v;
                }
                *(float4*)(crow + c0 + q * 4) = o;
            }
        }
    }
    __syncthreads();
    if (warp == 0) tc_dealloc(tmem, 256);
#else
    const int tid = threadIdx.x;
    const int row = m0 + (tid >> 1);
    const int nh  = (tid & 1) * 128;
    const float* arow;
    if (GATHER) {
        int tok = (row < M) ? tokall[e * CAP + row] : -1;
        arow = (tok >= 0) ? (Aall + (long long)tok * ldA) : nullptr;
    } else arow = Aall + (long long)e * sAe + (long long)row * ldA;
    for (int c = 0; c < 4; c++) {
        float acc[32];
        #pragma unroll
        for (int q = 0; q < 32; q++) acc[q] = 0.f;
        int nb = n0 + nh + c * 32;
        for (int k = 0; k < Kdim; k++) {
            float a = arow ? arow[k] : 0.f;
            const float* bk = B + (long long)k * ldB + nb;
            #pragma unroll 8
            for (int q = 0; q < 32; q++) acc[q] += a * bk[q];
        }
        float* crow = C + (long long)row * ldC;
        for (int q = 0; q < 32; q++) {
            float v = acc[q];
            if (GELU) v = gelu_tanh(v);
            crow[nb + q] = v;
        }
    }
#endif
}

__global__ __launch_bounds__(256) void combine_kernel(
    float* __restrict__ out, const float* __restrict__ y,
    const int* __restrict__ pair_slot, const float* __restrict__ pair_w)
{
    int t = blockIdx.x;
    int slot[KTOP]; float w[KTOP];
    #pragma unroll
    for (int k = 0; k < KTOP; k++) {
        slot[k] = pair_slot[t * KTOP + k];
        w[k]    = pair_w[t * KTOP + k];
    }
    int h4 = threadIdx.x;
    float4 acc = *(float4*)(out + (size_t)t * H + h4 * 4);
    #pragma unroll
    for (int k = 0; k < KTOP; k++) {
        float4 v = *(const float4*)(y + (size_t)slot[k] * H + h4 * 4);
        acc.x += w[k] * v.x; acc.y += w[k] * v.y;
        acc.z += w[k] * v.z; acc.w += w[k] * v.w;
    }
    *(float4*)(out + (size_t)t * H + h4 * 4) = acc;
}

extern "C" void kernel_launch(void* const* d_in, const int* in_sizes, int n_in,
                              void* d_out, int out_size)
{
    const float* x   = (const float*)d_in[0];
    const float* rw  = (const float*)d_in[1];
    const float* eb  = (const float*)d_in[2];
    const float* w1  = (const float*)d_in[3];
    const float* w2  = (const float*)d_in[4];
    const float* sw1 = (const float*)d_in[5];
    const float* sw2 = (const float*)d_in[6];
    float* out = (float*)d_out;

    void *pcnt, *ptok, *pps, *ppw, *pmid, *py, *psmid, *pxr, *psw1r, *psw2r;
    cudaGetSymbolAddress(&pcnt,  g_cnt);
    cudaGetSymbolAddress(&ptok,  g_slot_token);
    cudaGetSymbolAddress(&pps,   g_pair_slot);
    cudaGetSymbolAddress(&ppw,   g_pair_w);
    cudaGetSymbolAddress(&pmid,  g_mid);
    cudaGetSymbolAddress(&py,    g_y);
    cudaGetSymbolAddress(&psmid, g_smid);
    cudaGetSymbolAddress(&pxr,   g_xr);
    cudaGetSymbolAddress(&psw1r, g_sw1r);
    cudaGetSymbolAddress(&psw2r, g_sw2r);

    int*   cnt       = (int*)pcnt;
    int*   slot_tok  = (int*)ptok;
    int*   pair_slot = (int*)pps;
    float* pair_w    = (float*)ppw;
    float* mid       = (float*)pmid;
    float* y         = (float*)py;
    float* smid      = (float*)psmid;
    float* xr        = (float*)pxr;
    float* sw1r      = (float*)psw1r;
    float* sw2r      = (float*)psw2r;

    const int SM256 = 4 * (16384 + 256 * 128) + 1024 + 64;
    const int SM128 = 4 * (16384 + 128 * 128) + 1024 + 64;
    const int SMBT  = 197632 + 1024 + 64;

    static cudaStream_t s2 = nullptr;
    static cudaEvent_t evFork, evR, evS;
    if (!s2) {
        cudaStreamCreateWithFlags(&s2, cudaStreamNonBlocking);
        cudaEventCreateWithFlags(&evFork, cudaEventDisableTiming);
        cudaEventCreateWithFlags(&evR,    cudaEventDisableTiming);
        cudaEventCreateWithFlags(&evS,    cudaEventDisableTiming);
        cudaFuncSetAttribute(gemm_bt<true,  true,  true >, cudaFuncAttributeMaxDynamicSharedMemorySize, SMBT);
        cudaFuncSetAttribute(gemm_bt<false, false, false>, cudaFuncAttributeMaxDynamicSharedMemorySize, SMBT);
        cudaFuncSetAttribute(gemm_tc<false, true,  true,  256>, cudaFuncAttributeMaxDynamicSharedMemorySize, SM256);
        cudaFuncSetAttribute(gemm_tc<false, false, false, 128>, cudaFuncAttributeMaxDynamicSharedMemorySize, SM128);
    }

    zero_cnt_kernel<<<1, 64>>>(cnt);
    cudaEventRecord(evFork, 0);
    cudaStreamWaitEvent(s2, evFork, 0);

    prep_kernel<<<SF * H / 4 / 256, 256, 0, s2>>>(sw1, sw1r, sw2, sw2r);

    router2_kernel<<<T / 8, 256>>>(x, rw, eb, cnt, slot_tok, pair_slot, pair_w, xr);
    cudaEventRecord(evR, 0);
    cudaStreamWaitEvent(s2, evR, 0);

    // expert GEMM1: mid = round(gelu(gather(xr) @ w1))  (w1 [H][F] raw, in-kernel transpose)
    gemm_bt<true, true, true><<<dim3(F / 256, CAP / 128, E), 256, SMBT>>>(
        xr, 0LL, H, w1, (long long)H * F, F,
        mid, (long long)CAP * F, F, H, cnt, CAP, slot_tok);
    // expert GEMM2: y = mid @ w2  (w2 [F][H] raw)
    gemm_bt<false, false, false><<<dim3(H / 256, CAP / 128, E), 256, SMBT>>>(
        mid, (long long)CAP * F, F, w2, (long long)F * H, H,
        y, (long long)CAP * H, H, F, cnt, CAP, slot_tok);

    // shared chain on s2
    gemm_tc<false, true, true, 256><<<dim3(SF / 256, T / 128, 1), 256, SM256, s2>>>(
        xr, 0LL, H, sw1r, 0LL, smid, 0LL, SF, H, SF, nullptr, T, nullptr);
    gemm_tc<false, false, false, 128><<<dim3(H / 128, T / 128, 1), 256, SM128, s2>>>(
        smid, 0LL, SF, sw2r, 0LL, out, 0LL, H, SF, H, nullptr, T, nullptr);
    cudaEventRecord(evS, s2);

    cudaStreamWaitEvent(0, evS, 0);
    combine_kernel<<<T, 256>>>(out, y, pair_slot, pair_w);
}

// round 12
// speedup vs baseline: 3.3532x; 1.2271x over previous
#include <cuda_runtime.h>
#include <cuda_fp16.h>
#include <math.h>
#include <stdint.h>

#define E    64
#define KTOP 6
#define H    1024
#define F    512
#define SF   2048
#define T    2048
#define CAP  384

#if !defined(__CUDA_ARCH__) || defined(__CUDA_ARCH_FEAT_SM103_ALL) || \
    defined(__CUDA_ARCH_FEAT_SM100_ALL) || defined(__CUDA_ARCH_FEAT_SM101_ALL) || \
    defined(__CUDA_ARCH_SPECIFIC__)
#define TC_OK 1
#else
#define TC_OK 0
#endif

__device__ int    g_cnt[E];
__device__ int    g_slot_token[E * CAP];
__device__ int    g_pair_slot[T * KTOP];
__device__ float  g_pair_w[T * KTOP];
__device__ __half g_midh[(size_t)E * CAP * F];
__device__ __half g_yh[(size_t)E * CAP * H];
__device__ __half g_smidh[(size_t)T * SF];
__device__ __half g_xrh[(size_t)T * H];
__device__ __half g_sw1h[(size_t)SF * H];
__device__ __half g_sw2h[(size_t)H * SF];

__device__ __forceinline__ float gelu_tanh(float x) {
    float u = 0.7978845608028654f * (x + 0.044715f * x * x * x);
    return 0.5f * x * (1.0f + tanhf(u));
}
__device__ __forceinline__ uint32_t pack_h2(float hi, float lo) {
    uint32_t r;
    asm("cvt.rn.f16x2.f32 %0, %1, %2;" : "=r"(r) : "f"(hi), "f"(lo));
    return r;
}

#if TC_OK
__device__ __forceinline__ uint32_t smem_u32(const void* p) {
    uint32_t a;
    asm("{ .reg .u64 t; cvta.to.shared.u64 t, %1; cvt.u32.u64 %0, t; }" : "=r"(a) : "l"(p));
    return a;
}
__device__ __forceinline__ uint32_t elect_one() {
    uint32_t pred;
    asm volatile("{\n\t.reg .pred p;\n\telect.sync _|p, 0xFFFFFFFF;\n\tselp.b32 %0, 1, 0, p;\n\t}" : "=r"(pred));
    return pred;
}
__device__ __forceinline__ void cpasync16(uint32_t dst, const void* src, uint32_t sz) {
    asm volatile("cp.async.cg.shared.global [%0], [%1], 16, %2;" :: "r"(dst), "l"(src), "r"(sz) : "memory");
}
__device__ __forceinline__ void cp_commit() { asm volatile("cp.async.commit_group;" ::: "memory"); }
__device__ __forceinline__ void cp_wait1()  { asm volatile("cp.async.wait_group 1;" ::: "memory"); }
__device__ __forceinline__ void cp_wait2()  { asm volatile("cp.async.wait_group 2;" ::: "memory"); }
__device__ __forceinline__ void mbar_init(uint32_t mbar, uint32_t cnt) {
    asm volatile("mbarrier.init.shared.b64 [%0], %1;" :: "r"(mbar), "r"(cnt) : "memory");
}
__device__ __forceinline__ void mbar_wait(uint32_t mbar, uint32_t parity) {
    asm volatile(
        "{\n\t.reg .pred P;\nW_%=:\n\t"
        "mbarrier.try_wait.parity.acquire.cta.shared::cta.b64 P, [%0], %1, 0x989680;\n\t"
        "@P bra.uni D_%=;\n\tbra.uni W_%=;\nD_%=:\n\t}"
        :: "r"(mbar), "r"(parity) : "memory");
}
__device__ __forceinline__ void tc_alloc(uint32_t s, uint32_t n) {
    asm volatile("tcgen05.alloc.cta_group::1.sync.aligned.shared::cta.b32 [%0], %1;" :: "r"(s), "r"(n) : "memory");
}
__device__ __forceinline__ void tc_relinquish() {
    asm volatile("tcgen05.relinquish_alloc_permit.cta_group::1.sync.aligned;");
}
__device__ __forceinline__ void tc_dealloc(uint32_t t, uint32_t n) {
    asm volatile("tcgen05.dealloc.cta_group::1.sync.aligned.b32 %0, %1;" :: "r"(t), "r"(n));
}
__device__ __forceinline__ void tc_commit(uint32_t mbar) {
    asm volatile("tcgen05.commit.cta_group::1.mbarrier::arrive::one.shared::cluster.b64 [%0];" :: "r"(mbar) : "memory");
}
__device__ __forceinline__ void fence_async()   { asm volatile("fence.proxy.async.shared::cta;" ::: "memory"); }
__device__ __forceinline__ void tc_fence_after(){ asm volatile("tcgen05.fence::after_thread_sync;" ::: "memory"); }
__device__ __forceinline__ void tc_wait_ld()    { asm volatile("tcgen05.wait::ld.sync.aligned;" ::: "memory"); }
__device__ __forceinline__ void mma_f16_ss(uint32_t d, uint64_t ad, uint64_t bd, uint32_t idesc, uint32_t en) {
    asm volatile(
        "{\n\t.reg .pred p;\n\tsetp.ne.u32 p, %5, 0;\n\t"
        "tcgen05.mma.cta_group::1.kind::f16 [%0], %1, %2, %3, {%4, %4, %4, %4}, p;\n\t}"
        :: "r"(d), "l"(ad), "l"(bd), "r"(idesc), "r"(0u), "r"(en) : "memory");
}
__device__ __forceinline__ void ldtm32(uint32_t* r, uint32_t addr) {
    asm volatile(
        "tcgen05.ld.sync.aligned.32x32b.x32.b32 "
        "{%0, %1, %2, %3, %4, %5, %6, %7, %8, %9, %10, %11, %12, %13, %14, %15, "
        "%16, %17, %18, %19, %20, %21, %22, %23, %24, %25, %26, %27, %28, %29, %30, %31}, [%32];"
        : "=r"(r[0]), "=r"(r[1]), "=r"(r[2]), "=r"(r[3]), "=r"(r[4]), "=r"(r[5]), "=r"(r[6]), "=r"(r[7]),
          "=r"(r[8]), "=r"(r[9]), "=r"(r[10]), "=r"(r[11]), "=r"(r[12]), "=r"(r[13]), "=r"(r[14]), "=r"(r[15]),
          "=r"(r[16]), "=r"(r[17]), "=r"(r[18]), "=r"(r[19]), "=r"(r[20]), "=r"(r[21]), "=r"(r[22]), "=r"(r[23]),
          "=r"(r[24]), "=r"(r[25]), "=r"(r[26]), "=r"(r[27]), "=r"(r[28]), "=r"(r[29]), "=r"(r[30]), "=r"(r[31])
        : "r"(addr));
}
__device__ __forceinline__ float lds_f32(uint32_t a) {
    float v; asm volatile("ld.shared.f32 %0, [%1];" : "=f"(v) : "r"(a)); return v;
}
__device__ __forceinline__ void sts128u(uint32_t a, uint32_t r0, uint32_t r1, uint32_t r2, uint32_t r3) {
    asm volatile("st.shared.v4.b32 [%0], {%1,%2,%3,%4};" :: "r"(a), "r"(r0), "r"(r1), "r"(r2), "r"(r3) : "memory");
}
__device__ __forceinline__ uint32_t sw128(uint32_t b) { return b ^ ((b >> 3) & 0x70); }
#define DESCK      0x4000404000010000ull
#define IDESC_H256 0x8400010u
#define IDESC_H128 0x8200010u
#endif

__global__ void zero_cnt_kernel(int* cnt) {
    if (threadIdx.x < E) cnt[threadIdx.x] = 0;
}

__global__ __launch_bounds__(256) void prep_kernel(
    const float* __restrict__ sw1, __half* __restrict__ sw1h,
    const float* __restrict__ sw2, __half* __restrict__ sw2h)
{
    int i = blockIdx.x * 256 + threadIdx.x;
    float4 a = ((const float4*)sw1)[i];
    ((uint2*)sw1h)[i] = make_uint2(pack_h2(a.y, a.x), pack_h2(a.w, a.z));
    float4 b = ((const float4*)sw2)[i];
    ((uint2*)sw2h)[i] = make_uint2(pack_h2(b.y, b.x), pack_h2(b.w, b.z));
}

__global__ __launch_bounds__(256) void router2_kernel(
    const float* __restrict__ x, const float* __restrict__ rw,
    const float* __restrict__ bias,
    int* __restrict__ cnt, int* __restrict__ slot_token,
    int* __restrict__ pair_slot, float* __restrict__ pair_w,
    __half* __restrict__ xrh)
{
    const int tb = blockIdx.x * 8;
    __shared__ float xs[8][H];
    __shared__ float sc[8][E];
    __shared__ float sb[E];
    const int tid = threadIdx.x;
    const int warp = tid >> 5, lane = tid & 31;

    for (int i = tid; i < 8 * H / 4; i += 256) {
        int row = i >> 8, c4 = i & 255;
        float4 v = ((const float4*)(x + (size_t)(tb + row) * H))[c4];
        ((float4*)xs[row])[c4] = v;
        ((uint2*)(xrh + (size_t)(tb + row) * H))[c4] =
            make_uint2(pack_h2(v.y, v.x), pack_h2(v.w, v.z));
    }
    if (tid < E) sb[tid] = bias[tid];
    __syncthreads();

    for (int q = 0; q < 8; q++) {
        int e = warp * 8 + q;
        const float* wrow = rw + (size_t)e * H;
        float s[8];
        #pragma unroll
        for (int tt = 0; tt < 8; tt++) s[tt] = 0.f;
        for (int i = lane; i < H; i += 32) {
            float wv = wrow[i];
            #pragma unroll
            for (int tt = 0; tt < 8; tt++) s[tt] += xs[tt][i] * wv;
        }
        #pragma unroll
        for (int o = 16; o; o >>= 1)
            #pragma unroll
            for (int tt = 0; tt < 8; tt++) s[tt] += __shfl_xor_sync(0xffffffffu, s[tt], o);
        if (lane == 0) {
            #pragma unroll
            for (int tt = 0; tt < 8; tt++) sc[tt][e] = 1.f / (1.f + expf(-s[tt]));
        }
    }
    __syncthreads();

    if (tid < 8) {
        int t = tb + tid;
        unsigned long long used = 0ull;
        int idx[KTOP]; float tsc[KTOP]; float sum = 0.f;
        #pragma unroll
        for (int k = 0; k < KTOP; k++) {
            float best = -1e30f; int bi = 0;
            for (int e = 0; e < E; e++) {
                if (used & (1ull << e)) continue;
                float v = sc[tid][e] + sb[e];
                if (v > best) { best = v; bi = e; }
            }
            used |= 1ull << bi; idx[k] = bi; tsc[k] = sc[tid][bi]; sum += sc[tid][bi];
        }
        float inv = 1.f / (sum + 1e-20f);
        #pragma unroll
        for (int k = 0; k < KTOP; k++) {
            int e = idx[k];
            int pos = atomicAdd(&cnt[e], 1);
            float w = tsc[k] * inv;
            int slot;
            if (pos < CAP) { slot = e * CAP + pos; slot_token[slot] = t; }
            else           { slot = 0; w = 0.f; }
            pair_slot[t * KTOP + k] = slot;
            pair_w[t * KTOP + k]    = w;
        }
    }
}

// ===== gemm_tc: fp16 A & B (both K-major), K-chunk 64, D fp32 in TMEM =====
template<bool GATHER, bool GELU, bool HOUT, int NTILE>
__global__ __launch_bounds__(256) void gemm_tc(
    const __half* __restrict__ Aall, long long sAe, int ldA,
    const __half* __restrict__ Ball, long long sBe,
    void* __restrict__ Call, long long sCe, int ldC,
    int Kdim, int Ncols,
    const int* __restrict__ cnts, int Mmax,
    const int* __restrict__ tokall)
{
    const int e  = blockIdx.z;
    const int m0 = blockIdx.y * 128;
    const int n0 = blockIdx.x * NTILE;
    int M = Mmax;
    if (cnts) { M = min(cnts[e], Mmax); if (m0 >= M) return; }
    const __half* B = Ball + (long long)e * sBe;

#if TC_OK
    constexpr int ABYTES = 16384;
    constexpr int BBYTES = NTILE * 128;
    constexpr int STAGE  = ABYTES + BBYTES;
    constexpr int NB     = NTILE / 32;
    constexpr uint32_t IDESC = (NTILE == 256) ? IDESC_H256 : IDESC_H128;

    extern __shared__ char smraw_c[];
    const uint32_t sbase = (smem_u32(smraw_c) + 1023u) & ~1023u;
    const uint32_t ctrl  = sbase + 4 * STAGE;
    const int tid = threadIdx.x, warp = tid >> 5, lane = tid & 31;

    if (warp == 0) { tc_alloc(ctrl, 256); tc_relinquish(); }
    if (tid == 0) {
        #pragma unroll
        for (int j = 0; j < 4; j++) mbar_init(ctrl + 8 + 8 * j, 1);
    }
    __syncthreads();
    uint32_t tmem;
    asm volatile("ld.shared.b32 %0, [%1];" : "=r"(tmem) : "r"(ctrl));

    const __half* aptr[4]; uint32_t a_sts[4], a_ok[4];
    #pragma unroll
    for (int j = 0; j < 4; j++) {
        int g = tid + j * 256;
        int m = g >> 3, k8 = (g & 7) * 8;
        a_sts[j] = sw128(m * 128 + k8 * 2);
        if (GATHER) {
            int tok = (m0 + m < M) ? tokall[e * CAP + m0 + m] : -1;
            a_ok[j] = (tok >= 0) ? 16u : 0u;
            aptr[j] = (tok >= 0) ? (Aall + (long long)tok * ldA + k8) : Aall;
        } else {
            a_ok[j] = 16u;
            aptr[j] = Aall + (long long)e * sAe + (long long)(m0 + m) * ldA + k8;
        }
    }
    const __half* bptr[NB]; uint32_t b_sts[NB];
    #pragma unroll
    for (int j = 0; j < NB; j++) {
        int g = tid + j * 256;
        int n = g >> 3, k8 = (g & 7) * 8;
        b_sts[j] = sw128(n * 128 + k8 * 2);
        bptr[j]  = B + (long long)(n0 + n) * Kdim + k8;
    }
    const int ntiles = Kdim >> 6;

    auto issue = [&](int it) {
        uint32_t base = sbase + (it & 3) * STAGE;
        long long ka = (long long)it * 64;
        #pragma unroll
        for (int j = 0; j < 4; j++) cpasync16(base + a_sts[j], aptr[j] + ka, a_ok[j]);
        #pragma unroll
        for (int j = 0; j < NB; j++) cpasync16(base + ABYTES + b_sts[j], bptr[j] + ka, 16u);
    };

    issue(0); cp_commit();
    issue(1); cp_commit();
    issue(2); cp_commit();

    for (int it = 0; it < ntiles; ++it) {
        cp_wait2();
        __syncthreads();
        if (warp == 0 && elect_one()) {
            fence_async();
            uint32_t sa = sbase + (it & 3) * STAGE;
            uint64_t ad = DESCK | ((sa >> 4) & 0x3FFFu);
            uint64_t bd = DESCK | (((sa + ABYTES) >> 4) & 0x3FFFu);
            #pragma unroll
            for (int s = 0; s < 4; s++)
                mma_f16_ss(tmem, ad + 2 * s, bd + 2 * s, IDESC, (it | s) != 0);
            tc_commit(ctrl + 8 + 8 * (it & 3));
        }
        if (it + 3 < ntiles) {
            if (it >= 1) mbar_wait(ctrl + 8 + 8 * ((it - 1) & 3), ((it - 1) >> 2) & 1);
            issue(it + 3);
        }
        cp_commit();
    }
    { int p = ntiles - 1; mbar_wait(ctrl + 8 + 8 * (p & 3), (p >> 2) & 1); }
    tc_fence_after();

    {
        const int w4 = warp & 3, half = warp >> 2;
        const int row = m0 + w4 * 32 + lane;
        #pragma unroll
        for (int i = 0; i < NTILE / 64; i++) {
            int c0 = half * (NTILE / 2) + i * 32;
            uint32_t r[32];
            ldtm32(r, tmem + c0);
            tc_wait_ld();
            float fv[32];
            #pragma unroll
            for (int q = 0; q < 32; q++) {
                float v = __uint_as_float(r[q]);
                fv[q] = GELU ? gelu_tanh(v) : v;
            }
            if (HOUT) {
                __half* crow = (__half*)Call + (long long)e * sCe + (long long)row * ldC + n0;
                #pragma unroll
                for (int q = 0; q < 4; q++) {
                    uint4 o = make_uint4(
                        pack_h2(fv[q*8+1], fv[q*8+0]), pack_h2(fv[q*8+3], fv[q*8+2]),
                        pack_h2(fv[q*8+5], fv[q*8+4]), pack_h2(fv[q*8+7], fv[q*8+6]));
                    *(uint4*)(crow + c0 + q * 8) = o;
                }
            } else {
                float* crow = (float*)Call + (long long)e * sCe + (long long)row * ldC + n0;
                #pragma unroll
                for (int q = 0; q < 8; q++)
                    *(float4*)(crow + c0 + q * 4) =
                        make_float4(fv[q*4], fv[q*4+1], fv[q*4+2], fv[q*4+3]);
            }
        }
    }
    __syncthreads();
    if (warp == 0) tc_dealloc(tmem, 256);
#else
    const int tid = threadIdx.x;
    const int row = m0 + (tid >> 1);
    const int nh  = (tid & 1) * (NTILE / 2);
    const __half* arow;
    if (GATHER) {
        int tok = (row < M) ? tokall[e * CAP + row] : -1;
        arow = (tok >= 0) ? (Aall + (long long)tok * ldA) : nullptr;
    } else arow = Aall + (long long)e * sAe + (long long)row * ldA;
    for (int c = 0; c < NTILE / 64; c++) {
        float acc[32];
        #pragma unroll
        for (int q = 0; q < 32; q++) acc[q] = 0.f;
        int nb = n0 + nh + c * 32;
        for (int k = 0; k < Kdim; k++) {
            float a = arow ? __half2float(arow[k]) : 0.f;
            for (int q = 0; q < 32; q++)
                acc[q] += a * __half2float(B[(long long)(nb + q) * Kdim + k]);
        }
        for (int q = 0; q < 32; q++) {
            float v = acc[q];
            if (GELU) v = gelu_tanh(v);
            if (HOUT) ((__half*)Call)[(long long)e * sCe + (long long)row * ldC + nb + q] = __float2half(v);
            else      ((float*)Call)[(long long)e * sCe + (long long)row * ldC + nb + q] = v;
        }
    }
#endif
}

// ===== gemm_bt: fp16 A (K-major), B fp32 [K][N] transposed+converted in SMEM =====
template<bool GATHER, bool GELU, bool HOUT>
__global__ __launch_bounds__(256) void gemm_bt(
    const __half* __restrict__ Aall, long long sAe, int ldA,
    const float* __restrict__ Ball, long long sBe, int ldB,
    void* __restrict__ Call, long long sCe, int ldC,
    int Kdim,
    const int* __restrict__ cnts, int Mmax,
    const int* __restrict__ tokall)
{
    const int e  = blockIdx.z;
    const int m0 = blockIdx.y * 128;
    const int n0 = blockIdx.x * 256;
    int M = Mmax;
    if (cnts) { M = min(cnts[e], Mmax); if (m0 >= M) return; }
    const float* B = Ball + (long long)e * sBe;

#if TC_OK
    // A: 4x16KB @0 ; BK(fp16): 2x32KB @65536 ; BR(fp32 32k x 256n): 2x33280 @131072 ; ctrl @197632
    extern __shared__ char smraw_b[];
    const uint32_t sbase = (smem_u32(smraw_b) + 1023u) & ~1023u;
    const uint32_t ctrl = sbase + 197632u;
    const int tid = threadIdx.x, warp = tid >> 5, lane = tid & 31;

    if (warp == 0) { tc_alloc(ctrl, 256); tc_relinquish(); }
    if (tid == 0) {
        #pragma unroll
        for (int j = 0; j < 4; j++) mbar_init(ctrl + 8 + 8 * j, 1);
    }
    __syncthreads();
    uint32_t tmem;
    asm volatile("ld.shared.b32 %0, [%1];" : "=r"(tmem) : "r"(ctrl));

    const __half* aptr[4]; uint32_t a_sts[4], a_ok[4];
    #pragma unroll
    for (int j = 0; j < 4; j++) {
        int g = tid + j * 256;
        int m = g >> 3, k8 = (g & 7) * 8;
        a_sts[j] = sw128(m * 128 + k8 * 2);
        if (GATHER) {
            int tok = (m0 + m < M) ? tokall[e * CAP + m0 + m] : -1;
            a_ok[j] = (tok >= 0) ? 16u : 0u;
            aptr[j] = (tok >= 0) ? (Aall + (long long)tok * ldA + k8) : Aall;
        } else {
            a_ok[j] = 16u;
            aptr[j] = Aall + (long long)e * sAe + (long long)(m0 + m) * ldA + k8;
        }
    }

    const int nc  = Kdim >> 6;
    const int nhc = nc * 2;

    auto issueA = [&](int c) {
        uint32_t base = sbase + (c & 3) * 16384u;
        long long ka = (long long)c * 64;
        #pragma unroll
        for (int j = 0; j < 4; j++) cpasync16(base + a_sts[j], aptr[j] + ka, a_ok[j]);
    };
    auto issueBR = [&](int hc) {
        uint32_t base = sbase + 131072u + (hc & 1) * 33280u;
        const float* src0 = B + (long long)hc * 32 * ldB + n0;
        #pragma unroll
        for (int j = 0; j < 8; j++) {
            int g = tid + j * 256;
            int r = g >> 6, gc = g & 63;
            cpasync16(base + (uint32_t)r * 1040u + (uint32_t)gc * 16u,
                      src0 + (long long)r * ldB + gc * 4, 16u);
        }
    };

    // groups: g0={BR0,A0,A1}, g1={BR1}; loop hc commits {BR(hc+2)[, A(c+2) on even hc]}
    issueBR(0); issueA(0); issueA(1); cp_commit();
    issueBR(1);                       cp_commit();

    for (int hc = 0; hc < nhc; ++hc) {
        const int c = hc >> 1;
        cp_wait1();
        __syncthreads();
        if ((hc & 1) == 0 && c >= 2)
            mbar_wait(ctrl + 8 + 8 * ((c - 2) & 3), ((c - 2) >> 2) & 1);   // BK[c&1] + A buf free

        {   // transpose + cvt: BR[hc&1] (32k x 256n fp32) -> BK[c&1], k-half (hc&1)
            // FIX: k-half offset must be INSIDE the swizzle XOR.
            uint32_t brb = sbase + 131072u + (hc & 1) * 33280u + (uint32_t)tid * 4u;
            uint32_t bkrow = sbase + 65536u + (c & 1) * 32768u + (uint32_t)tid * 128u;
            uint32_t swx = (uint32_t)(tid & 7) << 4;
            uint32_t hoff = (uint32_t)(hc & 1) * 64u;
            float v[32];
            #pragma unroll
            for (int r = 0; r < 32; r++) v[r] = lds_f32(brb + (uint32_t)r * 1040u);
            uint32_t h2[16];
            #pragma unroll
            for (int j = 0; j < 16; j++) h2[j] = pack_h2(v[2*j+1], v[2*j]);
            #pragma unroll
            for (int j = 0; j < 4; j++) {
                uint32_t off = (hoff + (uint32_t)(j * 16)) ^ swx;
                sts128u(bkrow + off, h2[4*j], h2[4*j+1], h2[4*j+2], h2[4*j+3]);
            }
        }
        __syncthreads();

        if ((hc & 1) == 1 && warp == 0 && elect_one()) {
            fence_async();
            uint32_t sa = sbase + (c & 3) * 16384u;
            uint32_t sb = sbase + 65536u + (c & 1) * 32768u;
            uint64_t ad = DESCK | ((sa >> 4) & 0x3FFFu);
            uint64_t bd = DESCK | ((sb >> 4) & 0x3FFFu);
            #pragma unroll
            for (int s = 0; s < 4; s++)
                mma_f16_ss(tmem, ad + 2 * s, bd + 2 * s, IDESC_H256, (c | s) != 0);
            tc_commit(ctrl + 8 + 8 * (c & 3));
        }

        if (hc + 2 < nhc) issueBR(hc + 2);
        if ((hc & 1) == 0 && c + 2 < nc) issueA(c + 2);
        cp_commit();
    }
    { int p = nc - 1; mbar_wait(ctrl + 8 + 8 * (p & 3), (p >> 2) & 1); }
    tc_fence_after();

    {
        const int w4 = warp & 3, half = warp >> 2;
        const int row = m0 + w4 * 32 + lane;
        #pragma unroll
        for (int i = 0; i < 4; i++) {
            int c0 = half * 128 + i * 32;
            uint32_t r[32];
            ldtm32(r, tmem + c0);
            tc_wait_ld();
            float fv[32];
            #pragma unroll
            for (int q = 0; q < 32; q++) {
                float v = __uint_as_float(r[q]);
                fv[q] = GELU ? gelu_tanh(v) : v;
            }
            if (HOUT) {
                __half* crow = (__half*)Call + (long long)e * sCe + (long long)row * ldC + n0;
                #pragma unroll
                for (int q = 0; q < 4; q++) {
                    uint4 o = make_uint4(
                        pack_h2(fv[q*8+1], fv[q*8+0]), pack_h2(fv[q*8+3], fv[q*8+2]),
                        pack_h2(fv[q*8+5], fv[q*8+4]), pack_h2(fv[q*8+7], fv[q*8+6]));
                    *(uint4*)(crow + c0 + q * 8) = o;
                }
            } else {
                float* crow = (float*)Call + (long long)e * sCe + (long long)row * ldC + n0;
                #pragma unroll
                for (int q = 0; q < 8; q++)
                    *(float4*)(crow + c0 + q * 4) =
                        make_float4(fv[q*4], fv[q*4+1], fv[q*4+2], fv[q*4+3]);
            }
        }
    }
    __syncthreads();
    if (warp == 0) tc_dealloc(tmem, 256);
#else
    const int tid = threadIdx.x;
    const int row = m0 + (tid >> 1);
    const int nh  = (tid & 1) * 128;
    const __half* arow;
    if (GATHER) {
        int tok = (row < M) ? tokall[e * CAP + row] : -1;
        arow = (tok >= 0) ? (Aall + (long long)tok * ldA) : nullptr;
    } else arow = Aall + (long long)e * sAe + (long long)row * ldA;
    for (int c = 0; c < 4; c++) {
        float acc[32];
        #pragma unroll
        for (int q = 0; q < 32; q++) acc[q] = 0.f;
        int nb = n0 + nh + c * 32;
        for (int k = 0; k < Kdim; k++) {
            float a = arow ? __half2float(arow[k]) : 0.f;
            const float* bk = B + (long long)k * ldB + nb;
            for (int q = 0; q < 32; q++) acc[q] += a * (float)__float2half(bk[q]);
        }
        for (int q = 0; q < 32; q++) {
            float v = acc[q];
            if (GELU) v = gelu_tanh(v);
            if (HOUT) ((__half*)Call)[(long long)e * sCe + (long long)row * ldC + nb + q] = __float2half(v);
            else      ((float*)Call)[(long long)e * sCe + (long long)row * ldC + nb + q] = v;
        }
    }
#endif
}

__global__ __launch_bounds__(256) void combine_kernel(
    float* __restrict__ out, const __half* __restrict__ y,
    const int* __restrict__ pair_slot, const float* __restrict__ pair_w)
{
    int t = blockIdx.x;
    int slot[KTOP]; float w[KTOP];
    #pragma unroll
    for (int k = 0; k < KTOP; k++) {
        slot[k] = pair_slot[t * KTOP + k];
        w[k]    = pair_w[t * KTOP + k];
    }
    int h4 = threadIdx.x;
    float4 acc = *(float4*)(out + (size_t)t * H + h4 * 4);
    #pragma unroll
    for (int k = 0; k < KTOP; k++) {
        uint2 p = *(const uint2*)(y + (size_t)slot[k] * H + h4 * 4);
        __half2 a = *(__half2*)&p.x, b = *(__half2*)&p.y;
        acc.x += w[k] * __low2float(a);  acc.y += w[k] * __high2float(a);
        acc.z += w[k] * __low2float(b);  acc.w += w[k] * __high2float(b);
    }
    *(float4*)(out + (size_t)t * H + h4 * 4) = acc;
}

extern "C" void kernel_launch(void* const* d_in, const int* in_sizes, int n_in,
                              void* d_out, int out_size)
{
    const float* x   = (const float*)d_in[0];
    const float* rw  = (const float*)d_in[1];
    const float* eb  = (const float*)d_in[2];
    const float* w1  = (const float*)d_in[3];
    const float* w2  = (const float*)d_in[4];
    const float* sw1 = (const float*)d_in[5];
    const float* sw2 = (const float*)d_in[6];
    float* out = (float*)d_out;

    void *pcnt, *ptok, *pps, *ppw, *pmid, *py, *psmid, *pxr, *ps1, *ps2;
    cudaGetSymbolAddress(&pcnt,  g_cnt);
    cudaGetSymbolAddress(&ptok,  g_slot_token);
    cudaGetSymbolAddress(&pps,   g_pair_slot);
    cudaGetSymbolAddress(&ppw,   g_pair_w);
    cudaGetSymbolAddress(&pmid,  g_midh);
    cudaGetSymbolAddress(&py,    g_yh);
    cudaGetSymbolAddress(&psmid, g_smidh);
    cudaGetSymbolAddress(&pxr,   g_xrh);
    cudaGetSymbolAddress(&ps1,   g_sw1h);
    cudaGetSymbolAddress(&ps2,   g_sw2h);

    int*    cnt       = (int*)pcnt;
    int*    slot_tok  = (int*)ptok;
    int*    pair_slot = (int*)pps;
    float*  pair_w    = (float*)ppw;
    __half* midh      = (__half*)pmid;
    __half* yh        = (__half*)py;
    __half* smidh     = (__half*)psmid;
    __half* xrh       = (__half*)pxr;
    __half* sw1h      = (__half*)ps1;
    __half* sw2h      = (__half*)ps2;

    const int SM256 = 4 * (16384 + 256 * 128) + 1024 + 64;
    const int SM128 = 4 * (16384 + 128 * 128) + 1024 + 64;
    const int SMBT  = 197632 + 1024 + 64;

    static cudaStream_t s2 = nullptr;
    static cudaEvent_t evFork, evR, evS;
    if (!s2) {
        cudaStreamCreateWithFlags(&s2, cudaStreamNonBlocking);
        cudaEventCreateWithFlags(&evFork, cudaEventDisableTiming);
        cudaEventCreateWithFlags(&evR,    cudaEventDisableTiming);
        cudaEventCreateWithFlags(&evS,    cudaEventDisableTiming);
        cudaFuncSetAttribute(gemm_bt<true,  true,  true>, cudaFuncAttributeMaxDynamicSharedMemorySize, SMBT);
        cudaFuncSetAttribute(gemm_bt<false, false, true>, cudaFuncAttributeMaxDynamicSharedMemorySize, SMBT);
        cudaFuncSetAttribute(gemm_tc<false, true,  true,  256>, cudaFuncAttributeMaxDynamicSharedMemorySize, SM256);
        cudaFuncSetAttribute(gemm_tc<false, false, false, 128>, cudaFuncAttributeMaxDynamicSharedMemorySize, SM128);
    }

    zero_cnt_kernel<<<1, 64>>>(cnt);
    cudaEventRecord(evFork, 0);
    cudaStreamWaitEvent(s2, evFork, 0);

    prep_kernel<<<SF * H / 4 / 256, 256, 0, s2>>>(sw1, sw1h, sw2, sw2h);

    router2_kernel<<<T / 8, 256>>>(x, rw, eb, cnt, slot_tok, pair_slot, pair_w, xrh);
    cudaEventRecord(evR, 0);
    cudaStreamWaitEvent(s2, evR, 0);

    gemm_bt<true, true, true><<<dim3(F / 256, CAP / 128, E), 256, SMBT>>>(
        xrh, 0LL, H, w1, (long long)H * F, F,
        midh, (long long)CAP * F, F, H, cnt, CAP, slot_tok);
    gemm_bt<false, false, true><<<dim3(H / 256, CAP / 128, E), 256, SMBT>>>(
        midh, (long long)CAP * F, F, w2, (long long)F * H, H,
        yh, (long long)CAP * H, H, F, cnt, CAP, slot_tok);

    gemm_tc<false, true, true, 256><<<dim3(SF / 256, T / 128, 1), 256, SM256, s2>>>(
        xrh, 0LL, H, sw1h, 0LL, smidh, 0LL, SF, H, SF, nullptr, T, nullptr);
    gemm_tc<false, false, false, 128><<<dim3(H / 128, T / 128, 1), 256, SM128, s2>>>(
        smidh, 0LL, SF, sw2h, 0LL, out, 0LL, H, SF, H, nullptr, T, nullptr);
    cudaEventRecord(evS, s2);

    cudaStreamWaitEvent(0, evS, 0);
    combine_kernel<<<T, 256>>>(out, yh, pair_slot, pair_w);
}

// round 13
// speedup vs baseline: 3.7172x; 1.1085x over previous
#include <cuda_runtime.h>
#include <cuda_fp16.h>
#include <math.h>
#include <stdint.h>

#define E    64
#define KTOP 6
#define H    1024
#define F    512
#define SF   2048
#define T    2048
#define CAP  384

#if !defined(__CUDA_ARCH__) || defined(__CUDA_ARCH_FEAT_SM103_ALL) || \
    defined(__CUDA_ARCH_FEAT_SM100_ALL) || defined(__CUDA_ARCH_FEAT_SM101_ALL) || \
    defined(__CUDA_ARCH_SPECIFIC__)
#define TC_OK 1
#else
#define TC_OK 0
#endif

__device__ int    g_cnt[E];
__device__ int    g_slot_token[E * CAP];
__device__ int    g_pair_slot[T * KTOP];
__device__ float  g_pair_w[T * KTOP];
__device__ __half g_midh[(size_t)E * CAP * F];
__device__ __half g_yh[(size_t)E * CAP * H];
__device__ __half g_smidh[(size_t)T * SF];
__device__ __half g_xrh[(size_t)T * H];
__device__ __half g_sw1h[(size_t)SF * H];
__device__ __half g_sw2h[(size_t)H * SF];
__device__ __half g_w1th[(size_t)E * F * H];   // w1 -> [E][F][H] fp16 (K-major)
__device__ __half g_w2th[(size_t)E * H * F];   // w2 -> [E][H][F] fp16 (K-major)

__device__ __forceinline__ float gelu_tanh(float x) {
    float u = 0.7978845608028654f * (x + 0.044715f * x * x * x);
    return 0.5f * x * (1.0f + tanhf(u));
}
__device__ __forceinline__ uint32_t pack_h2(float hi, float lo) {
    uint32_t r;
    asm("cvt.rn.f16x2.f32 %0, %1, %2;" : "=r"(r) : "f"(hi), "f"(lo));
    return r;
}

#if TC_OK
__device__ __forceinline__ uint32_t smem_u32(const void* p) {
    uint32_t a;
    asm("{ .reg .u64 t; cvta.to.shared.u64 t, %1; cvt.u32.u64 %0, t; }" : "=r"(a) : "l"(p));
    return a;
}
__device__ __forceinline__ uint32_t elect_one() {
    uint32_t pred;
    asm volatile("{\n\t.reg .pred p;\n\telect.sync _|p, 0xFFFFFFFF;\n\tselp.b32 %0, 1, 0, p;\n\t}" : "=r"(pred));
    return pred;
}
__device__ __forceinline__ void cpasync16(uint32_t dst, const void* src, uint32_t sz) {
    asm volatile("cp.async.cg.shared.global [%0], [%1], 16, %2;" :: "r"(dst), "l"(src), "r"(sz) : "memory");
}
__device__ __forceinline__ void cp_commit() { asm volatile("cp.async.commit_group;" ::: "memory"); }
__device__ __forceinline__ void cp_wait2()  { asm volatile("cp.async.wait_group 2;" ::: "memory"); }
__device__ __forceinline__ void mbar_init(uint32_t mbar, uint32_t cnt) {
    asm volatile("mbarrier.init.shared.b64 [%0], %1;" :: "r"(mbar), "r"(cnt) : "memory");
}
__device__ __forceinline__ void mbar_wait(uint32_t mbar, uint32_t parity) {
    asm volatile(
        "{\n\t.reg .pred P;\nW_%=:\n\t"
        "mbarrier.try_wait.parity.acquire.cta.shared::cta.b64 P, [%0], %1, 0x989680;\n\t"
        "@P bra.uni D_%=;\n\tbra.uni W_%=;\nD_%=:\n\t}"
        :: "r"(mbar), "r"(parity) : "memory");
}
__device__ __forceinline__ void tc_alloc(uint32_t s, uint32_t n) {
    asm volatile("tcgen05.alloc.cta_group::1.sync.aligned.shared::cta.b32 [%0], %1;" :: "r"(s), "r"(n) : "memory");
}
__device__ __forceinline__ void tc_relinquish() {
    asm volatile("tcgen05.relinquish_alloc_permit.cta_group::1.sync.aligned;");
}
__device__ __forceinline__ void tc_dealloc(uint32_t t, uint32_t n) {
    asm volatile("tcgen05.dealloc.cta_group::1.sync.aligned.b32 %0, %1;" :: "r"(t), "r"(n));
}
__device__ __forceinline__ void tc_commit(uint32_t mbar) {
    asm volatile("tcgen05.commit.cta_group::1.mbarrier::arrive::one.shared::cluster.b64 [%0];" :: "r"(mbar) : "memory");
}
__device__ __forceinline__ void fence_async()   { asm volatile("fence.proxy.async.shared::cta;" ::: "memory"); }
__device__ __forceinline__ void tc_fence_after(){ asm volatile("tcgen05.fence::after_thread_sync;" ::: "memory"); }
__device__ __forceinline__ void tc_wait_ld()    { asm volatile("tcgen05.wait::ld.sync.aligned;" ::: "memory"); }
__device__ __forceinline__ void mma_f16_ss(uint32_t d, uint64_t ad, uint64_t bd, uint32_t idesc, uint32_t en) {
    asm volatile(
        "{\n\t.reg .pred p;\n\tsetp.ne.u32 p, %5, 0;\n\t"
        "tcgen05.mma.cta_group::1.kind::f16 [%0], %1, %2, %3, {%4, %4, %4, %4}, p;\n\t}"
        :: "r"(d), "l"(ad), "l"(bd), "r"(idesc), "r"(0u), "r"(en) : "memory");
}
__device__ __forceinline__ void ldtm32(uint32_t* r, uint32_t addr) {
    asm volatile(
        "tcgen05.ld.sync.aligned.32x32b.x32.b32 "
        "{%0, %1, %2, %3, %4, %5, %6, %7, %8, %9, %10, %11, %12, %13, %14, %15, "
        "%16, %17, %18, %19, %20, %21, %22, %23, %24, %25, %26, %27, %28, %29, %30, %31}, [%32];"
        : "=r"(r[0]), "=r"(r[1]), "=r"(r[2]), "=r"(r[3]), "=r"(r[4]), "=r"(r[5]), "=r"(r[6]), "=r"(r[7]),
          "=r"(r[8]), "=r"(r[9]), "=r"(r[10]), "=r"(r[11]), "=r"(r[12]), "=r"(r[13]), "=r"(r[14]), "=r"(r[15]),
          "=r"(r[16]), "=r"(r[17]), "=r"(r[18]), "=r"(r[19]), "=r"(r[20]), "=r"(r[21]), "=r"(r[22]), "=r"(r[23]),
          "=r"(r[24]), "=r"(r[25]), "=r"(r[26]), "=r"(r[27]), "=r"(r[28]), "=r"(r[29]), "=r"(r[30]), "=r"(r[31])
        : "r"(addr));
}
__device__ __forceinline__ uint32_t sw128(uint32_t b) { return b ^ ((b >> 3) & 0x70); }
#define DESCK      0x4000404000010000ull
#define IDESC_H256 0x8400010u
#define IDESC_H128 0x8200010u
#endif

__global__ void zero_cnt_kernel(int* cnt) {
    if (threadIdx.x < E) cnt[threadIdx.x] = 0;
}

// transpose + cvt: src fp32 [E][R][C] -> dst fp16 [E][C][R]
__global__ __launch_bounds__(256) void tcvt_kernel(
    const float* __restrict__ src, __half* __restrict__ dst, int R, int Cc)
{
    __shared__ float tile[32][133];
    int e = blockIdx.z;
    const float* S = src + (size_t)e * R * Cc;
    __half*      D = dst + (size_t)e * R * Cc;
    int r0 = blockIdx.y * 32, c0 = blockIdx.x * 128;
    int tx = threadIdx.x & 31, ty = threadIdx.x >> 5;
    #pragma unroll
    for (int i = 0; i < 4; i++) {
        int r = ty + 8 * i;
        float4 v = *(const float4*)(S + (size_t)(r0 + r) * Cc + c0 + tx * 4);
        tile[r][tx * 4 + 0] = v.x; tile[r][tx * 4 + 1] = v.y;
        tile[r][tx * 4 + 2] = v.z; tile[r][tx * 4 + 3] = v.w;
    }
    __syncthreads();
    int rx = threadIdx.x & 7, cy = threadIdx.x >> 3;
    #pragma unroll
    for (int i = 0; i < 4; i++) {
        int c = cy + 32 * i;
        uint2 o = make_uint2(
            pack_h2(tile[rx * 4 + 1][c], tile[rx * 4 + 0][c]),
            pack_h2(tile[rx * 4 + 3][c], tile[rx * 4 + 2][c]));
        *(uint2*)(D + (size_t)(c0 + c) * R + r0 + rx * 4) = o;
    }
}

__global__ __launch_bounds__(256) void prep_kernel(
    const float* __restrict__ sw1, __half* __restrict__ sw1h,
    const float* __restrict__ sw2, __half* __restrict__ sw2h)
{
    int i = blockIdx.x * 256 + threadIdx.x;
    float4 a = ((const float4*)sw1)[i];
    ((uint2*)sw1h)[i] = make_uint2(pack_h2(a.y, a.x), pack_h2(a.w, a.z));
    float4 b = ((const float4*)sw2)[i];
    ((uint2*)sw2h)[i] = make_uint2(pack_h2(b.y, b.x), pack_h2(b.w, b.z));
}

__global__ __launch_bounds__(256) void router2_kernel(
    const float* __restrict__ x, const float* __restrict__ rw,
    const float* __restrict__ bias,
    int* __restrict__ cnt, int* __restrict__ slot_token,
    int* __restrict__ pair_slot, float* __restrict__ pair_w,
    __half* __restrict__ xrh)
{
    const int tb = blockIdx.x * 8;
    __shared__ float xs[8][H];
    __shared__ float sc[8][E];
    __shared__ float sb[E];
    const int tid = threadIdx.x;
    const int warp = tid >> 5, lane = tid & 31;

    for (int i = tid; i < 8 * H / 4; i += 256) {
        int row = i >> 8, c4 = i & 255;
        float4 v = ((const float4*)(x + (size_t)(tb + row) * H))[c4];
        ((float4*)xs[row])[c4] = v;
        ((uint2*)(xrh + (size_t)(tb + row) * H))[c4] =
            make_uint2(pack_h2(v.y, v.x), pack_h2(v.w, v.z));
    }
    if (tid < E) sb[tid] = bias[tid];
    __syncthreads();

    for (int q = 0; q < 8; q++) {
        int e = warp * 8 + q;
        const float* wrow = rw + (size_t)e * H;
        float s[8];
        #pragma unroll
        for (int tt = 0; tt < 8; tt++) s[tt] = 0.f;
        for (int i = lane; i < H; i += 32) {
            float wv = wrow[i];
            #pragma unroll
            for (int tt = 0; tt < 8; tt++) s[tt] += xs[tt][i] * wv;
        }
        #pragma unroll
        for (int o = 16; o; o >>= 1)
            #pragma unroll
            for (int tt = 0; tt < 8; tt++) s[tt] += __shfl_xor_sync(0xffffffffu, s[tt], o);
        if (lane == 0) {
            #pragma unroll
            for (int tt = 0; tt < 8; tt++) sc[tt][e] = 1.f / (1.f + expf(-s[tt]));
        }
    }
    __syncthreads();

    if (tid < 8) {
        int t = tb + tid;
        unsigned long long used = 0ull;
        int idx[KTOP]; float tsc[KTOP]; float sum = 0.f;
        #pragma unroll
        for (int k = 0; k < KTOP; k++) {
            float best = -1e30f; int bi = 0;
            for (int e = 0; e < E; e++) {
                if (used & (1ull << e)) continue;
                float v = sc[tid][e] + sb[e];
                if (v > best) { best = v; bi = e; }
            }
            used |= 1ull << bi; idx[k] = bi; tsc[k] = sc[tid][bi]; sum += sc[tid][bi];
        }
        float inv = 1.f / (sum + 1e-20f);
        #pragma unroll
        for (int k = 0; k < KTOP; k++) {
            int e = idx[k];
            int pos = atomicAdd(&cnt[e], 1);
            float w = tsc[k] * inv;
            int slot;
            if (pos < CAP) { slot = e * CAP + pos; slot_token[slot] = t; }
            else           { slot = 0; w = 0.f; }
            pair_slot[t * KTOP + k] = slot;
            pair_w[t * KTOP + k]    = w;
        }
    }
}

// ===== gemm_tc: fp16 A & B (both K-major), K-chunk 64, D fp32 in TMEM =====
template<bool GATHER, bool GELU, bool HOUT, int NTILE>
__global__ __launch_bounds__(256) void gemm_tc(
    const __half* __restrict__ Aall, long long sAe, int ldA,
    const __half* __restrict__ Ball, long long sBe,
    void* __restrict__ Call, long long sCe, int ldC,
    int Kdim, int Ncols,
    const int* __restrict__ cnts, int Mmax,
    const int* __restrict__ tokall)
{
    const int e  = blockIdx.z;
    const int m0 = blockIdx.y * 128;
    const int n0 = blockIdx.x * NTILE;
    int M = Mmax;
    if (cnts) { M = min(cnts[e], Mmax); if (m0 >= M) return; }
    const __half* B = Ball + (long long)e * sBe;

#if TC_OK
    constexpr int ABYTES = 16384;
    constexpr int BBYTES = NTILE * 128;
    constexpr int STAGE  = ABYTES + BBYTES;
    constexpr int NB     = NTILE / 32;
    constexpr uint32_t IDESC = (NTILE == 256) ? IDESC_H256 : IDESC_H128;

    extern __shared__ char smraw_c[];
    const uint32_t sbase = (smem_u32(smraw_c) + 1023u) & ~1023u;
    const uint32_t ctrl  = sbase + 4 * STAGE;
    const int tid = threadIdx.x, warp = tid >> 5, lane = tid & 31;

    if (warp == 0) { tc_alloc(ctrl, 256); tc_relinquish(); }
    if (tid == 0) {
        #pragma unroll
        for (int j = 0; j < 4; j++) mbar_init(ctrl + 8 + 8 * j, 1);
    }
    __syncthreads();
    uint32_t tmem;
    asm volatile("ld.shared.b32 %0, [%1];" : "=r"(tmem) : "r"(ctrl));

    const __half* aptr[4]; uint32_t a_sts[4], a_ok[4];
    #pragma unroll
    for (int j = 0; j < 4; j++) {
        int g = tid + j * 256;
        int m = g >> 3, k8 = (g & 7) * 8;
        a_sts[j] = sw128(m * 128 + k8 * 2);
        if (GATHER) {
            int tok = (m0 + m < M) ? tokall[e * CAP + m0 + m] : -1;
            a_ok[j] = (tok >= 0) ? 16u : 0u;
            aptr[j] = (tok >= 0) ? (Aall + (long long)tok * ldA + k8) : Aall;
        } else {
            a_ok[j] = 16u;
            aptr[j] = Aall + (long long)e * sAe + (long long)(m0 + m) * ldA + k8;
        }
    }
    const __half* bptr[NB]; uint32_t b_sts[NB];
    #pragma unroll
    for (int j = 0; j < NB; j++) {
        int g = tid + j * 256;
        int n = g >> 3, k8 = (g & 7) * 8;
        b_sts[j] = sw128(n * 128 + k8 * 2);
        bptr[j]  = B + (long long)(n0 + n) * Kdim + k8;
    }
    const int ntiles = Kdim >> 6;

    auto issue = [&](int it) {
        uint32_t base = sbase + (it & 3) * STAGE;
        long long ka = (long long)it * 64;
        #pragma unroll
        for (int j = 0; j < 4; j++) cpasync16(base + a_sts[j], aptr[j] + ka, a_ok[j]);
        #pragma unroll
        for (int j = 0; j < NB; j++) cpasync16(base + ABYTES + b_sts[j], bptr[j] + ka, 16u);
    };

    issue(0); cp_commit();
    issue(1); cp_commit();
    issue(2); cp_commit();

    for (int it = 0; it < ntiles; ++it) {
        cp_wait2();
        __syncthreads();
        if (warp == 0 && elect_one()) {
            fence_async();
            uint32_t sa = sbase + (it & 3) * STAGE;
            uint64_t ad = DESCK | ((sa >> 4) & 0x3FFFu);
            uint64_t bd = DESCK | (((sa + ABYTES) >> 4) & 0x3FFFu);
            #pragma unroll
            for (int s = 0; s < 4; s++)
                mma_f16_ss(tmem, ad + 2 * s, bd + 2 * s, IDESC, (it | s) != 0);
            tc_commit(ctrl + 8 + 8 * (it & 3));
        }
        if (it + 3 < ntiles) {
            if (it >= 1) mbar_wait(ctrl + 8 + 8 * ((it - 1) & 3), ((it - 1) >> 2) & 1);
            issue(it + 3);
        }
        cp_commit();
    }
    { int p = ntiles - 1; mbar_wait(ctrl + 8 + 8 * (p & 3), (p >> 2) & 1); }
    tc_fence_after();

    {
        const int w4 = warp & 3, half = warp >> 2;
        const int row = m0 + w4 * 32 + lane;
        #pragma unroll
        for (int i = 0; i < NTILE / 64; i++) {
            int c0 = half * (NTILE / 2) + i * 32;
            uint32_t r[32];
            ldtm32(r, tmem + c0);
            tc_wait_ld();
            float fv[32];
            #pragma unroll
            for (int q = 0; q < 32; q++) {
                float v = __uint_as_float(r[q]);
                fv[q] = GELU ? gelu_tanh(v) : v;
            }
            if (HOUT) {
                __half* crow = (__half*)Call + (long long)e * sCe + (long long)row * ldC + n0;
                #pragma unroll
                for (int q = 0; q < 4; q++) {
                    uint4 o = make_uint4(
                        pack_h2(fv[q*8+1], fv[q*8+0]), pack_h2(fv[q*8+3], fv[q*8+2]),
                        pack_h2(fv[q*8+5], fv[q*8+4]), pack_h2(fv[q*8+7], fv[q*8+6]));
                    *(uint4*)(crow + c0 + q * 8) = o;
                }
            } else {
                float* crow = (float*)Call + (long long)e * sCe + (long long)row * ldC + n0;
                #pragma unroll
                for (int q = 0; q < 8; q++)
                    *(float4*)(crow + c0 + q * 4) =
                        make_float4(fv[q*4], fv[q*4+1], fv[q*4+2], fv[q*4+3]);
            }
        }
    }
    __syncthreads();
    if (warp == 0) tc_dealloc(tmem, 256);
#else
    const int tid = threadIdx.x;
    const int row = m0 + (tid >> 1);
    const int nh  = (tid & 1) * (NTILE / 2);
    const __half* arow;
    if (GATHER) {
        int tok = (row < M) ? tokall[e * CAP + row] : -1;
        arow = (tok >= 0) ? (Aall + (long long)tok * ldA) : nullptr;
    } else arow = Aall + (long long)e * sAe + (long long)row * ldA;
    for (int c = 0; c < NTILE / 64; c++) {
        float acc[32];
        #pragma unroll
        for (int q = 0; q < 32; q++) acc[q] = 0.f;
        int nb = n0 + nh + c * 32;
        for (int k = 0; k < Kdim; k++) {
            float a = arow ? __half2float(arow[k]) : 0.f;
            for (int q = 0; q < 32; q++)
                acc[q] += a * __half2float(B[(long long)(nb + q) * Kdim + k]);
        }
        for (int q = 0; q < 32; q++) {
            float v = acc[q];
            if (GELU) v = gelu_tanh(v);
            if (HOUT) ((__half*)Call)[(long long)e * sCe + (long long)row * ldC + nb + q] = __float2half(v);
            else      ((float*)Call)[(long long)e * sCe + (long long)row * ldC + nb + q] = v;
        }
    }
#endif
}

__global__ __launch_bounds__(256) void combine_kernel(
    float* __restrict__ out, const __half* __restrict__ y,
    const int* __restrict__ pair_slot, const float* __restrict__ pair_w)
{
    int t = blockIdx.x;
    int slot[KTOP]; float w[KTOP];
    #pragma unroll
    for (int k = 0; k < KTOP; k++) {
        slot[k] = pair_slot[t * KTOP + k];
        w[k]    = pair_w[t * KTOP + k];
    }
    int h4 = threadIdx.x;
    float4 acc = *(float4*)(out + (size_t)t * H + h4 * 4);
    #pragma unroll
    for (int k = 0; k < KTOP; k++) {
        uint2 p = *(const uint2*)(y + (size_t)slot[k] * H + h4 * 4);
        __half2 a = *(__half2*)&p.x, b = *(__half2*)&p.y;
        acc.x += w[k] * __low2float(a);  acc.y += w[k] * __high2float(a);
        acc.z += w[k] * __low2float(b);  acc.w += w[k] * __high2float(b);
    }
    *(float4*)(out + (size_t)t * H + h4 * 4) = acc;
}

extern "C" void kernel_launch(void* const* d_in, const int* in_sizes, int n_in,
                              void* d_out, int out_size)
{
    const float* x   = (const float*)d_in[0];
    const float* rw  = (const float*)d_in[1];
    const float* eb  = (const float*)d_in[2];
    const float* w1  = (const float*)d_in[3];
    const float* w2  = (const float*)d_in[4];
    const float* sw1 = (const float*)d_in[5];
    const float* sw2 = (const float*)d_in[6];
    float* out = (float*)d_out;

    void *pcnt, *ptok, *pps, *ppw, *pmid, *py, *psmid, *pxr, *ps1, *ps2, *pw1t, *pw2t;
    cudaGetSymbolAddress(&pcnt,  g_cnt);
    cudaGetSymbolAddress(&ptok,  g_slot_token);
    cudaGetSymbolAddress(&pps,   g_pair_slot);
    cudaGetSymbolAddress(&ppw,   g_pair_w);
    cudaGetSymbolAddress(&pmid,  g_midh);
    cudaGetSymbolAddress(&py,    g_yh);
    cudaGetSymbolAddress(&psmid, g_smidh);
    cudaGetSymbolAddress(&pxr,   g_xrh);
    cudaGetSymbolAddress(&ps1,   g_sw1h);
    cudaGetSymbolAddress(&ps2,   g_sw2h);
    cudaGetSymbolAddress(&pw1t,  g_w1th);
    cudaGetSymbolAddress(&pw2t,  g_w2th);

    int*    cnt       = (int*)pcnt;
    int*    slot_tok  = (int*)ptok;
    int*    pair_slot = (int*)pps;
    float*  pair_w    = (float*)ppw;
    __half* midh      = (__half*)pmid;
    __half* yh        = (__half*)py;
    __half* smidh     = (__half*)psmid;
    __half* xrh       = (__half*)pxr;
    __half* sw1h      = (__half*)ps1;
    __half* sw2h      = (__half*)ps2;
    __half* w1th      = (__half*)pw1t;
    __half* w2th      = (__half*)pw2t;

    const int SM256 = 4 * (16384 + 256 * 128) + 1024 + 64;
    const int SM128 = 4 * (16384 + 128 * 128) + 1024 + 64;

    static cudaStream_t s1 = nullptr, s2 = nullptr;
    static cudaEvent_t evF, evW1, evW2, evR, evS;
    if (!s1) {
        cudaStreamCreateWithFlags(&s1, cudaStreamNonBlocking);
        cudaStreamCreateWithFlags(&s2, cudaStreamNonBlocking);
        cudaEventCreateWithFlags(&evF,  cudaEventDisableTiming);
        cudaEventCreateWithFlags(&evW1, cudaEventDisableTiming);
        cudaEventCreateWithFlags(&evW2, cudaEventDisableTiming);
        cudaEventCreateWithFlags(&evR,  cudaEventDisableTiming);
        cudaEventCreateWithFlags(&evS,  cudaEventDisableTiming);
        cudaFuncSetAttribute(gemm_tc<true,  true,  true,  256>, cudaFuncAttributeMaxDynamicSharedMemorySize, SM256);
        cudaFuncSetAttribute(gemm_tc<false, false, true,  256>, cudaFuncAttributeMaxDynamicSharedMemorySize, SM256);
        cudaFuncSetAttribute(gemm_tc<false, true,  true,  256>, cudaFuncAttributeMaxDynamicSharedMemorySize, SM256);
        cudaFuncSetAttribute(gemm_tc<false, false, false, 128>, cudaFuncAttributeMaxDynamicSharedMemorySize, SM128);
    }

    // (1) zero
    zero_cnt_kernel<<<1, 64>>>(cnt);
    cudaEventRecord(evF, 0);
    cudaStreamWaitEvent(s1, evF, 0);
    cudaStreamWaitEvent(s2, evF, 0);

    // (2) router (+ fp16 x)
    router2_kernel<<<T / 8, 256>>>(x, rw, eb, cnt, slot_tok, pair_slot, pair_w, xrh);
    cudaEventRecord(evR, 0);

    // (3) weight cvt+transpose on s1: w1 [E][H][F] -> w1th [E][F][H]
    tcvt_kernel<<<dim3(F / 128, H / 32, E), 256, 0, s1>>>(w1, w1th, H, F);
    cudaEventRecord(evW1, s1);

    // (4) expert GEMM1 (waits w1th)   <-- ncu captures this launch
    cudaStreamWaitEvent(0, evW1, 0);
    gemm_tc<true, true, true, 256><<<dim3(F / 256, CAP / 128, E), 256, SM256>>>(
        xrh, 0LL, H, w1th, (long long)F * H,
        midh, (long long)CAP * F, F, H, F, cnt, CAP, slot_tok);

    // (5) w2 cvt+transpose on s1: w2 [E][F][H] -> w2th [E][H][F]
    tcvt_kernel<<<dim3(H / 128, F / 32, E), 256, 0, s1>>>(w2, w2th, F, H);
    cudaEventRecord(evW2, s1);

    // (6) expert GEMM2 (waits w2th)
    cudaStreamWaitEvent(0, evW2, 0);
    gemm_tc<false, false, true, 256><<<dim3(H / 256, CAP / 128, E), 256, SM256>>>(
        midh, (long long)CAP * F, F, w2th, (long long)H * F,
        yh, (long long)CAP * H, H, F, H, cnt, CAP, slot_tok);

    // (7-9) shared chain on s2
    prep_kernel<<<SF * H / 4 / 256, 256, 0, s2>>>(sw1, sw1h, sw2, sw2h);
    cudaStreamWaitEvent(s2, evR, 0);
    gemm_tc<false, true, true, 256><<<dim3(SF / 256, T / 128, 1), 256, SM256, s2>>>(
        xrh, 0LL, H, sw1h, 0LL, smidh, 0LL, SF, H, SF, nullptr, T, nullptr);
    gemm_tc<false, false, false, 128><<<dim3(H / 128, T / 128, 1), 256, SM128, s2>>>(
        smidh, 0LL, SF, sw2h, 0LL, out, 0LL, H, SF, H, nullptr, T, nullptr);
    cudaEventRecord(evS, s2);

    // (10) combine
    cudaStreamWaitEvent(0, evS, 0);
    combine_kernel<<<T, 256>>>(out, yh, pair_slot, pair_w);
}